// round 5
// baseline (speedup 1.0000x reference)
#include <cuda_runtime.h>

#define N_NODES 100000
#define N_EDGES 3200000
#define G_GROUPS 128
#define F_IN 9
#define H_DIM 64

// Scratch (__device__ globals; no allocation allowed).
__device__ __align__(16) float g_h1[N_NODES * H_DIM];   // hidden after conv1
__device__ __align__(16) float g_agg[N_NODES * H_DIM];  // aggregation (pass1 uses stride-12)
__device__ __align__(16) float g_xp[N_NODES * 12];      // x padded to 48B rows
__device__ int   g_deg[N_NODES];
__device__ int   g_off[N_NODES + 1];
__device__ int   g_cur[N_NODES];
__device__ __align__(8) int2 g_csr[N_EDGES];            // (src, attr bits), bucketed by dst
__device__ __align__(16) float g_pi[N_NODES];
__device__ __align__(16) float g_texp[G_GROUPS];

// ---------------------------------------------------------------------------
// prep: zero degree counters + texp, pad x into 16B-aligned stride-12 rows.
__global__ void prep_kernel(const float* __restrict__ x) {
    int i = blockIdx.x * blockDim.x + threadIdx.x;
    if (i < G_GROUPS) g_texp[i] = 0.f;
    if (i >= N_NODES) return;
    g_deg[i] = 0;
    float4 a = make_float4(x[i*9+0], x[i*9+1], x[i*9+2], x[i*9+3]);
    float4 b = make_float4(x[i*9+4], x[i*9+5], x[i*9+6], x[i*9+7]);
    float4 c = make_float4(x[i*9+8], 0.f, 0.f, 0.f);
    float4* p = reinterpret_cast<float4*>(&g_xp[i*12]);
    p[0] = a; p[1] = b; p[2] = c;
}

// ---------------------------------------------------------------------------
// Histogram of dst degrees; 4 edges per thread via int4.
__global__ void hist_kernel(const int* __restrict__ ei) {
    int t = blockIdx.x * blockDim.x + threadIdx.x;
    int e = t * 4;
    if (e >= N_EDGES) return;
    int4 d = __ldg(reinterpret_cast<const int4*>(&ei[N_EDGES + e]));
    atomicAdd(&g_deg[d.x], 1);
    atomicAdd(&g_deg[d.y], 1);
    atomicAdd(&g_deg[d.z], 1);
    atomicAdd(&g_deg[d.w], 1);
}

// ---------------------------------------------------------------------------
// Single-block exclusive scan of g_deg -> g_off (and g_cur copy). 1024 threads.
__global__ void scan_kernel() {
    const int T = 1024;
    const int CH = (N_NODES + T - 1) / T;  // 98
    int tid = threadIdx.x;
    int start = tid * CH;
    int end = min(start + CH, N_NODES);

    int local = 0;
    for (int i = start; i < end; i++) local += g_deg[i];

    __shared__ int sh[T];
    sh[tid] = local;
    __syncthreads();
    for (int off = 1; off < T; off <<= 1) {
        int v = (tid >= off) ? sh[tid - off] : 0;
        __syncthreads();
        sh[tid] += v;
        __syncthreads();
    }
    int run = sh[tid] - local;  // exclusive prefix

    for (int i = start; i < end; i++) {
        g_off[i] = run;
        g_cur[i] = run;
        run += g_deg[i];
    }
    if (end == N_NODES && start < N_NODES) g_off[N_NODES] = run;
    if (tid == T - 1 && start >= N_NODES) g_off[N_NODES] = sh[T - 1];
}

// ---------------------------------------------------------------------------
// Bucket edges by dst; 4 edges per thread via int4/float4 loads.
__global__ void scatter_kernel(const int* __restrict__ ei,
                               const float* __restrict__ eattr) {
    int t = blockIdx.x * blockDim.x + threadIdx.x;
    int e = t * 4;
    if (e >= N_EDGES) return;
    int4   s = __ldg(reinterpret_cast<const int4*>(&ei[e]));
    int4   d = __ldg(reinterpret_cast<const int4*>(&ei[N_EDGES + e]));
    float4 a = __ldg(reinterpret_cast<const float4*>(&eattr[e]));
    g_csr[atomicAdd(&g_cur[d.x], 1)] = make_int2(s.x, __float_as_int(a.x));
    g_csr[atomicAdd(&g_cur[d.y], 1)] = make_int2(s.y, __float_as_int(a.y));
    g_csr[atomicAdd(&g_cur[d.z], 1)] = make_int2(s.z, __float_as_int(a.z));
    g_csr[atomicAdd(&g_cur[d.w], 1)] = make_int2(s.w, __float_as_int(a.w));
}

// ---------------------------------------------------------------------------
// Edge pass 1 (gather): warp per dst node. Lane-strided edges, 9-float
// accumulators, butterfly reduce, lane0 writes stride-12 row.
__global__ void edge1_gather(const float* __restrict__ We1,
                             const float* __restrict__ be1) {
    int gt = blockIdx.x * blockDim.x + threadIdx.x;
    int n = gt >> 5;
    int lane = gt & 31;
    if (n >= N_NODES) return;

    float w[9], b[9];
#pragma unroll
    for (int f = 0; f < 9; f++) { w[f] = __ldg(&We1[f]); b[f] = __ldg(&be1[f]); }

    int beg = __ldg(&g_off[n]);
    int end = __ldg(&g_off[n + 1]);

    float acc[9];
#pragma unroll
    for (int f = 0; f < 9; f++) acc[f] = 0.f;

    for (int j = beg + lane; j < end; j += 32) {
        int2 sa = __ldg(&g_csr[j]);
        float a = __int_as_float(sa.y);
        const float4* xr = reinterpret_cast<const float4*>(&g_xp[sa.x * 12]);
        float4 x0 = __ldg(xr + 0);
        float4 x1 = __ldg(xr + 1);
        float4 x2 = __ldg(xr + 2);
        acc[0] += fmaxf(x0.x + fmaf(a, w[0], b[0]), 0.f);
        acc[1] += fmaxf(x0.y + fmaf(a, w[1], b[1]), 0.f);
        acc[2] += fmaxf(x0.z + fmaf(a, w[2], b[2]), 0.f);
        acc[3] += fmaxf(x0.w + fmaf(a, w[3], b[3]), 0.f);
        acc[4] += fmaxf(x1.x + fmaf(a, w[4], b[4]), 0.f);
        acc[5] += fmaxf(x1.y + fmaf(a, w[5], b[5]), 0.f);
        acc[6] += fmaxf(x1.z + fmaf(a, w[6], b[6]), 0.f);
        acc[7] += fmaxf(x1.w + fmaf(a, w[7], b[7]), 0.f);
        acc[8] += fmaxf(x2.x + fmaf(a, w[8], b[8]), 0.f);
    }
#pragma unroll
    for (int f = 0; f < 9; f++) {
#pragma unroll
        for (int o = 16; o > 0; o >>= 1)
            acc[f] += __shfl_xor_sync(0xffffffffu, acc[f], o);
    }
    if (lane == 0) {
        float* dst = &g_agg[n * 12];
#pragma unroll
        for (int f = 0; f < 9; f++) dst[f] = acc[f];
    }
}

// ---------------------------------------------------------------------------
// Node MLP 1: z = x + agg; h1 = relu(relu(z@W1a+b1a)@W1b+b1b)
__global__ void mlp1_kernel(const float* __restrict__ x,
                            const float* __restrict__ W1a, const float* __restrict__ b1a,
                            const float* __restrict__ W1b, const float* __restrict__ b1b) {
    __shared__ __align__(16) float sWa[F_IN * H_DIM];
    __shared__ __align__(16) float sWb[H_DIM * H_DIM];
    __shared__ __align__(16) float sba[H_DIM];
    __shared__ __align__(16) float sbb[H_DIM];
    int tid = threadIdx.x;
    for (int i = tid; i < F_IN * H_DIM; i += blockDim.x) sWa[i] = W1a[i];
    for (int i = tid; i < H_DIM * H_DIM; i += blockDim.x) sWb[i] = W1b[i];
    if (tid < H_DIM) { sba[tid] = b1a[tid]; sbb[tid] = b1b[tid]; }
    __syncthreads();

    int n = blockIdx.x * blockDim.x + tid;
    if (n >= N_NODES) return;

    float z[F_IN];
#pragma unroll
    for (int f = 0; f < F_IN; f++) z[f] = x[n * 9 + f] + g_agg[n * 12 + f];

    float t[H_DIM];
#pragma unroll
    for (int j = 0; j < H_DIM; j += 4) {
        float4 acc = *reinterpret_cast<float4*>(&sba[j]);
#pragma unroll
        for (int f = 0; f < F_IN; f++) {
            float4 w = *reinterpret_cast<float4*>(&sWa[f * H_DIM + j]);
            acc.x = fmaf(z[f], w.x, acc.x);
            acc.y = fmaf(z[f], w.y, acc.y);
            acc.z = fmaf(z[f], w.z, acc.z);
            acc.w = fmaf(z[f], w.w, acc.w);
        }
        t[j + 0] = fmaxf(acc.x, 0.f);
        t[j + 1] = fmaxf(acc.y, 0.f);
        t[j + 2] = fmaxf(acc.z, 0.f);
        t[j + 3] = fmaxf(acc.w, 0.f);
    }

    for (int j = 0; j < H_DIM; j += 4) {
        float4 acc = *reinterpret_cast<float4*>(&sbb[j]);
#pragma unroll
        for (int k = 0; k < H_DIM; k++) {
            float4 w = *reinterpret_cast<float4*>(&sWb[k * H_DIM + j]);
            acc.x = fmaf(t[k], w.x, acc.x);
            acc.y = fmaf(t[k], w.y, acc.y);
            acc.z = fmaf(t[k], w.z, acc.z);
            acc.w = fmaf(t[k], w.w, acc.w);
        }
        float4 o;
        o.x = fmaxf(acc.x, 0.f);
        o.y = fmaxf(acc.y, 0.f);
        o.z = fmaxf(acc.z, 0.f);
        o.w = fmaxf(acc.w, 0.f);
        *reinterpret_cast<float4*>(&g_h1[n * H_DIM + j]) = o;
    }
}

// ---------------------------------------------------------------------------
// Edge pass 2 (gather): warp per dst node, lane owns float2 feature slice.
// csr entry broadcast across warp; h1 row read fully coalesced (256B/edge).
__global__ void edge2_gather(const float* __restrict__ We2,
                             const float* __restrict__ be2) {
    int gt = blockIdx.x * blockDim.x + threadIdx.x;
    int n = gt >> 5;
    int lane = gt & 31;
    if (n >= N_NODES) return;
    int c = lane * 2;

    float2 w = __ldg(reinterpret_cast<const float2*>(&We2[c]));
    float2 b = __ldg(reinterpret_cast<const float2*>(&be2[c]));
    int beg = __ldg(&g_off[n]);
    int end = __ldg(&g_off[n + 1]);

    float2 acc = make_float2(0.f, 0.f);
#pragma unroll 4
    for (int j = beg; j < end; j++) {
        int2 sa = __ldg(&g_csr[j]);                       // broadcast (same addr all lanes)
        float a = __int_as_float(sa.y);
        float2 h = __ldg(reinterpret_cast<const float2*>(&g_h1[sa.x * H_DIM + c]));
        acc.x += fmaxf(h.x + fmaf(a, w.x, b.x), 0.f);
        acc.y += fmaxf(h.y + fmaf(a, w.y, b.y), 0.f);
    }
    *reinterpret_cast<float2*>(&g_agg[n * H_DIM + c]) = acc;
}

// ---------------------------------------------------------------------------
// Node MLP 2 + readout head + group segment-sum of expenses.
__global__ void mlp2_kernel(const float* __restrict__ W2a, const float* __restrict__ b2a,
                            const float* __restrict__ W2b, const float* __restrict__ b2b,
                            const float* __restrict__ Wr1, const float* __restrict__ br1,
                            const float* __restrict__ Wr2, const float* __restrict__ br2,
                            const int* __restrict__ batch,
                            const int* __restrict__ term,
                            const float* __restrict__ c_cost) {
    __shared__ __align__(16) float sWa[H_DIM * H_DIM];
    __shared__ __align__(16) float sWb[H_DIM * H_DIM];
    __shared__ __align__(16) float sWr1[H_DIM * 32];
    __shared__ __align__(16) float sba[H_DIM];
    __shared__ __align__(16) float sbb[H_DIM];
    __shared__ __align__(16) float sbr1[32];
    __shared__ __align__(16) float sWr2[32];
    __shared__ float sbr2;
    int tid = threadIdx.x;
    for (int i = tid; i < H_DIM * H_DIM; i += blockDim.x) { sWa[i] = W2a[i]; sWb[i] = W2b[i]; }
    for (int i = tid; i < H_DIM * 32; i += blockDim.x) sWr1[i] = Wr1[i];
    if (tid < H_DIM) { sba[tid] = b2a[tid]; sbb[tid] = b2b[tid]; }
    if (tid < 32) { sbr1[tid] = br1[tid]; sWr2[tid] = Wr2[tid]; }
    if (tid == 0) sbr2 = br2[0];
    __syncthreads();

    int n = blockIdx.x * blockDim.x + tid;
    if (n >= N_NODES) return;

    float z[H_DIM];
#pragma unroll
    for (int k = 0; k < H_DIM; k += 4) {
        float4 hv = *reinterpret_cast<const float4*>(&g_h1[n * H_DIM + k]);
        float4 av = *reinterpret_cast<const float4*>(&g_agg[n * H_DIM + k]);
        z[k + 0] = hv.x + av.x;
        z[k + 1] = hv.y + av.y;
        z[k + 2] = hv.z + av.z;
        z[k + 3] = hv.w + av.w;
    }

    float t[H_DIM];
    for (int j = 0; j < H_DIM; j += 4) {
        float4 acc = *reinterpret_cast<float4*>(&sba[j]);
#pragma unroll
        for (int k = 0; k < H_DIM; k++) {
            float4 w = *reinterpret_cast<float4*>(&sWa[k * H_DIM + j]);
            acc.x = fmaf(z[k], w.x, acc.x);
            acc.y = fmaf(z[k], w.y, acc.y);
            acc.z = fmaf(z[k], w.z, acc.z);
            acc.w = fmaf(z[k], w.w, acc.w);
        }
        t[j + 0] = fmaxf(acc.x, 0.f);
        t[j + 1] = fmaxf(acc.y, 0.f);
        t[j + 2] = fmaxf(acc.z, 0.f);
        t[j + 3] = fmaxf(acc.w, 0.f);
    }

    // reuse z[] as h2
    for (int j = 0; j < H_DIM; j += 4) {
        float4 acc = *reinterpret_cast<float4*>(&sbb[j]);
#pragma unroll
        for (int k = 0; k < H_DIM; k++) {
            float4 w = *reinterpret_cast<float4*>(&sWb[k * H_DIM + j]);
            acc.x = fmaf(t[k], w.x, acc.x);
            acc.y = fmaf(t[k], w.y, acc.y);
            acc.z = fmaf(t[k], w.z, acc.z);
            acc.w = fmaf(t[k], w.w, acc.w);
        }
        z[j + 0] = fmaxf(acc.x, 0.f);
        z[j + 1] = fmaxf(acc.y, 0.f);
        z[j + 2] = fmaxf(acc.z, 0.f);
        z[j + 3] = fmaxf(acc.w, 0.f);
    }

    // readout: r = relu(h2 @ Wr1 + br1) [32]; p = r @ Wr2 + br2
    float r[32];
    for (int j = 0; j < 32; j += 4) {
        float4 acc = *reinterpret_cast<float4*>(&sbr1[j]);
#pragma unroll
        for (int k = 0; k < H_DIM; k++) {
            float4 w = *reinterpret_cast<float4*>(&sWr1[k * 32 + j]);
            acc.x = fmaf(z[k], w.x, acc.x);
            acc.y = fmaf(z[k], w.y, acc.y);
            acc.z = fmaf(z[k], w.z, acc.z);
            acc.w = fmaf(z[k], w.w, acc.w);
        }
        r[j + 0] = fmaxf(acc.x, 0.f);
        r[j + 1] = fmaxf(acc.y, 0.f);
        r[j + 2] = fmaxf(acc.z, 0.f);
        r[j + 3] = fmaxf(acc.w, 0.f);
    }
    float p = sbr2;
#pragma unroll
    for (int k = 0; k < 32; k++) p = fmaf(r[k], sWr2[k], p);

    float pi = 1.f / (1.f + expf(-p));
    if (term[n] != 0) pi = 0.f;
    g_pi[n] = pi;
    atomicAdd(&g_texp[batch[n]], pi * c_cost[n]);
}

// ---------------------------------------------------------------------------
__global__ void final_kernel(const int* __restrict__ batch,
                             const float* __restrict__ B_total,
                             float* __restrict__ out) {
    int n = blockIdx.x * blockDim.x + threadIdx.x;
    if (n >= N_NODES) return;
    int b = batch[n];
    float ratio = fminf(B_total[b] / (g_texp[b] + 1e-12f), 1.f);
    out[n] = g_pi[n] * ratio;
}

// ---------------------------------------------------------------------------
extern "C" void kernel_launch(void* const* d_in, const int* in_sizes, int n_in,
                              void* d_out, int out_size) {
    const float* x       = (const float*)d_in[0];
    const int*   ei      = (const int*)d_in[1];
    const float* eattr   = (const float*)d_in[2];
    const int*   batch   = (const int*)d_in[3];
    const float* B_total = (const float*)d_in[4];
    const int*   term    = (const int*)d_in[5];
    const float* c_cost  = (const float*)d_in[6];
    const float* We1 = (const float*)d_in[7];
    const float* be1 = (const float*)d_in[8];
    const float* W1a = (const float*)d_in[9];
    const float* b1a = (const float*)d_in[10];
    const float* W1b = (const float*)d_in[11];
    const float* b1b = (const float*)d_in[12];
    const float* We2 = (const float*)d_in[13];
    const float* be2 = (const float*)d_in[14];
    const float* W2a = (const float*)d_in[15];
    const float* b2a = (const float*)d_in[16];
    const float* W2b = (const float*)d_in[17];
    const float* b2b = (const float*)d_in[18];
    const float* Wr1 = (const float*)d_in[19];
    const float* br1 = (const float*)d_in[20];
    const float* Wr2 = (const float*)d_in[21];
    const float* br2 = (const float*)d_in[22];
    float* out = (float*)d_out;

    const int NB_NODE = (N_NODES + 255) / 256;
    const int NB_EDGE4 = (N_EDGES / 4 + 255) / 256;

    prep_kernel<<<NB_NODE, 256>>>(x);
    hist_kernel<<<NB_EDGE4, 256>>>(ei);
    scan_kernel<<<1, 1024>>>();
    scatter_kernel<<<NB_EDGE4, 256>>>(ei, eattr);
    edge1_gather<<<(N_NODES * 32 + 255) / 256, 256>>>(We1, be1);
    mlp1_kernel<<<NB_NODE, 256>>>(x, W1a, b1a, W1b, b1b);
    edge2_gather<<<(N_NODES * 32 + 255) / 256, 256>>>(We2, be2);
    mlp2_kernel<<<NB_NODE, 256>>>(W2a, b2a, W2b, b2b, Wr1, br1, Wr2, br2,
                                  batch, term, c_cost);
    final_kernel<<<NB_NODE, 256>>>(batch, B_total, out);
}

// round 6
// speedup vs baseline: 1.3751x; 1.3751x over previous
#include <cuda_runtime.h>

#define N_NODES 100000
#define N_EDGES 3200000
#define G_GROUPS 128
#define F_IN 9
#define H_DIM 64
#define SCAN_B 256
#define N_SCAN_BLOCKS ((N_NODES + SCAN_B - 1) / SCAN_B)   // 391

// Scratch (__device__ globals; no allocation allowed).
__device__ __align__(16) float g_h1[N_NODES * H_DIM];   // hidden after conv1
__device__ __align__(16) float g_agg[N_NODES * H_DIM];  // aggregation (pass1 uses stride-12)
__device__ __align__(16) float g_xp[N_NODES * 12];      // x padded to 48B rows
__device__ int   g_deg[N_NODES];
__device__ int   g_off[N_NODES + 1];
__device__ int   g_cur[N_NODES];
__device__ int   g_bsum[N_SCAN_BLOCKS];
__device__ __align__(8) int2 g_csr[N_EDGES];            // (src, attr bits), bucketed by dst
__device__ __align__(16) float g_pi[N_NODES];
__device__ __align__(16) float g_texp[G_GROUPS];

// ---------------------------------------------------------------------------
// prep: zero degree counters + texp, pad x into 16B-aligned stride-12 rows.
__global__ void prep_kernel(const float* __restrict__ x) {
    int i = blockIdx.x * blockDim.x + threadIdx.x;
    if (i < G_GROUPS) g_texp[i] = 0.f;
    if (i >= N_NODES) return;
    g_deg[i] = 0;
    float4 a = make_float4(x[i*9+0], x[i*9+1], x[i*9+2], x[i*9+3]);
    float4 b = make_float4(x[i*9+4], x[i*9+5], x[i*9+6], x[i*9+7]);
    float4 c = make_float4(x[i*9+8], 0.f, 0.f, 0.f);
    float4* p = reinterpret_cast<float4*>(&g_xp[i*12]);
    p[0] = a; p[1] = b; p[2] = c;
}

// ---------------------------------------------------------------------------
// Histogram of dst degrees; 4 edges per thread via int4.
__global__ void hist_kernel(const int* __restrict__ ei) {
    int t = blockIdx.x * blockDim.x + threadIdx.x;
    int e = t * 4;
    if (e >= N_EDGES) return;
    int4 d = __ldg(reinterpret_cast<const int4*>(&ei[N_EDGES + e]));
    atomicAdd(&g_deg[d.x], 1);
    atomicAdd(&g_deg[d.y], 1);
    atomicAdd(&g_deg[d.z], 1);
    atomicAdd(&g_deg[d.w], 1);
}

// ---------------------------------------------------------------------------
// Parallel scan, phase A: per-block local exclusive scan (coalesced) of g_deg.
// Writes local-exclusive prefix to g_off[i], block total to g_bsum[b].
__global__ void scanA_kernel() {
    __shared__ int sh[SCAN_B];
    int tid = threadIdx.x;
    int i = blockIdx.x * SCAN_B + tid;
    int v = (i < N_NODES) ? g_deg[i] : 0;
    sh[tid] = v;
    __syncthreads();
#pragma unroll
    for (int off = 1; off < SCAN_B; off <<= 1) {
        int t = (tid >= off) ? sh[tid - off] : 0;
        __syncthreads();
        sh[tid] += t;
        __syncthreads();
    }
    if (i < N_NODES) g_off[i] = sh[tid] - v;   // local exclusive
    if (tid == SCAN_B - 1) g_bsum[blockIdx.x] = sh[tid];
}

// Phase B: one block scans the 391 block sums (exclusive); writes g_off[N].
__global__ void scanB_kernel() {
    __shared__ int sh[512];
    int tid = threadIdx.x;
    int v = (tid < N_SCAN_BLOCKS) ? g_bsum[tid] : 0;
    sh[tid] = v;
    __syncthreads();
#pragma unroll
    for (int off = 1; off < 512; off <<= 1) {
        int t = (tid >= off) ? sh[tid - off] : 0;
        __syncthreads();
        sh[tid] += t;
        __syncthreads();
    }
    if (tid < N_SCAN_BLOCKS) g_bsum[tid] = sh[tid] - v;  // exclusive
    if (tid == N_SCAN_BLOCKS - 1) g_off[N_NODES] = sh[tid];
}

// Phase C: add block offsets; materialize g_cur.
__global__ void scanC_kernel() {
    int i = blockIdx.x * blockDim.x + threadIdx.x;
    if (i >= N_NODES) return;
    int o = g_off[i] + g_bsum[i >> 8];
    g_off[i] = o;
    g_cur[i] = o;
}

// ---------------------------------------------------------------------------
// Bucket edges by dst; 4 edges per thread via int4/float4 loads.
__global__ void scatter_kernel(const int* __restrict__ ei,
                               const float* __restrict__ eattr) {
    int t = blockIdx.x * blockDim.x + threadIdx.x;
    int e = t * 4;
    if (e >= N_EDGES) return;
    int4   s = __ldg(reinterpret_cast<const int4*>(&ei[e]));
    int4   d = __ldg(reinterpret_cast<const int4*>(&ei[N_EDGES + e]));
    float4 a = __ldg(reinterpret_cast<const float4*>(&eattr[e]));
    g_csr[atomicAdd(&g_cur[d.x], 1)] = make_int2(s.x, __float_as_int(a.x));
    g_csr[atomicAdd(&g_cur[d.y], 1)] = make_int2(s.y, __float_as_int(a.y));
    g_csr[atomicAdd(&g_cur[d.z], 1)] = make_int2(s.z, __float_as_int(a.z));
    g_csr[atomicAdd(&g_cur[d.w], 1)] = make_int2(s.w, __float_as_int(a.w));
}

// ---------------------------------------------------------------------------
// Edge pass 1 (gather): warp per dst node. Lane-strided edges, 9-float
// accumulators, butterfly reduce, lane0 writes stride-12 row.
__global__ void edge1_gather(const float* __restrict__ We1,
                             const float* __restrict__ be1) {
    int gt = blockIdx.x * blockDim.x + threadIdx.x;
    int n = gt >> 5;
    int lane = gt & 31;
    if (n >= N_NODES) return;

    float w[9], b[9];
#pragma unroll
    for (int f = 0; f < 9; f++) { w[f] = __ldg(&We1[f]); b[f] = __ldg(&be1[f]); }

    int beg = __ldg(&g_off[n]);
    int end = __ldg(&g_off[n + 1]);

    float acc[9];
#pragma unroll
    for (int f = 0; f < 9; f++) acc[f] = 0.f;

    for (int j = beg + lane; j < end; j += 32) {
        int2 sa = __ldg(&g_csr[j]);
        float a = __int_as_float(sa.y);
        const float4* xr = reinterpret_cast<const float4*>(&g_xp[sa.x * 12]);
        float4 x0 = __ldg(xr + 0);
        float4 x1 = __ldg(xr + 1);
        float4 x2 = __ldg(xr + 2);
        acc[0] += fmaxf(x0.x + fmaf(a, w[0], b[0]), 0.f);
        acc[1] += fmaxf(x0.y + fmaf(a, w[1], b[1]), 0.f);
        acc[2] += fmaxf(x0.z + fmaf(a, w[2], b[2]), 0.f);
        acc[3] += fmaxf(x0.w + fmaf(a, w[3], b[3]), 0.f);
        acc[4] += fmaxf(x1.x + fmaf(a, w[4], b[4]), 0.f);
        acc[5] += fmaxf(x1.y + fmaf(a, w[5], b[5]), 0.f);
        acc[6] += fmaxf(x1.z + fmaf(a, w[6], b[6]), 0.f);
        acc[7] += fmaxf(x1.w + fmaf(a, w[7], b[7]), 0.f);
        acc[8] += fmaxf(x2.x + fmaf(a, w[8], b[8]), 0.f);
    }
#pragma unroll
    for (int f = 0; f < 9; f++) {
#pragma unroll
        for (int o = 16; o > 0; o >>= 1)
            acc[f] += __shfl_xor_sync(0xffffffffu, acc[f], o);
    }
    if (lane == 0) {
        float* dst = &g_agg[n * 12];
#pragma unroll
        for (int f = 0; f < 9; f++) dst[f] = acc[f];
    }
}

// ---------------------------------------------------------------------------
// Node MLP 1: z = x + agg; h1 = relu(relu(z@W1a+b1a)@W1b+b1b)
__global__ void mlp1_kernel(const float* __restrict__ x,
                            const float* __restrict__ W1a, const float* __restrict__ b1a,
                            const float* __restrict__ W1b, const float* __restrict__ b1b) {
    __shared__ __align__(16) float sWa[F_IN * H_DIM];
    __shared__ __align__(16) float sWb[H_DIM * H_DIM];
    __shared__ __align__(16) float sba[H_DIM];
    __shared__ __align__(16) float sbb[H_DIM];
    int tid = threadIdx.x;
    for (int i = tid; i < F_IN * H_DIM; i += blockDim.x) sWa[i] = W1a[i];
    for (int i = tid; i < H_DIM * H_DIM; i += blockDim.x) sWb[i] = W1b[i];
    if (tid < H_DIM) { sba[tid] = b1a[tid]; sbb[tid] = b1b[tid]; }
    __syncthreads();

    int n = blockIdx.x * blockDim.x + tid;
    if (n >= N_NODES) return;

    float z[F_IN];
#pragma unroll
    for (int f = 0; f < F_IN; f++) z[f] = x[n * 9 + f] + g_agg[n * 12 + f];

    float t[H_DIM];
#pragma unroll
    for (int j = 0; j < H_DIM; j += 4) {
        float4 acc = *reinterpret_cast<float4*>(&sba[j]);
#pragma unroll
        for (int f = 0; f < F_IN; f++) {
            float4 w = *reinterpret_cast<float4*>(&sWa[f * H_DIM + j]);
            acc.x = fmaf(z[f], w.x, acc.x);
            acc.y = fmaf(z[f], w.y, acc.y);
            acc.z = fmaf(z[f], w.z, acc.z);
            acc.w = fmaf(z[f], w.w, acc.w);
        }
        t[j + 0] = fmaxf(acc.x, 0.f);
        t[j + 1] = fmaxf(acc.y, 0.f);
        t[j + 2] = fmaxf(acc.z, 0.f);
        t[j + 3] = fmaxf(acc.w, 0.f);
    }

    for (int j = 0; j < H_DIM; j += 4) {
        float4 acc = *reinterpret_cast<float4*>(&sbb[j]);
#pragma unroll
        for (int k = 0; k < H_DIM; k++) {
            float4 w = *reinterpret_cast<float4*>(&sWb[k * H_DIM + j]);
            acc.x = fmaf(t[k], w.x, acc.x);
            acc.y = fmaf(t[k], w.y, acc.y);
            acc.z = fmaf(t[k], w.z, acc.z);
            acc.w = fmaf(t[k], w.w, acc.w);
        }
        float4 o;
        o.x = fmaxf(acc.x, 0.f);
        o.y = fmaxf(acc.y, 0.f);
        o.z = fmaxf(acc.z, 0.f);
        o.w = fmaxf(acc.w, 0.f);
        *reinterpret_cast<float4*>(&g_h1[n * H_DIM + j]) = o;
    }
}

// ---------------------------------------------------------------------------
// Edge pass 2 (gather): warp per dst node, lane owns float2 feature slice.
// csr entries prefetched 4-wide so 4 h1-row gathers are always in flight.
__global__ void edge2_gather(const float* __restrict__ We2,
                             const float* __restrict__ be2) {
    int gt = blockIdx.x * blockDim.x + threadIdx.x;
    int n = gt >> 5;
    int lane = gt & 31;
    if (n >= N_NODES) return;
    int c = lane * 2;

    float2 w = __ldg(reinterpret_cast<const float2*>(&We2[c]));
    float2 b = __ldg(reinterpret_cast<const float2*>(&be2[c]));
    int beg = __ldg(&g_off[n]);
    int end = __ldg(&g_off[n + 1]);

    float2 acc = make_float2(0.f, 0.f);
    int j = beg;
    for (; j + 4 <= end; j += 4) {
        int2 e0 = __ldg(&g_csr[j + 0]);
        int2 e1 = __ldg(&g_csr[j + 1]);
        int2 e2 = __ldg(&g_csr[j + 2]);
        int2 e3 = __ldg(&g_csr[j + 3]);
        float2 h0 = __ldg(reinterpret_cast<const float2*>(&g_h1[e0.x * H_DIM + c]));
        float2 h1 = __ldg(reinterpret_cast<const float2*>(&g_h1[e1.x * H_DIM + c]));
        float2 h2 = __ldg(reinterpret_cast<const float2*>(&g_h1[e2.x * H_DIM + c]));
        float2 h3 = __ldg(reinterpret_cast<const float2*>(&g_h1[e3.x * H_DIM + c]));
        float a0 = __int_as_float(e0.y), a1 = __int_as_float(e1.y);
        float a2 = __int_as_float(e2.y), a3 = __int_as_float(e3.y);
        acc.x += fmaxf(h0.x + fmaf(a0, w.x, b.x), 0.f);
        acc.y += fmaxf(h0.y + fmaf(a0, w.y, b.y), 0.f);
        acc.x += fmaxf(h1.x + fmaf(a1, w.x, b.x), 0.f);
        acc.y += fmaxf(h1.y + fmaf(a1, w.y, b.y), 0.f);
        acc.x += fmaxf(h2.x + fmaf(a2, w.x, b.x), 0.f);
        acc.y += fmaxf(h2.y + fmaf(a2, w.y, b.y), 0.f);
        acc.x += fmaxf(h3.x + fmaf(a3, w.x, b.x), 0.f);
        acc.y += fmaxf(h3.y + fmaf(a3, w.y, b.y), 0.f);
    }
    for (; j < end; j++) {
        int2 sa = __ldg(&g_csr[j]);
        float a = __int_as_float(sa.y);
        float2 h = __ldg(reinterpret_cast<const float2*>(&g_h1[sa.x * H_DIM + c]));
        acc.x += fmaxf(h.x + fmaf(a, w.x, b.x), 0.f);
        acc.y += fmaxf(h.y + fmaf(a, w.y, b.y), 0.f);
    }
    *reinterpret_cast<float2*>(&g_agg[n * H_DIM + c]) = acc;
}

// ---------------------------------------------------------------------------
// Node MLP 2 + readout head + group segment-sum of expenses.
__global__ void mlp2_kernel(const float* __restrict__ W2a, const float* __restrict__ b2a,
                            const float* __restrict__ W2b, const float* __restrict__ b2b,
                            const float* __restrict__ Wr1, const float* __restrict__ br1,
                            const float* __restrict__ Wr2, const float* __restrict__ br2,
                            const int* __restrict__ batch,
                            const int* __restrict__ term,
                            const float* __restrict__ c_cost) {
    __shared__ __align__(16) float sWa[H_DIM * H_DIM];
    __shared__ __align__(16) float sWb[H_DIM * H_DIM];
    __shared__ __align__(16) float sWr1[H_DIM * 32];
    __shared__ __align__(16) float sba[H_DIM];
    __shared__ __align__(16) float sbb[H_DIM];
    __shared__ __align__(16) float sbr1[32];
    __shared__ __align__(16) float sWr2[32];
    __shared__ float sbr2;
    int tid = threadIdx.x;
    for (int i = tid; i < H_DIM * H_DIM; i += blockDim.x) { sWa[i] = W2a[i]; sWb[i] = W2b[i]; }
    for (int i = tid; i < H_DIM * 32; i += blockDim.x) sWr1[i] = Wr1[i];
    if (tid < H_DIM) { sba[tid] = b2a[tid]; sbb[tid] = b2b[tid]; }
    if (tid < 32) { sbr1[tid] = br1[tid]; sWr2[tid] = Wr2[tid]; }
    if (tid == 0) sbr2 = br2[0];
    __syncthreads();

    int n = blockIdx.x * blockDim.x + tid;
    if (n >= N_NODES) return;

    float z[H_DIM];
#pragma unroll
    for (int k = 0; k < H_DIM; k += 4) {
        float4 hv = *reinterpret_cast<const float4*>(&g_h1[n * H_DIM + k]);
        float4 av = *reinterpret_cast<const float4*>(&g_agg[n * H_DIM + k]);
        z[k + 0] = hv.x + av.x;
        z[k + 1] = hv.y + av.y;
        z[k + 2] = hv.z + av.z;
        z[k + 3] = hv.w + av.w;
    }

    float t[H_DIM];
    for (int j = 0; j < H_DIM; j += 4) {
        float4 acc = *reinterpret_cast<float4*>(&sba[j]);
#pragma unroll
        for (int k = 0; k < H_DIM; k++) {
            float4 w = *reinterpret_cast<float4*>(&sWa[k * H_DIM + j]);
            acc.x = fmaf(z[k], w.x, acc.x);
            acc.y = fmaf(z[k], w.y, acc.y);
            acc.z = fmaf(z[k], w.z, acc.z);
            acc.w = fmaf(z[k], w.w, acc.w);
        }
        t[j + 0] = fmaxf(acc.x, 0.f);
        t[j + 1] = fmaxf(acc.y, 0.f);
        t[j + 2] = fmaxf(acc.z, 0.f);
        t[j + 3] = fmaxf(acc.w, 0.f);
    }

    // reuse z[] as h2
    for (int j = 0; j < H_DIM; j += 4) {
        float4 acc = *reinterpret_cast<float4*>(&sbb[j]);
#pragma unroll
        for (int k = 0; k < H_DIM; k++) {
            float4 w = *reinterpret_cast<float4*>(&sWb[k * H_DIM + j]);
            acc.x = fmaf(t[k], w.x, acc.x);
            acc.y = fmaf(t[k], w.y, acc.y);
            acc.z = fmaf(t[k], w.z, acc.z);
            acc.w = fmaf(t[k], w.w, acc.w);
        }
        z[j + 0] = fmaxf(acc.x, 0.f);
        z[j + 1] = fmaxf(acc.y, 0.f);
        z[j + 2] = fmaxf(acc.z, 0.f);
        z[j + 3] = fmaxf(acc.w, 0.f);
    }

    // readout: r = relu(h2 @ Wr1 + br1) [32]; p = r @ Wr2 + br2
    float r[32];
    for (int j = 0; j < 32; j += 4) {
        float4 acc = *reinterpret_cast<float4*>(&sbr1[j]);
#pragma unroll
        for (int k = 0; k < H_DIM; k++) {
            float4 w = *reinterpret_cast<float4*>(&sWr1[k * 32 + j]);
            acc.x = fmaf(z[k], w.x, acc.x);
            acc.y = fmaf(z[k], w.y, acc.y);
            acc.z = fmaf(z[k], w.z, acc.z);
            acc.w = fmaf(z[k], w.w, acc.w);
        }
        r[j + 0] = fmaxf(acc.x, 0.f);
        r[j + 1] = fmaxf(acc.y, 0.f);
        r[j + 2] = fmaxf(acc.z, 0.f);
        r[j + 3] = fmaxf(acc.w, 0.f);
    }
    float p = sbr2;
#pragma unroll
    for (int k = 0; k < 32; k++) p = fmaf(r[k], sWr2[k], p);

    float pi = 1.f / (1.f + expf(-p));
    if (term[n] != 0) pi = 0.f;
    g_pi[n] = pi;
    atomicAdd(&g_texp[batch[n]], pi * c_cost[n]);
}

// ---------------------------------------------------------------------------
__global__ void final_kernel(const int* __restrict__ batch,
                             const float* __restrict__ B_total,
                             float* __restrict__ out) {
    int n = blockIdx.x * blockDim.x + threadIdx.x;
    if (n >= N_NODES) return;
    int b = batch[n];
    float ratio = fminf(B_total[b] / (g_texp[b] + 1e-12f), 1.f);
    out[n] = g_pi[n] * ratio;
}

// ---------------------------------------------------------------------------
extern "C" void kernel_launch(void* const* d_in, const int* in_sizes, int n_in,
                              void* d_out, int out_size) {
    const float* x       = (const float*)d_in[0];
    const int*   ei      = (const int*)d_in[1];
    const float* eattr   = (const float*)d_in[2];
    const int*   batch   = (const int*)d_in[3];
    const float* B_total = (const float*)d_in[4];
    const int*   term    = (const int*)d_in[5];
    const float* c_cost  = (const float*)d_in[6];
    const float* We1 = (const float*)d_in[7];
    const float* be1 = (const float*)d_in[8];
    const float* W1a = (const float*)d_in[9];
    const float* b1a = (const float*)d_in[10];
    const float* W1b = (const float*)d_in[11];
    const float* b1b = (const float*)d_in[12];
    const float* We2 = (const float*)d_in[13];
    const float* be2 = (const float*)d_in[14];
    const float* W2a = (const float*)d_in[15];
    const float* b2a = (const float*)d_in[16];
    const float* W2b = (const float*)d_in[17];
    const float* b2b = (const float*)d_in[18];
    const float* Wr1 = (const float*)d_in[19];
    const float* br1 = (const float*)d_in[20];
    const float* Wr2 = (const float*)d_in[21];
    const float* br2 = (const float*)d_in[22];
    float* out = (float*)d_out;

    const int NB_NODE = (N_NODES + 255) / 256;
    const int NB_EDGE4 = (N_EDGES / 4 + 255) / 256;

    prep_kernel<<<NB_NODE, 256>>>(x);
    hist_kernel<<<NB_EDGE4, 256>>>(ei);
    scanA_kernel<<<N_SCAN_BLOCKS, SCAN_B>>>();
    scanB_kernel<<<1, 512>>>();
    scanC_kernel<<<NB_NODE, 256>>>();
    scatter_kernel<<<NB_EDGE4, 256>>>(ei, eattr);
    edge1_gather<<<(N_NODES * 32 + 255) / 256, 256>>>(We1, be1);
    mlp1_kernel<<<NB_NODE, 256>>>(x, W1a, b1a, W1b, b1b);
    edge2_gather<<<(N_NODES * 32 + 255) / 256, 256>>>(We2, be2);
    mlp2_kernel<<<NB_NODE, 256>>>(W2a, b2a, W2b, b2b, Wr1, br1, Wr2, br2,
                                  batch, term, c_cost);
    final_kernel<<<NB_NODE, 256>>>(batch, B_total, out);
}

// round 7
// speedup vs baseline: 1.3880x; 1.0094x over previous
#include <cuda_runtime.h>

#define N_NODES 100000
#define N_EDGES 3200000
#define G_GROUPS 128
#define F_IN 9
#define H_DIM 64
#define SCAN_B 256
#define N_SCAN_BLOCKS ((N_NODES + SCAN_B - 1) / SCAN_B)   // 391

// Scratch (__device__ globals; no allocation allowed).
// NOTE: g_deg relies on zero-init at module load; scanC re-zeroes it after use
// so every launch (and every graph replay) starts with g_deg == 0.
__device__ __align__(16) float g_h1[N_NODES * H_DIM];   // hidden after conv1
__device__ __align__(16) float g_agg[N_NODES * H_DIM];  // aggregation (pass1 uses stride-12)
__device__ __align__(16) float g_xp[N_NODES * 12];      // x padded to 48B rows
__device__ int   g_deg[N_NODES];
__device__ int   g_off[N_NODES + 1];
__device__ int   g_cur[N_NODES];
__device__ int   g_bsum[N_SCAN_BLOCKS];
__device__ __align__(16) int2 g_csr[N_EDGES];           // (src, attr bits), bucketed by dst
__device__ __align__(16) float g_pi[N_NODES];
__device__ __align__(16) float g_texp[G_GROUPS];

// ---------------------------------------------------------------------------
// Fused prep + histogram. prep: zero texp, pad x into stride-12 rows.
// hist: dst-degree histogram, 4 edges/thread via int4. No write overlap.
__global__ void prep_hist_kernel(const float* __restrict__ x,
                                 const int* __restrict__ ei) {
    int t = blockIdx.x * blockDim.x + threadIdx.x;
    if (t < G_GROUPS) g_texp[t] = 0.f;
    if (t < N_NODES) {
        float4 a = make_float4(x[t*9+0], x[t*9+1], x[t*9+2], x[t*9+3]);
        float4 b = make_float4(x[t*9+4], x[t*9+5], x[t*9+6], x[t*9+7]);
        float4 c = make_float4(x[t*9+8], 0.f, 0.f, 0.f);
        float4* p = reinterpret_cast<float4*>(&g_xp[t*12]);
        p[0] = a; p[1] = b; p[2] = c;
    }
    int e = t * 4;
    if (e < N_EDGES) {
        int4 d = __ldg(reinterpret_cast<const int4*>(&ei[N_EDGES + e]));
        atomicAdd(&g_deg[d.x], 1);
        atomicAdd(&g_deg[d.y], 1);
        atomicAdd(&g_deg[d.z], 1);
        atomicAdd(&g_deg[d.w], 1);
    }
}

// ---------------------------------------------------------------------------
// Parallel scan, phase A: per-block local exclusive scan (coalesced) of g_deg.
__global__ void scanA_kernel() {
    __shared__ int sh[SCAN_B];
    int tid = threadIdx.x;
    int i = blockIdx.x * SCAN_B + tid;
    int v = (i < N_NODES) ? g_deg[i] : 0;
    sh[tid] = v;
    __syncthreads();
#pragma unroll
    for (int off = 1; off < SCAN_B; off <<= 1) {
        int t = (tid >= off) ? sh[tid - off] : 0;
        __syncthreads();
        sh[tid] += t;
        __syncthreads();
    }
    if (i < N_NODES) g_off[i] = sh[tid] - v;   // local exclusive
    if (tid == SCAN_B - 1) g_bsum[blockIdx.x] = sh[tid];
}

// Phase B: one block scans the block sums (exclusive); writes g_off[N].
__global__ void scanB_kernel() {
    __shared__ int sh[512];
    int tid = threadIdx.x;
    int v = (tid < N_SCAN_BLOCKS) ? g_bsum[tid] : 0;
    sh[tid] = v;
    __syncthreads();
#pragma unroll
    for (int off = 1; off < 512; off <<= 1) {
        int t = (tid >= off) ? sh[tid - off] : 0;
        __syncthreads();
        sh[tid] += t;
        __syncthreads();
    }
    if (tid < N_SCAN_BLOCKS) g_bsum[tid] = sh[tid] - v;  // exclusive
    if (tid == N_SCAN_BLOCKS - 1) g_off[N_NODES] = sh[tid];
}

// Phase C: add block offsets; materialize g_cur; re-zero g_deg for next launch.
__global__ void scanC_kernel() {
    int i = blockIdx.x * blockDim.x + threadIdx.x;
    if (i >= N_NODES) return;
    int o = g_off[i] + g_bsum[i >> 8];
    g_off[i] = o;
    g_cur[i] = o;
    g_deg[i] = 0;
}

// ---------------------------------------------------------------------------
// Bucket edges by dst; 4 edges per thread via int4/float4 loads.
__global__ void scatter_kernel(const int* __restrict__ ei,
                               const float* __restrict__ eattr) {
    int t = blockIdx.x * blockDim.x + threadIdx.x;
    int e = t * 4;
    if (e >= N_EDGES) return;
    int4   s = __ldg(reinterpret_cast<const int4*>(&ei[e]));
    int4   d = __ldg(reinterpret_cast<const int4*>(&ei[N_EDGES + e]));
    float4 a = __ldg(reinterpret_cast<const float4*>(&eattr[e]));
    g_csr[atomicAdd(&g_cur[d.x], 1)] = make_int2(s.x, __float_as_int(a.x));
    g_csr[atomicAdd(&g_cur[d.y], 1)] = make_int2(s.y, __float_as_int(a.y));
    g_csr[atomicAdd(&g_cur[d.z], 1)] = make_int2(s.z, __float_as_int(a.z));
    g_csr[atomicAdd(&g_cur[d.w], 1)] = make_int2(s.w, __float_as_int(a.w));
}

// ---------------------------------------------------------------------------
// Edge pass 1 (gather): warp per dst node. Lane-strided edges, 9-float
// accumulators, butterfly reduce, lane0 writes stride-12 row.
__global__ void edge1_gather(const float* __restrict__ We1,
                             const float* __restrict__ be1) {
    int gt = blockIdx.x * blockDim.x + threadIdx.x;
    int n = gt >> 5;
    int lane = gt & 31;
    if (n >= N_NODES) return;

    float w[9], b[9];
#pragma unroll
    for (int f = 0; f < 9; f++) { w[f] = __ldg(&We1[f]); b[f] = __ldg(&be1[f]); }

    int beg = __ldg(&g_off[n]);
    int end = __ldg(&g_off[n + 1]);

    float acc[9];
#pragma unroll
    for (int f = 0; f < 9; f++) acc[f] = 0.f;

    for (int j = beg + lane; j < end; j += 32) {
        int2 sa = __ldg(&g_csr[j]);
        float a = __int_as_float(sa.y);
        const float4* xr = reinterpret_cast<const float4*>(&g_xp[sa.x * 12]);
        float4 x0 = __ldg(xr + 0);
        float4 x1 = __ldg(xr + 1);
        float4 x2 = __ldg(xr + 2);
        acc[0] += fmaxf(x0.x + fmaf(a, w[0], b[0]), 0.f);
        acc[1] += fmaxf(x0.y + fmaf(a, w[1], b[1]), 0.f);
        acc[2] += fmaxf(x0.z + fmaf(a, w[2], b[2]), 0.f);
        acc[3] += fmaxf(x0.w + fmaf(a, w[3], b[3]), 0.f);
        acc[4] += fmaxf(x1.x + fmaf(a, w[4], b[4]), 0.f);
        acc[5] += fmaxf(x1.y + fmaf(a, w[5], b[5]), 0.f);
        acc[6] += fmaxf(x1.z + fmaf(a, w[6], b[6]), 0.f);
        acc[7] += fmaxf(x1.w + fmaf(a, w[7], b[7]), 0.f);
        acc[8] += fmaxf(x2.x + fmaf(a, w[8], b[8]), 0.f);
    }
#pragma unroll
    for (int f = 0; f < 9; f++) {
#pragma unroll
        for (int o = 16; o > 0; o >>= 1)
            acc[f] += __shfl_xor_sync(0xffffffffu, acc[f], o);
    }
    if (lane == 0) {
        float* dst = &g_agg[n * 12];
#pragma unroll
        for (int f = 0; f < 9; f++) dst[f] = acc[f];
    }
}

// ---------------------------------------------------------------------------
// Node MLP 1: z = x + agg; h1 = relu(relu(z@W1a+b1a)@W1b+b1b)
__global__ void mlp1_kernel(const float* __restrict__ x,
                            const float* __restrict__ W1a, const float* __restrict__ b1a,
                            const float* __restrict__ W1b, const float* __restrict__ b1b) {
    __shared__ __align__(16) float sWa[F_IN * H_DIM];
    __shared__ __align__(16) float sWb[H_DIM * H_DIM];
    __shared__ __align__(16) float sba[H_DIM];
    __shared__ __align__(16) float sbb[H_DIM];
    int tid = threadIdx.x;
    for (int i = tid; i < F_IN * H_DIM; i += blockDim.x) sWa[i] = W1a[i];
    for (int i = tid; i < H_DIM * H_DIM; i += blockDim.x) sWb[i] = W1b[i];
    if (tid < H_DIM) { sba[tid] = b1a[tid]; sbb[tid] = b1b[tid]; }
    __syncthreads();

    int n = blockIdx.x * blockDim.x + tid;
    if (n >= N_NODES) return;

    float z[F_IN];
#pragma unroll
    for (int f = 0; f < F_IN; f++) z[f] = x[n * 9 + f] + g_agg[n * 12 + f];

    float t[H_DIM];
#pragma unroll
    for (int j = 0; j < H_DIM; j += 4) {
        float4 acc = *reinterpret_cast<float4*>(&sba[j]);
#pragma unroll
        for (int f = 0; f < F_IN; f++) {
            float4 w = *reinterpret_cast<float4*>(&sWa[f * H_DIM + j]);
            acc.x = fmaf(z[f], w.x, acc.x);
            acc.y = fmaf(z[f], w.y, acc.y);
            acc.z = fmaf(z[f], w.z, acc.z);
            acc.w = fmaf(z[f], w.w, acc.w);
        }
        t[j + 0] = fmaxf(acc.x, 0.f);
        t[j + 1] = fmaxf(acc.y, 0.f);
        t[j + 2] = fmaxf(acc.z, 0.f);
        t[j + 3] = fmaxf(acc.w, 0.f);
    }

    for (int j = 0; j < H_DIM; j += 4) {
        float4 acc = *reinterpret_cast<float4*>(&sbb[j]);
#pragma unroll
        for (int k = 0; k < H_DIM; k++) {
            float4 w = *reinterpret_cast<float4*>(&sWb[k * H_DIM + j]);
            acc.x = fmaf(t[k], w.x, acc.x);
            acc.y = fmaf(t[k], w.y, acc.y);
            acc.z = fmaf(t[k], w.z, acc.z);
            acc.w = fmaf(t[k], w.w, acc.w);
        }
        float4 o;
        o.x = fmaxf(acc.x, 0.f);
        o.y = fmaxf(acc.y, 0.f);
        o.z = fmaxf(acc.z, 0.f);
        o.w = fmaxf(acc.w, 0.f);
        *reinterpret_cast<float4*>(&g_h1[n * H_DIM + j]) = o;
    }
}

// ---------------------------------------------------------------------------
// Edge pass 2 (gather): warp per dst node, lane owns float2 feature slice.
// 8-edge software pipeline: csr loaded 2-entries-at-a-time via int4 (j kept
// even by peeling), 8 independent h1-row gathers in flight.
__global__ void edge2_gather(const float* __restrict__ We2,
                             const float* __restrict__ be2) {
    int gt = blockIdx.x * blockDim.x + threadIdx.x;
    int n = gt >> 5;
    int lane = gt & 31;
    if (n >= N_NODES) return;
    int c = lane * 2;

    float2 w = __ldg(reinterpret_cast<const float2*>(&We2[c]));
    float2 b = __ldg(reinterpret_cast<const float2*>(&be2[c]));
    int beg = __ldg(&g_off[n]);
    int end = __ldg(&g_off[n + 1]);

    float2 acc = make_float2(0.f, 0.f);
    int j = beg;
    if ((j & 1) && j < end) {  // peel to make j even (int4 csr alignment)
        int2 sa = __ldg(&g_csr[j]);
        float a = __int_as_float(sa.y);
        float2 h = __ldg(reinterpret_cast<const float2*>(&g_h1[sa.x * H_DIM + c]));
        acc.x += fmaxf(h.x + fmaf(a, w.x, b.x), 0.f);
        acc.y += fmaxf(h.y + fmaf(a, w.y, b.y), 0.f);
        j++;
    }
    for (; j + 8 <= end; j += 8) {
        int4 p0 = __ldg(reinterpret_cast<const int4*>(&g_csr[j + 0]));
        int4 p1 = __ldg(reinterpret_cast<const int4*>(&g_csr[j + 2]));
        int4 p2 = __ldg(reinterpret_cast<const int4*>(&g_csr[j + 4]));
        int4 p3 = __ldg(reinterpret_cast<const int4*>(&g_csr[j + 6]));
        float2 h0 = __ldg(reinterpret_cast<const float2*>(&g_h1[p0.x * H_DIM + c]));
        float2 h1 = __ldg(reinterpret_cast<const float2*>(&g_h1[p0.z * H_DIM + c]));
        float2 h2 = __ldg(reinterpret_cast<const float2*>(&g_h1[p1.x * H_DIM + c]));
        float2 h3 = __ldg(reinterpret_cast<const float2*>(&g_h1[p1.z * H_DIM + c]));
        float2 h4 = __ldg(reinterpret_cast<const float2*>(&g_h1[p2.x * H_DIM + c]));
        float2 h5 = __ldg(reinterpret_cast<const float2*>(&g_h1[p2.z * H_DIM + c]));
        float2 h6 = __ldg(reinterpret_cast<const float2*>(&g_h1[p3.x * H_DIM + c]));
        float2 h7 = __ldg(reinterpret_cast<const float2*>(&g_h1[p3.z * H_DIM + c]));
        float a0 = __int_as_float(p0.y), a1 = __int_as_float(p0.w);
        float a2 = __int_as_float(p1.y), a3 = __int_as_float(p1.w);
        float a4 = __int_as_float(p2.y), a5 = __int_as_float(p2.w);
        float a6 = __int_as_float(p3.y), a7 = __int_as_float(p3.w);
        acc.x += fmaxf(h0.x + fmaf(a0, w.x, b.x), 0.f);
        acc.y += fmaxf(h0.y + fmaf(a0, w.y, b.y), 0.f);
        acc.x += fmaxf(h1.x + fmaf(a1, w.x, b.x), 0.f);
        acc.y += fmaxf(h1.y + fmaf(a1, w.y, b.y), 0.f);
        acc.x += fmaxf(h2.x + fmaf(a2, w.x, b.x), 0.f);
        acc.y += fmaxf(h2.y + fmaf(a2, w.y, b.y), 0.f);
        acc.x += fmaxf(h3.x + fmaf(a3, w.x, b.x), 0.f);
        acc.y += fmaxf(h3.y + fmaf(a3, w.y, b.y), 0.f);
        acc.x += fmaxf(h4.x + fmaf(a4, w.x, b.x), 0.f);
        acc.y += fmaxf(h4.y + fmaf(a4, w.y, b.y), 0.f);
        acc.x += fmaxf(h5.x + fmaf(a5, w.x, b.x), 0.f);
        acc.y += fmaxf(h5.y + fmaf(a5, w.y, b.y), 0.f);
        acc.x += fmaxf(h6.x + fmaf(a6, w.x, b.x), 0.f);
        acc.y += fmaxf(h6.y + fmaf(a6, w.y, b.y), 0.f);
        acc.x += fmaxf(h7.x + fmaf(a7, w.x, b.x), 0.f);
        acc.y += fmaxf(h7.y + fmaf(a7, w.y, b.y), 0.f);
    }
    for (; j < end; j++) {
        int2 sa = __ldg(&g_csr[j]);
        float a = __int_as_float(sa.y);
        float2 h = __ldg(reinterpret_cast<const float2*>(&g_h1[sa.x * H_DIM + c]));
        acc.x += fmaxf(h.x + fmaf(a, w.x, b.x), 0.f);
        acc.y += fmaxf(h.y + fmaf(a, w.y, b.y), 0.f);
    }
    *reinterpret_cast<float2*>(&g_agg[n * H_DIM + c]) = acc;
}

// ---------------------------------------------------------------------------
// Node MLP 2 + readout head + group segment-sum of expenses.
__global__ void mlp2_kernel(const float* __restrict__ W2a, const float* __restrict__ b2a,
                            const float* __restrict__ W2b, const float* __restrict__ b2b,
                            const float* __restrict__ Wr1, const float* __restrict__ br1,
                            const float* __restrict__ Wr2, const float* __restrict__ br2,
                            const int* __restrict__ batch,
                            const int* __restrict__ term,
                            const float* __restrict__ c_cost) {
    __shared__ __align__(16) float sWa[H_DIM * H_DIM];
    __shared__ __align__(16) float sWb[H_DIM * H_DIM];
    __shared__ __align__(16) float sWr1[H_DIM * 32];
    __shared__ __align__(16) float sba[H_DIM];
    __shared__ __align__(16) float sbb[H_DIM];
    __shared__ __align__(16) float sbr1[32];
    __shared__ __align__(16) float sWr2[32];
    __shared__ float sbr2;
    int tid = threadIdx.x;
    for (int i = tid; i < H_DIM * H_DIM; i += blockDim.x) { sWa[i] = W2a[i]; sWb[i] = W2b[i]; }
    for (int i = tid; i < H_DIM * 32; i += blockDim.x) sWr1[i] = Wr1[i];
    if (tid < H_DIM) { sba[tid] = b2a[tid]; sbb[tid] = b2b[tid]; }
    if (tid < 32) { sbr1[tid] = br1[tid]; sWr2[tid] = Wr2[tid]; }
    if (tid == 0) sbr2 = br2[0];
    __syncthreads();

    int n = blockIdx.x * blockDim.x + tid;
    if (n >= N_NODES) return;

    float z[H_DIM];
#pragma unroll
    for (int k = 0; k < H_DIM; k += 4) {
        float4 hv = *reinterpret_cast<const float4*>(&g_h1[n * H_DIM + k]);
        float4 av = *reinterpret_cast<const float4*>(&g_agg[n * H_DIM + k]);
        z[k + 0] = hv.x + av.x;
        z[k + 1] = hv.y + av.y;
        z[k + 2] = hv.z + av.z;
        z[k + 3] = hv.w + av.w;
    }

    float t[H_DIM];
    for (int j = 0; j < H_DIM; j += 4) {
        float4 acc = *reinterpret_cast<float4*>(&sba[j]);
#pragma unroll
        for (int k = 0; k < H_DIM; k++) {
            float4 w = *reinterpret_cast<float4*>(&sWa[k * H_DIM + j]);
            acc.x = fmaf(z[k], w.x, acc.x);
            acc.y = fmaf(z[k], w.y, acc.y);
            acc.z = fmaf(z[k], w.z, acc.z);
            acc.w = fmaf(z[k], w.w, acc.w);
        }
        t[j + 0] = fmaxf(acc.x, 0.f);
        t[j + 1] = fmaxf(acc.y, 0.f);
        t[j + 2] = fmaxf(acc.z, 0.f);
        t[j + 3] = fmaxf(acc.w, 0.f);
    }

    // reuse z[] as h2
    for (int j = 0; j < H_DIM; j += 4) {
        float4 acc = *reinterpret_cast<float4*>(&sbb[j]);
#pragma unroll
        for (int k = 0; k < H_DIM; k++) {
            float4 w = *reinterpret_cast<float4*>(&sWb[k * H_DIM + j]);
            acc.x = fmaf(t[k], w.x, acc.x);
            acc.y = fmaf(t[k], w.y, acc.y);
            acc.z = fmaf(t[k], w.z, acc.z);
            acc.w = fmaf(t[k], w.w, acc.w);
        }
        z[j + 0] = fmaxf(acc.x, 0.f);
        z[j + 1] = fmaxf(acc.y, 0.f);
        z[j + 2] = fmaxf(acc.z, 0.f);
        z[j + 3] = fmaxf(acc.w, 0.f);
    }

    // readout: r = relu(h2 @ Wr1 + br1) [32]; p = r @ Wr2 + br2
    float r[32];
    for (int j = 0; j < 32; j += 4) {
        float4 acc = *reinterpret_cast<float4*>(&sbr1[j]);
#pragma unroll
        for (int k = 0; k < H_DIM; k++) {
            float4 w = *reinterpret_cast<float4*>(&sWr1[k * 32 + j]);
            acc.x = fmaf(z[k], w.x, acc.x);
            acc.y = fmaf(z[k], w.y, acc.y);
            acc.z = fmaf(z[k], w.z, acc.z);
            acc.w = fmaf(z[k], w.w, acc.w);
        }
        r[j + 0] = fmaxf(acc.x, 0.f);
        r[j + 1] = fmaxf(acc.y, 0.f);
        r[j + 2] = fmaxf(acc.z, 0.f);
        r[j + 3] = fmaxf(acc.w, 0.f);
    }
    float p = sbr2;
#pragma unroll
    for (int k = 0; k < 32; k++) p = fmaf(r[k], sWr2[k], p);

    float pi = 1.f / (1.f + expf(-p));
    if (term[n] != 0) pi = 0.f;
    g_pi[n] = pi;
    atomicAdd(&g_texp[batch[n]], pi * c_cost[n]);
}

// ---------------------------------------------------------------------------
__global__ void final_kernel(const int* __restrict__ batch,
                             const float* __restrict__ B_total,
                             float* __restrict__ out) {
    int n = blockIdx.x * blockDim.x + threadIdx.x;
    if (n >= N_NODES) return;
    int b = batch[n];
    float ratio = fminf(B_total[b] / (g_texp[b] + 1e-12f), 1.f);
    out[n] = g_pi[n] * ratio;
}

// ---------------------------------------------------------------------------
extern "C" void kernel_launch(void* const* d_in, const int* in_sizes, int n_in,
                              void* d_out, int out_size) {
    const float* x       = (const float*)d_in[0];
    const int*   ei      = (const int*)d_in[1];
    const float* eattr   = (const float*)d_in[2];
    const int*   batch   = (const int*)d_in[3];
    const float* B_total = (const float*)d_in[4];
    const int*   term    = (const int*)d_in[5];
    const float* c_cost  = (const float*)d_in[6];
    const float* We1 = (const float*)d_in[7];
    const float* be1 = (const float*)d_in[8];
    const float* W1a = (const float*)d_in[9];
    const float* b1a = (const float*)d_in[10];
    const float* W1b = (const float*)d_in[11];
    const float* b1b = (const float*)d_in[12];
    const float* We2 = (const float*)d_in[13];
    const float* be2 = (const float*)d_in[14];
    const float* W2a = (const float*)d_in[15];
    const float* b2a = (const float*)d_in[16];
    const float* W2b = (const float*)d_in[17];
    const float* b2b = (const float*)d_in[18];
    const float* Wr1 = (const float*)d_in[19];
    const float* br1 = (const float*)d_in[20];
    const float* Wr2 = (const float*)d_in[21];
    const float* br2 = (const float*)d_in[22];
    float* out = (float*)d_out;

    const int NB_NODE = (N_NODES + 255) / 256;
    const int NB_EDGE4 = (N_EDGES / 4 + 255) / 256;

    prep_hist_kernel<<<NB_EDGE4, 256>>>(x, ei);
    scanA_kernel<<<N_SCAN_BLOCKS, SCAN_B>>>();
    scanB_kernel<<<1, 512>>>();
    scanC_kernel<<<NB_NODE, 256>>>();
    scatter_kernel<<<NB_EDGE4, 256>>>(ei, eattr);
    edge1_gather<<<(N_NODES * 32 + 255) / 256, 256>>>(We1, be1);
    mlp1_kernel<<<NB_NODE, 256>>>(x, W1a, b1a, W1b, b1b);
    edge2_gather<<<(N_NODES * 32 + 255) / 256, 256>>>(We2, be2);
    mlp2_kernel<<<NB_NODE, 256>>>(W2a, b2a, W2b, b2b, Wr1, br1, Wr2, br2,
                                  batch, term, c_cost);
    final_kernel<<<NB_NODE, 256>>>(batch, B_total, out);
}

// round 8
// speedup vs baseline: 1.3922x; 1.0030x over previous
#include <cuda_runtime.h>

#define N_NODES 100000
#define N_EDGES 3200000
#define G_GROUPS 128
#define F_IN 9
#define H_DIM 64
#define SCAN_B 256
#define N_SCAN_BLOCKS ((N_NODES + SCAN_B - 1) / SCAN_B)   // 391

// Scratch (__device__ globals; no allocation allowed).
// g_deg relies on zero-init at module load; scanC re-zeroes it after use so
// every launch (and every graph replay) starts with g_deg == 0.
__device__ __align__(16) float g_h1[N_NODES * H_DIM];   // hidden after conv1
__device__ __align__(16) float g_agg[N_NODES * H_DIM];  // aggregation (pass1 uses stride-12)
__device__ __align__(16) float g_xp[N_NODES * 12];      // x padded to 48B rows
__device__ int   g_deg[N_NODES];
__device__ int   g_off[N_NODES + 1];
__device__ int   g_cur[N_NODES];
__device__ int   g_bsum[N_SCAN_BLOCKS];
__device__ __align__(16) int2 g_csr[N_EDGES];           // (src, attr bits), bucketed by dst
__device__ __align__(16) float g_pi[N_NODES];
__device__ __align__(16) float g_texp[G_GROUPS];

__device__ __forceinline__ void red_add_v4(float* addr, float a, float b, float c, float d) {
    asm volatile("red.global.add.v4.f32 [%0], {%1,%2,%3,%4};"
                 :: "l"(addr), "f"(a), "f"(b), "f"(c), "f"(d) : "memory");
}

// ---------------------------------------------------------------------------
// Fused prep + histogram. prep: zero texp, pad x into stride-12 rows.
// hist: dst-degree histogram, 4 edges/thread via int4.
__global__ void prep_hist_kernel(const float* __restrict__ x,
                                 const int* __restrict__ ei) {
    int t = blockIdx.x * blockDim.x + threadIdx.x;
    if (t < G_GROUPS) g_texp[t] = 0.f;
    if (t < N_NODES) {
        float4 a = make_float4(x[t*9+0], x[t*9+1], x[t*9+2], x[t*9+3]);
        float4 b = make_float4(x[t*9+4], x[t*9+5], x[t*9+6], x[t*9+7]);
        float4 c = make_float4(x[t*9+8], 0.f, 0.f, 0.f);
        float4* p = reinterpret_cast<float4*>(&g_xp[t*12]);
        p[0] = a; p[1] = b; p[2] = c;
    }
    int e = t * 4;
    if (e < N_EDGES) {
        int4 d = __ldg(reinterpret_cast<const int4*>(&ei[N_EDGES + e]));
        atomicAdd(&g_deg[d.x], 1);
        atomicAdd(&g_deg[d.y], 1);
        atomicAdd(&g_deg[d.z], 1);
        atomicAdd(&g_deg[d.w], 1);
    }
}

// ---------------------------------------------------------------------------
// Parallel scan, phase A: per-block local exclusive scan (coalesced) of g_deg.
__global__ void scanA_kernel() {
    __shared__ int sh[SCAN_B];
    int tid = threadIdx.x;
    int i = blockIdx.x * SCAN_B + tid;
    int v = (i < N_NODES) ? g_deg[i] : 0;
    sh[tid] = v;
    __syncthreads();
#pragma unroll
    for (int off = 1; off < SCAN_B; off <<= 1) {
        int t = (tid >= off) ? sh[tid - off] : 0;
        __syncthreads();
        sh[tid] += t;
        __syncthreads();
    }
    if (i < N_NODES) g_off[i] = sh[tid] - v;   // local exclusive
    if (tid == SCAN_B - 1) g_bsum[blockIdx.x] = sh[tid];
}

// Phase B: one block scans the block sums (exclusive); writes g_off[N].
__global__ void scanB_kernel() {
    __shared__ int sh[512];
    int tid = threadIdx.x;
    int v = (tid < N_SCAN_BLOCKS) ? g_bsum[tid] : 0;
    sh[tid] = v;
    __syncthreads();
#pragma unroll
    for (int off = 1; off < 512; off <<= 1) {
        int t = (tid >= off) ? sh[tid - off] : 0;
        __syncthreads();
        sh[tid] += t;
        __syncthreads();
    }
    if (tid < N_SCAN_BLOCKS) g_bsum[tid] = sh[tid] - v;  // exclusive
    if (tid == N_SCAN_BLOCKS - 1) g_off[N_NODES] = sh[tid];
}

// Phase C: add block offsets; materialize g_cur; re-zero g_deg; zero the
// stride-12 agg region that scatter_red accumulates into.
__global__ void scanC_kernel() {
    int i = blockIdx.x * blockDim.x + threadIdx.x;
    if (i >= N_NODES) return;
    int o = g_off[i] + g_bsum[i >> 8];
    g_off[i] = o;
    g_cur[i] = o;
    g_deg[i] = 0;
    float4 z = make_float4(0.f, 0.f, 0.f, 0.f);
    float4* p = reinterpret_cast<float4*>(&g_agg[i * 12]);
    p[0] = z; p[1] = z; p[2] = z;
}

// ---------------------------------------------------------------------------
// Fused scatter + pass-1 aggregation. Per edge: bucket (s,a) into csr AND
// red.add.v4 the relu'd pass-1 message into g_agg (stride-12 rows).
__global__ void scatter_red_kernel(const int* __restrict__ ei,
                                   const float* __restrict__ eattr,
                                   const float* __restrict__ We1,
                                   const float* __restrict__ be1) {
    int t = blockIdx.x * blockDim.x + threadIdx.x;
    int e = t * 4;
    if (e >= N_EDGES) return;

    float w[9], bb[9];
#pragma unroll
    for (int f = 0; f < 9; f++) { w[f] = __ldg(&We1[f]); bb[f] = __ldg(&be1[f]); }

    int4   s = __ldg(reinterpret_cast<const int4*>(&ei[e]));
    int4   d = __ldg(reinterpret_cast<const int4*>(&ei[N_EDGES + e]));
    float4 a = __ldg(reinterpret_cast<const float4*>(&eattr[e]));

    int ss[4] = {s.x, s.y, s.z, s.w};
    int dd[4] = {d.x, d.y, d.z, d.w};
    float aa[4] = {a.x, a.y, a.z, a.w};

#pragma unroll
    for (int k = 0; k < 4; k++) {
        g_csr[atomicAdd(&g_cur[dd[k]], 1)] = make_int2(ss[k], __float_as_int(aa[k]));
        const float4* xr = reinterpret_cast<const float4*>(&g_xp[ss[k] * 12]);
        float4 x0 = __ldg(xr + 0);
        float4 x1 = __ldg(xr + 1);
        float4 x2 = __ldg(xr + 2);
        float av = aa[k];
        float m0 = fmaxf(x0.x + fmaf(av, w[0], bb[0]), 0.f);
        float m1 = fmaxf(x0.y + fmaf(av, w[1], bb[1]), 0.f);
        float m2 = fmaxf(x0.z + fmaf(av, w[2], bb[2]), 0.f);
        float m3 = fmaxf(x0.w + fmaf(av, w[3], bb[3]), 0.f);
        float m4 = fmaxf(x1.x + fmaf(av, w[4], bb[4]), 0.f);
        float m5 = fmaxf(x1.y + fmaf(av, w[5], bb[5]), 0.f);
        float m6 = fmaxf(x1.z + fmaf(av, w[6], bb[6]), 0.f);
        float m7 = fmaxf(x1.w + fmaf(av, w[7], bb[7]), 0.f);
        float m8 = fmaxf(x2.x + fmaf(av, w[8], bb[8]), 0.f);
        float* base = &g_agg[dd[k] * 12];
        red_add_v4(base + 0, m0, m1, m2, m3);
        red_add_v4(base + 4, m4, m5, m6, m7);
        red_add_v4(base + 8, m8, 0.f, 0.f, 0.f);
    }
}

// ---------------------------------------------------------------------------
// Node MLP 1: z = x + agg; h1 = relu(relu(z@W1a+b1a)@W1b+b1b)
__global__ void mlp1_kernel(const float* __restrict__ x,
                            const float* __restrict__ W1a, const float* __restrict__ b1a,
                            const float* __restrict__ W1b, const float* __restrict__ b1b) {
    __shared__ __align__(16) float sWa[F_IN * H_DIM];
    __shared__ __align__(16) float sWb[H_DIM * H_DIM];
    __shared__ __align__(16) float sba[H_DIM];
    __shared__ __align__(16) float sbb[H_DIM];
    int tid = threadIdx.x;
    for (int i = tid; i < F_IN * H_DIM; i += blockDim.x) sWa[i] = W1a[i];
    for (int i = tid; i < H_DIM * H_DIM; i += blockDim.x) sWb[i] = W1b[i];
    if (tid < H_DIM) { sba[tid] = b1a[tid]; sbb[tid] = b1b[tid]; }
    __syncthreads();

    int n = blockIdx.x * blockDim.x + tid;
    if (n >= N_NODES) return;

    float z[F_IN];
#pragma unroll
    for (int f = 0; f < F_IN; f++) z[f] = x[n * 9 + f] + g_agg[n * 12 + f];

    float t[H_DIM];
#pragma unroll
    for (int j = 0; j < H_DIM; j += 4) {
        float4 acc = *reinterpret_cast<float4*>(&sba[j]);
#pragma unroll
        for (int f = 0; f < F_IN; f++) {
            float4 w = *reinterpret_cast<float4*>(&sWa[f * H_DIM + j]);
            acc.x = fmaf(z[f], w.x, acc.x);
            acc.y = fmaf(z[f], w.y, acc.y);
            acc.z = fmaf(z[f], w.z, acc.z);
            acc.w = fmaf(z[f], w.w, acc.w);
        }
        t[j + 0] = fmaxf(acc.x, 0.f);
        t[j + 1] = fmaxf(acc.y, 0.f);
        t[j + 2] = fmaxf(acc.z, 0.f);
        t[j + 3] = fmaxf(acc.w, 0.f);
    }

    for (int j = 0; j < H_DIM; j += 4) {
        float4 acc = *reinterpret_cast<float4*>(&sbb[j]);
#pragma unroll
        for (int k = 0; k < H_DIM; k++) {
            float4 w = *reinterpret_cast<float4*>(&sWb[k * H_DIM + j]);
            acc.x = fmaf(t[k], w.x, acc.x);
            acc.y = fmaf(t[k], w.y, acc.y);
            acc.z = fmaf(t[k], w.z, acc.z);
            acc.w = fmaf(t[k], w.w, acc.w);
        }
        float4 o;
        o.x = fmaxf(acc.x, 0.f);
        o.y = fmaxf(acc.y, 0.f);
        o.z = fmaxf(acc.z, 0.f);
        o.w = fmaxf(acc.w, 0.f);
        *reinterpret_cast<float4*>(&g_h1[n * H_DIM + j]) = o;
    }
}

// ---------------------------------------------------------------------------
// Edge pass 2 (gather): warp per dst node, lane owns float2 feature slice.
// csr loaded 2-entries-at-a-time via int4; 8 h1-row gathers in flight.
__global__ void edge2_gather(const float* __restrict__ We2,
                             const float* __restrict__ be2) {
    int gt = blockIdx.x * blockDim.x + threadIdx.x;
    int n = gt >> 5;
    int lane = gt & 31;
    if (n >= N_NODES) return;
    int c = lane * 2;

    float2 w = __ldg(reinterpret_cast<const float2*>(&We2[c]));
    float2 b = __ldg(reinterpret_cast<const float2*>(&be2[c]));
    int beg = __ldg(&g_off[n]);
    int end = __ldg(&g_off[n + 1]);

    float2 acc = make_float2(0.f, 0.f);
    int j = beg;
    if ((j & 1) && j < end) {  // peel to make j even (int4 csr alignment)
        int2 sa = __ldg(&g_csr[j]);
        float a = __int_as_float(sa.y);
        float2 h = __ldg(reinterpret_cast<const float2*>(&g_h1[sa.x * H_DIM + c]));
        acc.x += fmaxf(h.x + fmaf(a, w.x, b.x), 0.f);
        acc.y += fmaxf(h.y + fmaf(a, w.y, b.y), 0.f);
        j++;
    }
    for (; j + 8 <= end; j += 8) {
        int4 p0 = __ldg(reinterpret_cast<const int4*>(&g_csr[j + 0]));
        int4 p1 = __ldg(reinterpret_cast<const int4*>(&g_csr[j + 2]));
        int4 p2 = __ldg(reinterpret_cast<const int4*>(&g_csr[j + 4]));
        int4 p3 = __ldg(reinterpret_cast<const int4*>(&g_csr[j + 6]));
        float2 h0 = __ldg(reinterpret_cast<const float2*>(&g_h1[p0.x * H_DIM + c]));
        float2 h1 = __ldg(reinterpret_cast<const float2*>(&g_h1[p0.z * H_DIM + c]));
        float2 h2 = __ldg(reinterpret_cast<const float2*>(&g_h1[p1.x * H_DIM + c]));
        float2 h3 = __ldg(reinterpret_cast<const float2*>(&g_h1[p1.z * H_DIM + c]));
        float2 h4 = __ldg(reinterpret_cast<const float2*>(&g_h1[p2.x * H_DIM + c]));
        float2 h5 = __ldg(reinterpret_cast<const float2*>(&g_h1[p2.z * H_DIM + c]));
        float2 h6 = __ldg(reinterpret_cast<const float2*>(&g_h1[p3.x * H_DIM + c]));
        float2 h7 = __ldg(reinterpret_cast<const float2*>(&g_h1[p3.z * H_DIM + c]));
        float a0 = __int_as_float(p0.y), a1 = __int_as_float(p0.w);
        float a2 = __int_as_float(p1.y), a3 = __int_as_float(p1.w);
        float a4 = __int_as_float(p2.y), a5 = __int_as_float(p2.w);
        float a6 = __int_as_float(p3.y), a7 = __int_as_float(p3.w);
        acc.x += fmaxf(h0.x + fmaf(a0, w.x, b.x), 0.f);
        acc.y += fmaxf(h0.y + fmaf(a0, w.y, b.y), 0.f);
        acc.x += fmaxf(h1.x + fmaf(a1, w.x, b.x), 0.f);
        acc.y += fmaxf(h1.y + fmaf(a1, w.y, b.y), 0.f);
        acc.x += fmaxf(h2.x + fmaf(a2, w.x, b.x), 0.f);
        acc.y += fmaxf(h2.y + fmaf(a2, w.y, b.y), 0.f);
        acc.x += fmaxf(h3.x + fmaf(a3, w.x, b.x), 0.f);
        acc.y += fmaxf(h3.y + fmaf(a3, w.y, b.y), 0.f);
        acc.x += fmaxf(h4.x + fmaf(a4, w.x, b.x), 0.f);
        acc.y += fmaxf(h4.y + fmaf(a4, w.y, b.y), 0.f);
        acc.x += fmaxf(h5.x + fmaf(a5, w.x, b.x), 0.f);
        acc.y += fmaxf(h5.y + fmaf(a5, w.y, b.y), 0.f);
        acc.x += fmaxf(h6.x + fmaf(a6, w.x, b.x), 0.f);
        acc.y += fmaxf(h6.y + fmaf(a6, w.y, b.y), 0.f);
        acc.x += fmaxf(h7.x + fmaf(a7, w.x, b.x), 0.f);
        acc.y += fmaxf(h7.y + fmaf(a7, w.y, b.y), 0.f);
    }
    for (; j < end; j++) {
        int2 sa = __ldg(&g_csr[j]);
        float a = __int_as_float(sa.y);
        float2 h = __ldg(reinterpret_cast<const float2*>(&g_h1[sa.x * H_DIM + c]));
        acc.x += fmaxf(h.x + fmaf(a, w.x, b.x), 0.f);
        acc.y += fmaxf(h.y + fmaf(a, w.y, b.y), 0.f);
    }
    *reinterpret_cast<float2*>(&g_agg[n * H_DIM + c]) = acc;
}

// ---------------------------------------------------------------------------
// Node MLP 2 + readout head + group segment-sum of expenses.
__global__ void mlp2_kernel(const float* __restrict__ W2a, const float* __restrict__ b2a,
                            const float* __restrict__ W2b, const float* __restrict__ b2b,
                            const float* __restrict__ Wr1, const float* __restrict__ br1,
                            const float* __restrict__ Wr2, const float* __restrict__ br2,
                            const int* __restrict__ batch,
                            const int* __restrict__ term,
                            const float* __restrict__ c_cost) {
    __shared__ __align__(16) float sWa[H_DIM * H_DIM];
    __shared__ __align__(16) float sWb[H_DIM * H_DIM];
    __shared__ __align__(16) float sWr1[H_DIM * 32];
    __shared__ __align__(16) float sba[H_DIM];
    __shared__ __align__(16) float sbb[H_DIM];
    __shared__ __align__(16) float sbr1[32];
    __shared__ __align__(16) float sWr2[32];
    __shared__ float sbr2;
    int tid = threadIdx.x;
    for (int i = tid; i < H_DIM * H_DIM; i += blockDim.x) { sWa[i] = W2a[i]; sWb[i] = W2b[i]; }
    for (int i = tid; i < H_DIM * 32; i += blockDim.x) sWr1[i] = Wr1[i];
    if (tid < H_DIM) { sba[tid] = b2a[tid]; sbb[tid] = b2b[tid]; }
    if (tid < 32) { sbr1[tid] = br1[tid]; sWr2[tid] = Wr2[tid]; }
    if (tid == 0) sbr2 = br2[0];
    __syncthreads();

    int n = blockIdx.x * blockDim.x + tid;
    if (n >= N_NODES) return;

    float z[H_DIM];
#pragma unroll
    for (int k = 0; k < H_DIM; k += 4) {
        float4 hv = *reinterpret_cast<const float4*>(&g_h1[n * H_DIM + k]);
        float4 av = *reinterpret_cast<const float4*>(&g_agg[n * H_DIM + k]);
        z[k + 0] = hv.x + av.x;
        z[k + 1] = hv.y + av.y;
        z[k + 2] = hv.z + av.z;
        z[k + 3] = hv.w + av.w;
    }

    float t[H_DIM];
    for (int j = 0; j < H_DIM; j += 4) {
        float4 acc = *reinterpret_cast<float4*>(&sba[j]);
#pragma unroll
        for (int k = 0; k < H_DIM; k++) {
            float4 w = *reinterpret_cast<float4*>(&sWa[k * H_DIM + j]);
            acc.x = fmaf(z[k], w.x, acc.x);
            acc.y = fmaf(z[k], w.y, acc.y);
            acc.z = fmaf(z[k], w.z, acc.z);
            acc.w = fmaf(z[k], w.w, acc.w);
        }
        t[j + 0] = fmaxf(acc.x, 0.f);
        t[j + 1] = fmaxf(acc.y, 0.f);
        t[j + 2] = fmaxf(acc.z, 0.f);
        t[j + 3] = fmaxf(acc.w, 0.f);
    }

    // reuse z[] as h2
    for (int j = 0; j < H_DIM; j += 4) {
        float4 acc = *reinterpret_cast<float4*>(&sbb[j]);
#pragma unroll
        for (int k = 0; k < H_DIM; k++) {
            float4 w = *reinterpret_cast<float4*>(&sWb[k * H_DIM + j]);
            acc.x = fmaf(t[k], w.x, acc.x);
            acc.y = fmaf(t[k], w.y, acc.y);
            acc.z = fmaf(t[k], w.z, acc.z);
            acc.w = fmaf(t[k], w.w, acc.w);
        }
        z[j + 0] = fmaxf(acc.x, 0.f);
        z[j + 1] = fmaxf(acc.y, 0.f);
        z[j + 2] = fmaxf(acc.z, 0.f);
        z[j + 3] = fmaxf(acc.w, 0.f);
    }

    // readout: r = relu(h2 @ Wr1 + br1) [32]; p = r @ Wr2 + br2
    float r[32];
    for (int j = 0; j < 32; j += 4) {
        float4 acc = *reinterpret_cast<float4*>(&sbr1[j]);
#pragma unroll
        for (int k = 0; k < H_DIM; k++) {
            float4 w = *reinterpret_cast<float4*>(&sWr1[k * 32 + j]);
            acc.x = fmaf(z[k], w.x, acc.x);
            acc.y = fmaf(z[k], w.y, acc.y);
            acc.z = fmaf(z[k], w.z, acc.z);
            acc.w = fmaf(z[k], w.w, acc.w);
        }
        r[j + 0] = fmaxf(acc.x, 0.f);
        r[j + 1] = fmaxf(acc.y, 0.f);
        r[j + 2] = fmaxf(acc.z, 0.f);
        r[j + 3] = fmaxf(acc.w, 0.f);
    }
    float p = sbr2;
#pragma unroll
    for (int k = 0; k < 32; k++) p = fmaf(r[k], sWr2[k], p);

    float pi = 1.f / (1.f + expf(-p));
    if (term[n] != 0) pi = 0.f;
    g_pi[n] = pi;
    atomicAdd(&g_texp[batch[n]], pi * c_cost[n]);
}

// ---------------------------------------------------------------------------
__global__ void final_kernel(const int* __restrict__ batch,
                             const float* __restrict__ B_total,
                             float* __restrict__ out) {
    int n = blockIdx.x * blockDim.x + threadIdx.x;
    if (n >= N_NODES) return;
    int b = batch[n];
    float ratio = fminf(B_total[b] / (g_texp[b] + 1e-12f), 1.f);
    out[n] = g_pi[n] * ratio;
}

// ---------------------------------------------------------------------------
extern "C" void kernel_launch(void* const* d_in, const int* in_sizes, int n_in,
                              void* d_out, int out_size) {
    const float* x       = (const float*)d_in[0];
    const int*   ei      = (const int*)d_in[1];
    const float* eattr   = (const float*)d_in[2];
    const int*   batch   = (const int*)d_in[3];
    const float* B_total = (const float*)d_in[4];
    const int*   term    = (const int*)d_in[5];
    const float* c_cost  = (const float*)d_in[6];
    const float* We1 = (const float*)d_in[7];
    const float* be1 = (const float*)d_in[8];
    const float* W1a = (const float*)d_in[9];
    const float* b1a = (const float*)d_in[10];
    const float* W1b = (const float*)d_in[11];
    const float* b1b = (const float*)d_in[12];
    const float* We2 = (const float*)d_in[13];
    const float* be2 = (const float*)d_in[14];
    const float* W2a = (const float*)d_in[15];
    const float* b2a = (const float*)d_in[16];
    const float* W2b = (const float*)d_in[17];
    const float* b2b = (const float*)d_in[18];
    const float* Wr1 = (const float*)d_in[19];
    const float* br1 = (const float*)d_in[20];
    const float* Wr2 = (const float*)d_in[21];
    const float* br2 = (const float*)d_in[22];
    float* out = (float*)d_out;

    const int NB_NODE = (N_NODES + 255) / 256;
    const int NB_EDGE4 = (N_EDGES / 4 + 255) / 256;

    prep_hist_kernel<<<NB_EDGE4, 256>>>(x, ei);
    scanA_kernel<<<N_SCAN_BLOCKS, SCAN_B>>>();
    scanB_kernel<<<1, 512>>>();
    scanC_kernel<<<NB_NODE, 256>>>();
    scatter_red_kernel<<<NB_EDGE4, 256>>>(ei, eattr, We1, be1);
    mlp1_kernel<<<NB_NODE, 256>>>(x, W1a, b1a, W1b, b1b);
    edge2_gather<<<(N_NODES * 32 + 255) / 256, 256>>>(We2, be2);
    mlp2_kernel<<<NB_NODE, 256>>>(W2a, b2a, W2b, b2b, Wr1, br1, Wr2, br2,
                                  batch, term, c_cost);
    final_kernel<<<NB_NODE, 256>>>(batch, B_total, out);
}

// round 9
// speedup vs baseline: 1.4165x; 1.0175x over previous
#include <cuda_runtime.h>
#include <cuda_fp16.h>

#define N_NODES 100000
#define N_EDGES 3200000
#define G_GROUPS 128
#define F_IN 9
#define H_DIM 64
#define SCAN_B 256
#define N_SCAN_BLOCKS ((N_NODES + SCAN_B - 1) / SCAN_B)   // 391

// Scratch (__device__ globals; no allocation allowed).
// g_deg relies on zero-init at module load; scanC re-zeroes it after use so
// every launch (and every graph replay) starts with g_deg == 0.
__device__ __align__(16) __half2 g_h1h[N_NODES * 32];   // hidden after conv1 (fp16x2, 128B rows)
__device__ __align__(16) float g_agg[N_NODES * H_DIM];  // aggregation (pass1 uses stride-12)
__device__ __align__(16) float g_xp[N_NODES * 12];      // x padded to 48B rows
__device__ int   g_deg[N_NODES];
__device__ int   g_off[N_NODES + 1];
__device__ int   g_cur[N_NODES];
__device__ int   g_bsum[N_SCAN_BLOCKS];
__device__ __align__(16) int2 g_csr[N_EDGES];           // (src, attr bits), bucketed by dst
__device__ __align__(16) float g_pi[N_NODES];
__device__ __align__(16) float g_texp[G_GROUPS];

__device__ __forceinline__ void red_add_v4(float* addr, float a, float b, float c, float d) {
    asm volatile("red.global.add.v4.f32 [%0], {%1,%2,%3,%4};"
                 :: "l"(addr), "f"(a), "f"(b), "f"(c), "f"(d) : "memory");
}

// ---------------------------------------------------------------------------
// Fused prep + histogram. prep: zero texp, pad x into stride-12 rows.
// hist: dst-degree histogram, 4 edges/thread via int4.
__global__ void prep_hist_kernel(const float* __restrict__ x,
                                 const int* __restrict__ ei) {
    int t = blockIdx.x * blockDim.x + threadIdx.x;
    if (t < G_GROUPS) g_texp[t] = 0.f;
    if (t < N_NODES) {
        float4 a = make_float4(x[t*9+0], x[t*9+1], x[t*9+2], x[t*9+3]);
        float4 b = make_float4(x[t*9+4], x[t*9+5], x[t*9+6], x[t*9+7]);
        float4 c = make_float4(x[t*9+8], 0.f, 0.f, 0.f);
        float4* p = reinterpret_cast<float4*>(&g_xp[t*12]);
        p[0] = a; p[1] = b; p[2] = c;
    }
    int e = t * 4;
    if (e < N_EDGES) {
        int4 d = __ldg(reinterpret_cast<const int4*>(&ei[N_EDGES + e]));
        atomicAdd(&g_deg[d.x], 1);
        atomicAdd(&g_deg[d.y], 1);
        atomicAdd(&g_deg[d.z], 1);
        atomicAdd(&g_deg[d.w], 1);
    }
}

// ---------------------------------------------------------------------------
// Parallel scan, phase A: per-block local exclusive scan (coalesced) of g_deg.
__global__ void scanA_kernel() {
    __shared__ int sh[SCAN_B];
    int tid = threadIdx.x;
    int i = blockIdx.x * SCAN_B + tid;
    int v = (i < N_NODES) ? g_deg[i] : 0;
    sh[tid] = v;
    __syncthreads();
#pragma unroll
    for (int off = 1; off < SCAN_B; off <<= 1) {
        int t = (tid >= off) ? sh[tid - off] : 0;
        __syncthreads();
        sh[tid] += t;
        __syncthreads();
    }
    if (i < N_NODES) g_off[i] = sh[tid] - v;   // local exclusive
    if (tid == SCAN_B - 1) g_bsum[blockIdx.x] = sh[tid];
}

// Phase B: one block scans the block sums (exclusive); writes g_off[N].
__global__ void scanB_kernel() {
    __shared__ int sh[512];
    int tid = threadIdx.x;
    int v = (tid < N_SCAN_BLOCKS) ? g_bsum[tid] : 0;
    sh[tid] = v;
    __syncthreads();
#pragma unroll
    for (int off = 1; off < 512; off <<= 1) {
        int t = (tid >= off) ? sh[tid - off] : 0;
        __syncthreads();
        sh[tid] += t;
        __syncthreads();
    }
    if (tid < N_SCAN_BLOCKS) g_bsum[tid] = sh[tid] - v;  // exclusive
    if (tid == N_SCAN_BLOCKS - 1) g_off[N_NODES] = sh[tid];
}

// Phase C: add block offsets; materialize g_cur; re-zero g_deg; zero the
// stride-12 agg region that scatter_red accumulates into.
__global__ void scanC_kernel() {
    int i = blockIdx.x * blockDim.x + threadIdx.x;
    if (i >= N_NODES) return;
    int o = g_off[i] + g_bsum[i >> 8];
    g_off[i] = o;
    g_cur[i] = o;
    g_deg[i] = 0;
    float4 z = make_float4(0.f, 0.f, 0.f, 0.f);
    float4* p = reinterpret_cast<float4*>(&g_agg[i * 12]);
    p[0] = z; p[1] = z; p[2] = z;
}

// ---------------------------------------------------------------------------
// Fused scatter + pass-1 aggregation. Per edge: bucket (s,a) into csr AND
// red.add.v4 the relu'd pass-1 message into g_agg (stride-12 rows).
__global__ void scatter_red_kernel(const int* __restrict__ ei,
                                   const float* __restrict__ eattr,
                                   const float* __restrict__ We1,
                                   const float* __restrict__ be1) {
    int t = blockIdx.x * blockDim.x + threadIdx.x;
    int e = t * 4;
    if (e >= N_EDGES) return;

    float w[9], bb[9];
#pragma unroll
    for (int f = 0; f < 9; f++) { w[f] = __ldg(&We1[f]); bb[f] = __ldg(&be1[f]); }

    int4   s = __ldg(reinterpret_cast<const int4*>(&ei[e]));
    int4   d = __ldg(reinterpret_cast<const int4*>(&ei[N_EDGES + e]));
    float4 a = __ldg(reinterpret_cast<const float4*>(&eattr[e]));

    int ss[4] = {s.x, s.y, s.z, s.w};
    int dd[4] = {d.x, d.y, d.z, d.w};
    float aa[4] = {a.x, a.y, a.z, a.w};

#pragma unroll
    for (int k = 0; k < 4; k++) {
        g_csr[atomicAdd(&g_cur[dd[k]], 1)] = make_int2(ss[k], __float_as_int(aa[k]));
        const float4* xr = reinterpret_cast<const float4*>(&g_xp[ss[k] * 12]);
        float4 x0 = __ldg(xr + 0);
        float4 x1 = __ldg(xr + 1);
        float4 x2 = __ldg(xr + 2);
        float av = aa[k];
        float m0 = fmaxf(x0.x + fmaf(av, w[0], bb[0]), 0.f);
        float m1 = fmaxf(x0.y + fmaf(av, w[1], bb[1]), 0.f);
        float m2 = fmaxf(x0.z + fmaf(av, w[2], bb[2]), 0.f);
        float m3 = fmaxf(x0.w + fmaf(av, w[3], bb[3]), 0.f);
        float m4 = fmaxf(x1.x + fmaf(av, w[4], bb[4]), 0.f);
        float m5 = fmaxf(x1.y + fmaf(av, w[5], bb[5]), 0.f);
        float m6 = fmaxf(x1.z + fmaf(av, w[6], bb[6]), 0.f);
        float m7 = fmaxf(x1.w + fmaf(av, w[7], bb[7]), 0.f);
        float m8 = fmaxf(x2.x + fmaf(av, w[8], bb[8]), 0.f);
        float* base = &g_agg[dd[k] * 12];
        red_add_v4(base + 0, m0, m1, m2, m3);
        red_add_v4(base + 4, m4, m5, m6, m7);
        red_add_v4(base + 8, m8, 0.f, 0.f, 0.f);
    }
}

// ---------------------------------------------------------------------------
// Node MLP 1: z = x + agg; h1 = relu(relu(z@W1a+b1a)@W1b+b1b), stored fp16.
__global__ void mlp1_kernel(const float* __restrict__ x,
                            const float* __restrict__ W1a, const float* __restrict__ b1a,
                            const float* __restrict__ W1b, const float* __restrict__ b1b) {
    __shared__ __align__(16) float sWa[F_IN * H_DIM];
    __shared__ __align__(16) float sWb[H_DIM * H_DIM];
    __shared__ __align__(16) float sba[H_DIM];
    __shared__ __align__(16) float sbb[H_DIM];
    int tid = threadIdx.x;
    for (int i = tid; i < F_IN * H_DIM; i += blockDim.x) sWa[i] = W1a[i];
    for (int i = tid; i < H_DIM * H_DIM; i += blockDim.x) sWb[i] = W1b[i];
    if (tid < H_DIM) { sba[tid] = b1a[tid]; sbb[tid] = b1b[tid]; }
    __syncthreads();

    int n = blockIdx.x * blockDim.x + tid;
    if (n >= N_NODES) return;

    float z[F_IN];
#pragma unroll
    for (int f = 0; f < F_IN; f++) z[f] = x[n * 9 + f] + g_agg[n * 12 + f];

    float t[H_DIM];
#pragma unroll
    for (int j = 0; j < H_DIM; j += 4) {
        float4 acc = *reinterpret_cast<float4*>(&sba[j]);
#pragma unroll
        for (int f = 0; f < F_IN; f++) {
            float4 w = *reinterpret_cast<float4*>(&sWa[f * H_DIM + j]);
            acc.x = fmaf(z[f], w.x, acc.x);
            acc.y = fmaf(z[f], w.y, acc.y);
            acc.z = fmaf(z[f], w.z, acc.z);
            acc.w = fmaf(z[f], w.w, acc.w);
        }
        t[j + 0] = fmaxf(acc.x, 0.f);
        t[j + 1] = fmaxf(acc.y, 0.f);
        t[j + 2] = fmaxf(acc.z, 0.f);
        t[j + 3] = fmaxf(acc.w, 0.f);
    }

    __half2 hrow[32];
#pragma unroll
    for (int j = 0; j < H_DIM; j += 4) {
        float4 acc = *reinterpret_cast<float4*>(&sbb[j]);
#pragma unroll
        for (int k = 0; k < H_DIM; k++) {
            float4 w = *reinterpret_cast<float4*>(&sWb[k * H_DIM + j]);
            acc.x = fmaf(t[k], w.x, acc.x);
            acc.y = fmaf(t[k], w.y, acc.y);
            acc.z = fmaf(t[k], w.z, acc.z);
            acc.w = fmaf(t[k], w.w, acc.w);
        }
        hrow[j / 2 + 0] = __floats2half2_rn(fmaxf(acc.x, 0.f), fmaxf(acc.y, 0.f));
        hrow[j / 2 + 1] = __floats2half2_rn(fmaxf(acc.z, 0.f), fmaxf(acc.w, 0.f));
    }
    // 8 x 16B stores (128B row)
    uint4* dst = reinterpret_cast<uint4*>(&g_h1h[n * 32]);
    const uint4* src = reinterpret_cast<const uint4*>(hrow);
#pragma unroll
    for (int q = 0; q < 8; q++) dst[q] = src[q];
}

// ---------------------------------------------------------------------------
// Edge pass 2 (gather): warp per dst node, lane owns 2 features (one half2).
// h1 row read = 128B/warp (1 line). csr loaded 2-at-a-time via int4; 8 edges
// in flight. Accumulation in fp32.
__global__ void edge2_gather(const float* __restrict__ We2,
                             const float* __restrict__ be2) {
    int gt = blockIdx.x * blockDim.x + threadIdx.x;
    int n = gt >> 5;
    int lane = gt & 31;
    if (n >= N_NODES) return;
    int c = lane * 2;

    float2 w = __ldg(reinterpret_cast<const float2*>(&We2[c]));
    float2 b = __ldg(reinterpret_cast<const float2*>(&be2[c]));
    int beg = __ldg(&g_off[n]);
    int end = __ldg(&g_off[n + 1]);

    float2 acc = make_float2(0.f, 0.f);
    int j = beg;
    if ((j & 1) && j < end) {  // peel to make j even (int4 csr alignment)
        int2 sa = __ldg(&g_csr[j]);
        float a = __int_as_float(sa.y);
        float2 h = __half22float2(g_h1h[sa.x * 32 + lane]);
        acc.x += fmaxf(h.x + fmaf(a, w.x, b.x), 0.f);
        acc.y += fmaxf(h.y + fmaf(a, w.y, b.y), 0.f);
        j++;
    }
    for (; j + 8 <= end; j += 8) {
        int4 p0 = __ldg(reinterpret_cast<const int4*>(&g_csr[j + 0]));
        int4 p1 = __ldg(reinterpret_cast<const int4*>(&g_csr[j + 2]));
        int4 p2 = __ldg(reinterpret_cast<const int4*>(&g_csr[j + 4]));
        int4 p3 = __ldg(reinterpret_cast<const int4*>(&g_csr[j + 6]));
        float2 h0 = __half22float2(g_h1h[p0.x * 32 + lane]);
        float2 h1 = __half22float2(g_h1h[p0.z * 32 + lane]);
        float2 h2 = __half22float2(g_h1h[p1.x * 32 + lane]);
        float2 h3 = __half22float2(g_h1h[p1.z * 32 + lane]);
        float2 h4 = __half22float2(g_h1h[p2.x * 32 + lane]);
        float2 h5 = __half22float2(g_h1h[p2.z * 32 + lane]);
        float2 h6 = __half22float2(g_h1h[p3.x * 32 + lane]);
        float2 h7 = __half22float2(g_h1h[p3.z * 32 + lane]);
        float a0 = __int_as_float(p0.y), a1 = __int_as_float(p0.w);
        float a2 = __int_as_float(p1.y), a3 = __int_as_float(p1.w);
        float a4 = __int_as_float(p2.y), a5 = __int_as_float(p2.w);
        float a6 = __int_as_float(p3.y), a7 = __int_as_float(p3.w);
        acc.x += fmaxf(h0.x + fmaf(a0, w.x, b.x), 0.f);
        acc.y += fmaxf(h0.y + fmaf(a0, w.y, b.y), 0.f);
        acc.x += fmaxf(h1.x + fmaf(a1, w.x, b.x), 0.f);
        acc.y += fmaxf(h1.y + fmaf(a1, w.y, b.y), 0.f);
        acc.x += fmaxf(h2.x + fmaf(a2, w.x, b.x), 0.f);
        acc.y += fmaxf(h2.y + fmaf(a2, w.y, b.y), 0.f);
        acc.x += fmaxf(h3.x + fmaf(a3, w.x, b.x), 0.f);
        acc.y += fmaxf(h3.y + fmaf(a3, w.y, b.y), 0.f);
        acc.x += fmaxf(h4.x + fmaf(a4, w.x, b.x), 0.f);
        acc.y += fmaxf(h4.y + fmaf(a4, w.y, b.y), 0.f);
        acc.x += fmaxf(h5.x + fmaf(a5, w.x, b.x), 0.f);
        acc.y += fmaxf(h5.y + fmaf(a5, w.y, b.y), 0.f);
        acc.x += fmaxf(h6.x + fmaf(a6, w.x, b.x), 0.f);
        acc.y += fmaxf(h6.y + fmaf(a6, w.y, b.y), 0.f);
        acc.x += fmaxf(h7.x + fmaf(a7, w.x, b.x), 0.f);
        acc.y += fmaxf(h7.y + fmaf(a7, w.y, b.y), 0.f);
    }
    for (; j < end; j++) {
        int2 sa = __ldg(&g_csr[j]);
        float a = __int_as_float(sa.y);
        float2 h = __half22float2(g_h1h[sa.x * 32 + lane]);
        acc.x += fmaxf(h.x + fmaf(a, w.x, b.x), 0.f);
        acc.y += fmaxf(h.y + fmaf(a, w.y, b.y), 0.f);
    }
    *reinterpret_cast<float2*>(&g_agg[n * H_DIM + c]) = acc;
}

// ---------------------------------------------------------------------------
// Node MLP 2 + readout head + group segment-sum of expenses.
__global__ void mlp2_kernel(const float* __restrict__ W2a, const float* __restrict__ b2a,
                            const float* __restrict__ W2b, const float* __restrict__ b2b,
                            const float* __restrict__ Wr1, const float* __restrict__ br1,
                            const float* __restrict__ Wr2, const float* __restrict__ br2,
                            const int* __restrict__ batch,
                            const int* __restrict__ term,
                            const float* __restrict__ c_cost) {
    __shared__ __align__(16) float sWa[H_DIM * H_DIM];
    __shared__ __align__(16) float sWb[H_DIM * H_DIM];
    __shared__ __align__(16) float sWr1[H_DIM * 32];
    __shared__ __align__(16) float sba[H_DIM];
    __shared__ __align__(16) float sbb[H_DIM];
    __shared__ __align__(16) float sbr1[32];
    __shared__ __align__(16) float sWr2[32];
    __shared__ float sbr2;
    int tid = threadIdx.x;
    for (int i = tid; i < H_DIM * H_DIM; i += blockDim.x) { sWa[i] = W2a[i]; sWb[i] = W2b[i]; }
    for (int i = tid; i < H_DIM * 32; i += blockDim.x) sWr1[i] = Wr1[i];
    if (tid < H_DIM) { sba[tid] = b2a[tid]; sbb[tid] = b2b[tid]; }
    if (tid < 32) { sbr1[tid] = br1[tid]; sWr2[tid] = Wr2[tid]; }
    if (tid == 0) sbr2 = br2[0];
    __syncthreads();

    int n = blockIdx.x * blockDim.x + tid;
    if (n >= N_NODES) return;

    // load fp16 h1 row (8 x 16B) + fp32 agg, z = h1 + agg
    uint4 hraw[8];
    const uint4* hsrc = reinterpret_cast<const uint4*>(&g_h1h[n * 32]);
#pragma unroll
    for (int q = 0; q < 8; q++) hraw[q] = hsrc[q];
    const __half2* hp = reinterpret_cast<const __half2*>(hraw);

    float z[H_DIM];
#pragma unroll
    for (int k = 0; k < H_DIM; k += 4) {
        float2 a01 = __half22float2(hp[k / 2 + 0]);
        float2 a23 = __half22float2(hp[k / 2 + 1]);
        float4 av = *reinterpret_cast<const float4*>(&g_agg[n * H_DIM + k]);
        z[k + 0] = a01.x + av.x;
        z[k + 1] = a01.y + av.y;
        z[k + 2] = a23.x + av.z;
        z[k + 3] = a23.y + av.w;
    }

    float t[H_DIM];
    for (int j = 0; j < H_DIM; j += 4) {
        float4 acc = *reinterpret_cast<float4*>(&sba[j]);
#pragma unroll
        for (int k = 0; k < H_DIM; k++) {
            float4 w = *reinterpret_cast<float4*>(&sWa[k * H_DIM + j]);
            acc.x = fmaf(z[k], w.x, acc.x);
            acc.y = fmaf(z[k], w.y, acc.y);
            acc.z = fmaf(z[k], w.z, acc.z);
            acc.w = fmaf(z[k], w.w, acc.w);
        }
        t[j + 0] = fmaxf(acc.x, 0.f);
        t[j + 1] = fmaxf(acc.y, 0.f);
        t[j + 2] = fmaxf(acc.z, 0.f);
        t[j + 3] = fmaxf(acc.w, 0.f);
    }

    // reuse z[] as h2
    for (int j = 0; j < H_DIM; j += 4) {
        float4 acc = *reinterpret_cast<float4*>(&sbb[j]);
#pragma unroll
        for (int k = 0; k < H_DIM; k++) {
            float4 w = *reinterpret_cast<float4*>(&sWb[k * H_DIM + j]);
            acc.x = fmaf(t[k], w.x, acc.x);
            acc.y = fmaf(t[k], w.y, acc.y);
            acc.z = fmaf(t[k], w.z, acc.z);
            acc.w = fmaf(t[k], w.w, acc.w);
        }
        z[j + 0] = fmaxf(acc.x, 0.f);
        z[j + 1] = fmaxf(acc.y, 0.f);
        z[j + 2] = fmaxf(acc.z, 0.f);
        z[j + 3] = fmaxf(acc.w, 0.f);
    }

    // readout: r = relu(h2 @ Wr1 + br1) [32]; p = r @ Wr2 + br2
    float r[32];
    for (int j = 0; j < 32; j += 4) {
        float4 acc = *reinterpret_cast<float4*>(&sbr1[j]);
#pragma unroll
        for (int k = 0; k < H_DIM; k++) {
            float4 w = *reinterpret_cast<float4*>(&sWr1[k * 32 + j]);
            acc.x = fmaf(z[k], w.x, acc.x);
            acc.y = fmaf(z[k], w.y, acc.y);
            acc.z = fmaf(z[k], w.z, acc.z);
            acc.w = fmaf(z[k], w.w, acc.w);
        }
        r[j + 0] = fmaxf(acc.x, 0.f);
        r[j + 1] = fmaxf(acc.y, 0.f);
        r[j + 2] = fmaxf(acc.z, 0.f);
        r[j + 3] = fmaxf(acc.w, 0.f);
    }
    float p = sbr2;
#pragma unroll
    for (int k = 0; k < 32; k++) p = fmaf(r[k], sWr2[k], p);

    float pi = 1.f / (1.f + expf(-p));
    if (term[n] != 0) pi = 0.f;
    g_pi[n] = pi;
    atomicAdd(&g_texp[batch[n]], pi * c_cost[n]);
}

// ---------------------------------------------------------------------------
__global__ void final_kernel(const int* __restrict__ batch,
                             const float* __restrict__ B_total,
                             float* __restrict__ out) {
    int n = blockIdx.x * blockDim.x + threadIdx.x;
    if (n >= N_NODES) return;
    int b = batch[n];
    float ratio = fminf(B_total[b] / (g_texp[b] + 1e-12f), 1.f);
    out[n] = g_pi[n] * ratio;
}

// ---------------------------------------------------------------------------
extern "C" void kernel_launch(void* const* d_in, const int* in_sizes, int n_in,
                              void* d_out, int out_size) {
    const float* x       = (const float*)d_in[0];
    const int*   ei      = (const int*)d_in[1];
    const float* eattr   = (const float*)d_in[2];
    const int*   batch   = (const int*)d_in[3];
    const float* B_total = (const float*)d_in[4];
    const int*   term    = (const int*)d_in[5];
    const float* c_cost  = (const float*)d_in[6];
    const float* We1 = (const float*)d_in[7];
    const float* be1 = (const float*)d_in[8];
    const float* W1a = (const float*)d_in[9];
    const float* b1a = (const float*)d_in[10];
    const float* W1b = (const float*)d_in[11];
    const float* b1b = (const float*)d_in[12];
    const float* We2 = (const float*)d_in[13];
    const float* be2 = (const float*)d_in[14];
    const float* W2a = (const float*)d_in[15];
    const float* b2a = (const float*)d_in[16];
    const float* W2b = (const float*)d_in[17];
    const float* b2b = (const float*)d_in[18];
    const float* Wr1 = (const float*)d_in[19];
    const float* br1 = (const float*)d_in[20];
    const float* Wr2 = (const float*)d_in[21];
    const float* br2 = (const float*)d_in[22];
    float* out = (float*)d_out;

    const int NB_NODE = (N_NODES + 255) / 256;
    const int NB_EDGE4 = (N_EDGES / 4 + 255) / 256;

    prep_hist_kernel<<<NB_EDGE4, 256>>>(x, ei);
    scanA_kernel<<<N_SCAN_BLOCKS, SCAN_B>>>();
    scanB_kernel<<<1, 512>>>();
    scanC_kernel<<<NB_NODE, 256>>>();
    scatter_red_kernel<<<NB_EDGE4, 256>>>(ei, eattr, We1, be1);
    mlp1_kernel<<<NB_NODE, 256>>>(x, W1a, b1a, W1b, b1b);
    edge2_gather<<<(N_NODES * 32 + 255) / 256, 256>>>(We2, be2);
    mlp2_kernel<<<NB_NODE, 256>>>(W2a, b2a, W2b, b2b, Wr1, br1, Wr2, br2,
                                  batch, term, c_cost);
    final_kernel<<<NB_NODE, 256>>>(batch, B_total, out);
}

// round 10
// speedup vs baseline: 1.4853x; 1.0485x over previous
#include <cuda_runtime.h>
#include <cuda_fp16.h>

#define N_NODES 100000
#define N_EDGES 3200000
#define G_GROUPS 128
#define F_IN 9
#define H_DIM 64
#define SCAN_B 256
#define N_SCAN_BLOCKS ((N_NODES + SCAN_B - 1) / SCAN_B)   // 391

// Scratch (__device__ globals; no allocation allowed).
// g_deg relies on zero-init at module load; scanC re-zeroes it after use so
// every launch (and every graph replay) starts with g_deg == 0.
__device__ __align__(16) __half2 g_h1h[N_NODES * 32];   // hidden after conv1 (fp16x2, 128B rows)
__device__ __align__(16) __half2 g_xh[N_NODES * 8];     // x padded fp16 rows (32B, 1 line each)
__device__ __align__(16) float g_agg[N_NODES * H_DIM];  // aggregation (pass1 uses stride-12)
__device__ int   g_deg[N_NODES];
__device__ int   g_off[N_NODES + 1];
__device__ int   g_cur[N_NODES];
__device__ int   g_bsum[N_SCAN_BLOCKS];
__device__ __align__(16) int2 g_csr[N_EDGES];           // (src, attr bits), bucketed by dst
__device__ __align__(16) float g_pi[N_NODES];
__device__ __align__(16) float g_texp[G_GROUPS];

__device__ __forceinline__ void red_add_v4(float* addr, float a, float b, float c, float d) {
    asm volatile("red.global.add.v4.f32 [%0], {%1,%2,%3,%4};"
                 :: "l"(addr), "f"(a), "f"(b), "f"(c), "f"(d) : "memory");
}
__device__ __forceinline__ void red_add_f32(float* addr, float a) {
    asm volatile("red.global.add.f32 [%0], %1;" :: "l"(addr), "f"(a) : "memory");
}
__device__ __forceinline__ __half2 u2h2(unsigned int u) {
    __half2 h; *reinterpret_cast<unsigned int*>(&h) = u; return h;
}
__device__ __forceinline__ unsigned int h22u(__half2 h) {
    return *reinterpret_cast<unsigned int*>(&h);
}

// ---------------------------------------------------------------------------
// Fused prep + histogram. prep: zero texp, pack x into fp16 32B rows.
// hist: dst-degree histogram, 4 edges/thread via int4.
__global__ void prep_hist_kernel(const float* __restrict__ x,
                                 const int* __restrict__ ei) {
    int t = blockIdx.x * blockDim.x + threadIdx.x;
    if (t < G_GROUPS) g_texp[t] = 0.f;
    if (t < N_NODES) {
        const float* xr = &x[t * 9];
        uint4 u0;
        u0.x = h22u(__floats2half2_rn(xr[0], xr[1]));
        u0.y = h22u(__floats2half2_rn(xr[2], xr[3]));
        u0.z = h22u(__floats2half2_rn(xr[4], xr[5]));
        u0.w = h22u(__floats2half2_rn(xr[6], xr[7]));
        uint4 u1;
        u1.x = h22u(__floats2half2_rn(xr[8], 0.f));
        u1.y = 0; u1.z = 0; u1.w = 0;
        uint4* p = reinterpret_cast<uint4*>(&g_xh[t * 8]);
        p[0] = u0; p[1] = u1;
    }
    int e = t * 4;
    if (e < N_EDGES) {
        int4 d = __ldg(reinterpret_cast<const int4*>(&ei[N_EDGES + e]));
        atomicAdd(&g_deg[d.x], 1);
        atomicAdd(&g_deg[d.y], 1);
        atomicAdd(&g_deg[d.z], 1);
        atomicAdd(&g_deg[d.w], 1);
    }
}

// ---------------------------------------------------------------------------
// Parallel scan, phase A: per-block local exclusive scan (coalesced) of g_deg.
__global__ void scanA_kernel() {
    __shared__ int sh[SCAN_B];
    int tid = threadIdx.x;
    int i = blockIdx.x * SCAN_B + tid;
    int v = (i < N_NODES) ? g_deg[i] : 0;
    sh[tid] = v;
    __syncthreads();
#pragma unroll
    for (int off = 1; off < SCAN_B; off <<= 1) {
        int t = (tid >= off) ? sh[tid - off] : 0;
        __syncthreads();
        sh[tid] += t;
        __syncthreads();
    }
    if (i < N_NODES) g_off[i] = sh[tid] - v;   // local exclusive
    if (tid == SCAN_B - 1) g_bsum[blockIdx.x] = sh[tid];
}

// Phase B: one block scans the block sums (exclusive); writes g_off[N].
__global__ void scanB_kernel() {
    __shared__ int sh[512];
    int tid = threadIdx.x;
    int v = (tid < N_SCAN_BLOCKS) ? g_bsum[tid] : 0;
    sh[tid] = v;
    __syncthreads();
#pragma unroll
    for (int off = 1; off < 512; off <<= 1) {
        int t = (tid >= off) ? sh[tid - off] : 0;
        __syncthreads();
        sh[tid] += t;
        __syncthreads();
    }
    if (tid < N_SCAN_BLOCKS) g_bsum[tid] = sh[tid] - v;  // exclusive
    if (tid == N_SCAN_BLOCKS - 1) g_off[N_NODES] = sh[tid];
}

// Phase C: add block offsets; materialize g_cur; re-zero g_deg; zero the
// stride-12 agg region that scatter_red accumulates into.
__global__ void scanC_kernel() {
    int i = blockIdx.x * blockDim.x + threadIdx.x;
    if (i >= N_NODES) return;
    int o = g_off[i] + g_bsum[i >> 8];
    g_off[i] = o;
    g_cur[i] = o;
    g_deg[i] = 0;
    float4 z = make_float4(0.f, 0.f, 0.f, 0.f);
    float4* p = reinterpret_cast<float4*>(&g_agg[i * 12]);
    p[0] = z; p[1] = z; p[2] = z;
}

// ---------------------------------------------------------------------------
// Fused scatter + pass-1 aggregation. Per edge: bucket (s,a) into csr AND
// reduce the relu'd pass-1 message (half2 math, fp32 sums) into g_agg.
__global__ void scatter_red_kernel(const int* __restrict__ ei,
                                   const float* __restrict__ eattr,
                                   const float* __restrict__ We1,
                                   const float* __restrict__ be1) {
    int t = blockIdx.x * blockDim.x + threadIdx.x;
    int e = t * 4;
    if (e >= N_EDGES) return;

    __half2 w01 = __floats2half2_rn(__ldg(&We1[0]), __ldg(&We1[1]));
    __half2 w23 = __floats2half2_rn(__ldg(&We1[2]), __ldg(&We1[3]));
    __half2 w45 = __floats2half2_rn(__ldg(&We1[4]), __ldg(&We1[5]));
    __half2 w67 = __floats2half2_rn(__ldg(&We1[6]), __ldg(&We1[7]));
    __half2 w8p = __floats2half2_rn(__ldg(&We1[8]), 0.f);
    __half2 b01 = __floats2half2_rn(__ldg(&be1[0]), __ldg(&be1[1]));
    __half2 b23 = __floats2half2_rn(__ldg(&be1[2]), __ldg(&be1[3]));
    __half2 b45 = __floats2half2_rn(__ldg(&be1[4]), __ldg(&be1[5]));
    __half2 b67 = __floats2half2_rn(__ldg(&be1[6]), __ldg(&be1[7]));
    __half2 b8p = __floats2half2_rn(__ldg(&be1[8]), 0.f);
    const __half2 z2 = __float2half2_rn(0.f);

    int4   s = __ldg(reinterpret_cast<const int4*>(&ei[e]));
    int4   d = __ldg(reinterpret_cast<const int4*>(&ei[N_EDGES + e]));
    float4 a = __ldg(reinterpret_cast<const float4*>(&eattr[e]));

    int ss[4] = {s.x, s.y, s.z, s.w};
    int dd[4] = {d.x, d.y, d.z, d.w};
    float aa[4] = {a.x, a.y, a.z, a.w};

#pragma unroll
    for (int k = 0; k < 4; k++) {
        g_csr[atomicAdd(&g_cur[dd[k]], 1)] = make_int2(ss[k], __float_as_int(aa[k]));
        const uint4* xr = reinterpret_cast<const uint4*>(&g_xh[ss[k] * 8]);
        uint4 r0 = __ldg(xr);
        unsigned int r1 = __ldg(reinterpret_cast<const unsigned int*>(xr + 1));
        __half2 a2 = __float2half2_rn(aa[k]);
        __half2 m01 = __hmax2(__hadd2(u2h2(r0.x), __hfma2(a2, w01, b01)), z2);
        __half2 m23 = __hmax2(__hadd2(u2h2(r0.y), __hfma2(a2, w23, b23)), z2);
        __half2 m45 = __hmax2(__hadd2(u2h2(r0.z), __hfma2(a2, w45, b45)), z2);
        __half2 m67 = __hmax2(__hadd2(u2h2(r0.w), __hfma2(a2, w67, b67)), z2);
        __half2 m8p = __hmax2(__hadd2(u2h2(r1),   __hfma2(a2, w8p, b8p)), z2);
        float2 f01 = __half22float2(m01);
        float2 f23 = __half22float2(m23);
        float2 f45 = __half22float2(m45);
        float2 f67 = __half22float2(m67);
        float2 f8p = __half22float2(m8p);
        float* base = &g_agg[dd[k] * 12];
        red_add_v4(base + 0, f01.x, f01.y, f23.x, f23.y);
        red_add_v4(base + 4, f45.x, f45.y, f67.x, f67.y);
        red_add_f32(base + 8, f8p.x);
    }
}

// ---------------------------------------------------------------------------
// Node MLP 1: z = x + agg; h1 = relu(relu(z@W1a+b1a)@W1b+b1b), stored fp16.
__global__ void mlp1_kernel(const float* __restrict__ x,
                            const float* __restrict__ W1a, const float* __restrict__ b1a,
                            const float* __restrict__ W1b, const float* __restrict__ b1b) {
    __shared__ __align__(16) float sWa[F_IN * H_DIM];
    __shared__ __align__(16) float sWb[H_DIM * H_DIM];
    __shared__ __align__(16) float sba[H_DIM];
    __shared__ __align__(16) float sbb[H_DIM];
    int tid = threadIdx.x;
    for (int i = tid; i < F_IN * H_DIM; i += blockDim.x) sWa[i] = W1a[i];
    for (int i = tid; i < H_DIM * H_DIM; i += blockDim.x) sWb[i] = W1b[i];
    if (tid < H_DIM) { sba[tid] = b1a[tid]; sbb[tid] = b1b[tid]; }
    __syncthreads();

    int n = blockIdx.x * blockDim.x + tid;
    if (n >= N_NODES) return;

    float z[F_IN];
#pragma unroll
    for (int f = 0; f < F_IN; f++) z[f] = x[n * 9 + f] + g_agg[n * 12 + f];

    float t[H_DIM];
#pragma unroll
    for (int j = 0; j < H_DIM; j += 4) {
        float4 acc = *reinterpret_cast<float4*>(&sba[j]);
#pragma unroll
        for (int f = 0; f < F_IN; f++) {
            float4 w = *reinterpret_cast<float4*>(&sWa[f * H_DIM + j]);
            acc.x = fmaf(z[f], w.x, acc.x);
            acc.y = fmaf(z[f], w.y, acc.y);
            acc.z = fmaf(z[f], w.z, acc.z);
            acc.w = fmaf(z[f], w.w, acc.w);
        }
        t[j + 0] = fmaxf(acc.x, 0.f);
        t[j + 1] = fmaxf(acc.y, 0.f);
        t[j + 2] = fmaxf(acc.z, 0.f);
        t[j + 3] = fmaxf(acc.w, 0.f);
    }

    __half2 hrow[32];
#pragma unroll
    for (int j = 0; j < H_DIM; j += 4) {
        float4 acc = *reinterpret_cast<float4*>(&sbb[j]);
#pragma unroll
        for (int k = 0; k < H_DIM; k++) {
            float4 w = *reinterpret_cast<float4*>(&sWb[k * H_DIM + j]);
            acc.x = fmaf(t[k], w.x, acc.x);
            acc.y = fmaf(t[k], w.y, acc.y);
            acc.z = fmaf(t[k], w.z, acc.z);
            acc.w = fmaf(t[k], w.w, acc.w);
        }
        hrow[j / 2 + 0] = __floats2half2_rn(fmaxf(acc.x, 0.f), fmaxf(acc.y, 0.f));
        hrow[j / 2 + 1] = __floats2half2_rn(fmaxf(acc.z, 0.f), fmaxf(acc.w, 0.f));
    }
    uint4* dst = reinterpret_cast<uint4*>(&g_h1h[n * 32]);
    const uint4* src = reinterpret_cast<const uint4*>(hrow);
#pragma unroll
    for (int q = 0; q < 8; q++) dst[q] = src[q];
}

// ---------------------------------------------------------------------------
// Edge pass 2 (gather): warp per dst node, lane owns 2 features (one half2).
// half2 message math, fp32 accumulation; 8 edges in flight.
__global__ void edge2_gather(const float* __restrict__ We2,
                             const float* __restrict__ be2) {
    int gt = blockIdx.x * blockDim.x + threadIdx.x;
    int n = gt >> 5;
    int lane = gt & 31;
    if (n >= N_NODES) return;
    int c = lane * 2;

    __half2 w2 = __floats2half2_rn(__ldg(&We2[c]), __ldg(&We2[c + 1]));
    __half2 b2 = __floats2half2_rn(__ldg(&be2[c]), __ldg(&be2[c + 1]));
    const __half2 z2 = __float2half2_rn(0.f);
    int beg = __ldg(&g_off[n]);
    int end = __ldg(&g_off[n + 1]);

    float2 acc = make_float2(0.f, 0.f);
    int j = beg;
    if ((j & 1) && j < end) {  // peel to make j even (int4 csr alignment)
        int2 sa = __ldg(&g_csr[j]);
        __half2 a2 = __float2half2_rn(__int_as_float(sa.y));
        __half2 h2 = __ldg(&g_h1h[sa.x * 32 + lane]);
        float2 f = __half22float2(__hmax2(__hadd2(h2, __hfma2(a2, w2, b2)), z2));
        acc.x += f.x; acc.y += f.y;
        j++;
    }
    for (; j + 8 <= end; j += 8) {
        int4 p0 = __ldg(reinterpret_cast<const int4*>(&g_csr[j + 0]));
        int4 p1 = __ldg(reinterpret_cast<const int4*>(&g_csr[j + 2]));
        int4 p2 = __ldg(reinterpret_cast<const int4*>(&g_csr[j + 4]));
        int4 p3 = __ldg(reinterpret_cast<const int4*>(&g_csr[j + 6]));
        __half2 h0 = __ldg(&g_h1h[p0.x * 32 + lane]);
        __half2 h1 = __ldg(&g_h1h[p0.z * 32 + lane]);
        __half2 h2 = __ldg(&g_h1h[p1.x * 32 + lane]);
        __half2 h3 = __ldg(&g_h1h[p1.z * 32 + lane]);
        __half2 h4 = __ldg(&g_h1h[p2.x * 32 + lane]);
        __half2 h5 = __ldg(&g_h1h[p2.z * 32 + lane]);
        __half2 h6 = __ldg(&g_h1h[p3.x * 32 + lane]);
        __half2 h7 = __ldg(&g_h1h[p3.z * 32 + lane]);
        float2 f0 = __half22float2(__hmax2(__hadd2(h0, __hfma2(__float2half2_rn(__int_as_float(p0.y)), w2, b2)), z2));
        float2 f1 = __half22float2(__hmax2(__hadd2(h1, __hfma2(__float2half2_rn(__int_as_float(p0.w)), w2, b2)), z2));
        float2 f2 = __half22float2(__hmax2(__hadd2(h2, __hfma2(__float2half2_rn(__int_as_float(p1.y)), w2, b2)), z2));
        float2 f3 = __half22float2(__hmax2(__hadd2(h3, __hfma2(__float2half2_rn(__int_as_float(p1.w)), w2, b2)), z2));
        float2 f4 = __half22float2(__hmax2(__hadd2(h4, __hfma2(__float2half2_rn(__int_as_float(p2.y)), w2, b2)), z2));
        float2 f5 = __half22float2(__hmax2(__hadd2(h5, __hfma2(__float2half2_rn(__int_as_float(p2.w)), w2, b2)), z2));
        float2 f6 = __half22float2(__hmax2(__hadd2(h6, __hfma2(__float2half2_rn(__int_as_float(p3.y)), w2, b2)), z2));
        float2 f7 = __half22float2(__hmax2(__hadd2(h7, __hfma2(__float2half2_rn(__int_as_float(p3.w)), w2, b2)), z2));
        acc.x += f0.x + f1.x + f2.x + f3.x;
        acc.y += f0.y + f1.y + f2.y + f3.y;
        acc.x += f4.x + f5.x + f6.x + f7.x;
        acc.y += f4.y + f5.y + f6.y + f7.y;
    }
    for (; j < end; j++) {
        int2 sa = __ldg(&g_csr[j]);
        __half2 a2 = __float2half2_rn(__int_as_float(sa.y));
        __half2 h2 = __ldg(&g_h1h[sa.x * 32 + lane]);
        float2 f = __half22float2(__hmax2(__hadd2(h2, __hfma2(a2, w2, b2)), z2));
        acc.x += f.x; acc.y += f.y;
    }
    *reinterpret_cast<float2*>(&g_agg[n * H_DIM + c]) = acc;
}

// ---------------------------------------------------------------------------
// Node MLP 2 + readout head + group segment-sum of expenses.
__global__ void mlp2_kernel(const float* __restrict__ W2a, const float* __restrict__ b2a,
                            const float* __restrict__ W2b, const float* __restrict__ b2b,
                            const float* __restrict__ Wr1, const float* __restrict__ br1,
                            const float* __restrict__ Wr2, const float* __restrict__ br2,
                            const int* __restrict__ batch,
                            const int* __restrict__ term,
                            const float* __restrict__ c_cost) {
    __shared__ __align__(16) float sWa[H_DIM * H_DIM];
    __shared__ __align__(16) float sWb[H_DIM * H_DIM];
    __shared__ __align__(16) float sWr1[H_DIM * 32];
    __shared__ __align__(16) float sba[H_DIM];
    __shared__ __align__(16) float sbb[H_DIM];
    __shared__ __align__(16) float sbr1[32];
    __shared__ __align__(16) float sWr2[32];
    __shared__ float sbr2;
    int tid = threadIdx.x;
    for (int i = tid; i < H_DIM * H_DIM; i += blockDim.x) { sWa[i] = W2a[i]; sWb[i] = W2b[i]; }
    for (int i = tid; i < H_DIM * 32; i += blockDim.x) sWr1[i] = Wr1[i];
    if (tid < H_DIM) { sba[tid] = b2a[tid]; sbb[tid] = b2b[tid]; }
    if (tid < 32) { sbr1[tid] = br1[tid]; sWr2[tid] = Wr2[tid]; }
    if (tid == 0) sbr2 = br2[0];
    __syncthreads();

    int n = blockIdx.x * blockDim.x + tid;
    if (n >= N_NODES) return;

    uint4 hraw[8];
    const uint4* hsrc = reinterpret_cast<const uint4*>(&g_h1h[n * 32]);
#pragma unroll
    for (int q = 0; q < 8; q++) hraw[q] = hsrc[q];
    const __half2* hp = reinterpret_cast<const __half2*>(hraw);

    float z[H_DIM];
#pragma unroll
    for (int k = 0; k < H_DIM; k += 4) {
        float2 a01 = __half22float2(hp[k / 2 + 0]);
        float2 a23 = __half22float2(hp[k / 2 + 1]);
        float4 av = *reinterpret_cast<const float4*>(&g_agg[n * H_DIM + k]);
        z[k + 0] = a01.x + av.x;
        z[k + 1] = a01.y + av.y;
        z[k + 2] = a23.x + av.z;
        z[k + 3] = a23.y + av.w;
    }

    float t[H_DIM];
    for (int j = 0; j < H_DIM; j += 4) {
        float4 acc = *reinterpret_cast<float4*>(&sba[j]);
#pragma unroll
        for (int k = 0; k < H_DIM; k++) {
            float4 w = *reinterpret_cast<float4*>(&sWa[k * H_DIM + j]);
            acc.x = fmaf(z[k], w.x, acc.x);
            acc.y = fmaf(z[k], w.y, acc.y);
            acc.z = fmaf(z[k], w.z, acc.z);
            acc.w = fmaf(z[k], w.w, acc.w);
        }
        t[j + 0] = fmaxf(acc.x, 0.f);
        t[j + 1] = fmaxf(acc.y, 0.f);
        t[j + 2] = fmaxf(acc.z, 0.f);
        t[j + 3] = fmaxf(acc.w, 0.f);
    }

    for (int j = 0; j < H_DIM; j += 4) {
        float4 acc = *reinterpret_cast<float4*>(&sbb[j]);
#pragma unroll
        for (int k = 0; k < H_DIM; k++) {
            float4 w = *reinterpret_cast<float4*>(&sWb[k * H_DIM + j]);
            acc.x = fmaf(t[k], w.x, acc.x);
            acc.y = fmaf(t[k], w.y, acc.y);
            acc.z = fmaf(t[k], w.z, acc.z);
            acc.w = fmaf(t[k], w.w, acc.w);
        }
        z[j + 0] = fmaxf(acc.x, 0.f);
        z[j + 1] = fmaxf(acc.y, 0.f);
        z[j + 2] = fmaxf(acc.z, 0.f);
        z[j + 3] = fmaxf(acc.w, 0.f);
    }

    float r[32];
    for (int j = 0; j < 32; j += 4) {
        float4 acc = *reinterpret_cast<float4*>(&sbr1[j]);
#pragma unroll
        for (int k = 0; k < H_DIM; k++) {
            float4 w = *reinterpret_cast<float4*>(&sWr1[k * 32 + j]);
            acc.x = fmaf(z[k], w.x, acc.x);
            acc.y = fmaf(z[k], w.y, acc.y);
            acc.z = fmaf(z[k], w.z, acc.z);
            acc.w = fmaf(z[k], w.w, acc.w);
        }
        r[j + 0] = fmaxf(acc.x, 0.f);
        r[j + 1] = fmaxf(acc.y, 0.f);
        r[j + 2] = fmaxf(acc.z, 0.f);
        r[j + 3] = fmaxf(acc.w, 0.f);
    }
    float p = sbr2;
#pragma unroll
    for (int k = 0; k < 32; k++) p = fmaf(r[k], sWr2[k], p);

    float pi = 1.f / (1.f + expf(-p));
    if (term[n] != 0) pi = 0.f;
    g_pi[n] = pi;
    atomicAdd(&g_texp[batch[n]], pi * c_cost[n]);
}

// ---------------------------------------------------------------------------
__global__ void final_kernel(const int* __restrict__ batch,
                             const float* __restrict__ B_total,
                             float* __restrict__ out) {
    int n = blockIdx.x * blockDim.x + threadIdx.x;
    if (n >= N_NODES) return;
    int b = batch[n];
    float ratio = fminf(B_total[b] / (g_texp[b] + 1e-12f), 1.f);
    out[n] = g_pi[n] * ratio;
}

// ---------------------------------------------------------------------------
extern "C" void kernel_launch(void* const* d_in, const int* in_sizes, int n_in,
                              void* d_out, int out_size) {
    const float* x       = (const float*)d_in[0];
    const int*   ei      = (const int*)d_in[1];
    const float* eattr   = (const float*)d_in[2];
    const int*   batch   = (const int*)d_in[3];
    const float* B_total = (const float*)d_in[4];
    const int*   term    = (const int*)d_in[5];
    const float* c_cost  = (const float*)d_in[6];
    const float* We1 = (const float*)d_in[7];
    const float* be1 = (const float*)d_in[8];
    const float* W1a = (const float*)d_in[9];
    const float* b1a = (const float*)d_in[10];
    const float* W1b = (const float*)d_in[11];
    const float* b1b = (const float*)d_in[12];
    const float* We2 = (const float*)d_in[13];
    const float* be2 = (const float*)d_in[14];
    const float* W2a = (const float*)d_in[15];
    const float* b2a = (const float*)d_in[16];
    const float* W2b = (const float*)d_in[17];
    const float* b2b = (const float*)d_in[18];
    const float* Wr1 = (const float*)d_in[19];
    const float* br1 = (const float*)d_in[20];
    const float* Wr2 = (const float*)d_in[21];
    const float* br2 = (const float*)d_in[22];
    float* out = (float*)d_out;

    const int NB_NODE = (N_NODES + 255) / 256;
    const int NB_EDGE4 = (N_EDGES / 4 + 255) / 256;

    prep_hist_kernel<<<NB_EDGE4, 256>>>(x, ei);
    scanA_kernel<<<N_SCAN_BLOCKS, SCAN_B>>>();
    scanB_kernel<<<1, 512>>>();
    scanC_kernel<<<NB_NODE, 256>>>();
    scatter_red_kernel<<<NB_EDGE4, 256>>>(ei, eattr, We1, be1);
    mlp1_kernel<<<NB_NODE, 256>>>(x, W1a, b1a, W1b, b1b);
    edge2_gather<<<(N_NODES * 32 + 255) / 256, 256>>>(We2, be2);
    mlp2_kernel<<<NB_NODE, 256>>>(W2a, b2a, W2b, b2b, Wr1, br1, Wr2, br2,
                                  batch, term, c_cost);
    final_kernel<<<NB_NODE, 256>>>(batch, B_total, out);
}

// round 11
// speedup vs baseline: 1.5692x; 1.0565x over previous
#include <cuda_runtime.h>
#include <cuda_fp16.h>

#define N_NODES 100000
#define N_EDGES 3200000
#define G_GROUPS 128
#define F_IN 9
#define H_DIM 64
#define SCAN_B 256
#define N_SCAN_BLOCKS ((N_NODES + SCAN_B - 1) / SCAN_B)   // 391

typedef unsigned long long ull;

// Scratch (__device__ globals; no allocation allowed).
// g_deg relies on zero-init at module load; scanC re-zeroes it after use so
// every launch (and every graph replay) starts with g_deg == 0.
__device__ __align__(16) __half2 g_h1h[N_NODES * 32];   // hidden after conv1 (fp16x2, 128B rows)
__device__ __align__(16) __half2 g_xh[N_NODES * 8];     // x padded fp16 rows (32B, 1 line each)
__device__ __align__(16) float g_agg[N_NODES * H_DIM];  // aggregation (pass1 uses stride-12)
__device__ int   g_deg[N_NODES];
__device__ int   g_off[N_NODES + 1];
__device__ int   g_cur[N_NODES];
__device__ int   g_bsum[N_SCAN_BLOCKS];
__device__ __align__(16) int2 g_csr[N_EDGES];           // (src, attr bits), bucketed by dst
__device__ __align__(16) float g_pi[N_NODES];
__device__ __align__(16) float g_texp[G_GROUPS];

__device__ __forceinline__ void red_add_v4(float* addr, float a, float b, float c, float d) {
    asm volatile("red.global.add.v4.f32 [%0], {%1,%2,%3,%4};"
                 :: "l"(addr), "f"(a), "f"(b), "f"(c), "f"(d) : "memory");
}
__device__ __forceinline__ void red_add_f32(float* addr, float a) {
    asm volatile("red.global.add.f32 [%0], %1;" :: "l"(addr), "f"(a) : "memory");
}
__device__ __forceinline__ __half2 u2h2(unsigned int u) {
    __half2 h; *reinterpret_cast<unsigned int*>(&h) = u; return h;
}
__device__ __forceinline__ unsigned int h22u(__half2 h) {
    return *reinterpret_cast<unsigned int*>(&h);
}
// packed fp32x2 FMA (sm_100+): two IEEE fp32 FMAs per instruction.
__device__ __forceinline__ ull ffma2(ull a, ull b, ull c) {
    ull d;
    asm("fma.rn.f32x2 %0, %1, %2, %3;" : "=l"(d) : "l"(a), "l"(b), "l"(c));
    return d;
}
__device__ __forceinline__ ull pack2(float x, float y) {
    ull r; asm("mov.b64 %0, {%1, %2};" : "=l"(r) : "f"(x), "f"(y)); return r;
}
__device__ __forceinline__ float2 unpack2(ull r) {
    float2 f; asm("mov.b64 {%0, %1}, %2;" : "=f"(f.x), "=f"(f.y) : "l"(r)); return f;
}

// 16-output FFMA2 block: acc[8] (f32x2) += z[k] * W[k][jb..jb+15], k = 0..kdim-1
// W row-major [kdim x 64], 16B-aligned.
__device__ __forceinline__ void gemv16_f32x2(ull acc[8], const float* __restrict__ sW,
                                             const float* __restrict__ z, int jb, int kdim) {
#pragma unroll 8
    for (int k = 0; k < kdim; k++) {
        ull zz = pack2(z[k], z[k]);
        const ulonglong2* wp = reinterpret_cast<const ulonglong2*>(&sW[k * H_DIM + jb]);
        ulonglong2 w0 = wp[0], w1 = wp[1];
        acc[0] = ffma2(zz, w0.x, acc[0]);
        acc[1] = ffma2(zz, w0.y, acc[1]);
        acc[2] = ffma2(zz, w1.x, acc[2]);
        acc[3] = ffma2(zz, w1.y, acc[3]);
        const ulonglong2* wq = wp + 2;
        ulonglong2 w2 = wq[0], w3 = wq[1];
        acc[4] = ffma2(zz, w2.x, acc[4]);
        acc[5] = ffma2(zz, w2.y, acc[5]);
        acc[6] = ffma2(zz, w3.x, acc[6]);
        acc[7] = ffma2(zz, w3.y, acc[7]);
    }
}
__device__ __forceinline__ void load_bias16(ull acc[8], const float* __restrict__ sb, int jb) {
    const ulonglong2* bp = reinterpret_cast<const ulonglong2*>(&sb[jb]);
    ulonglong2 b0 = bp[0], b1 = bp[1], b2 = bp[2], b3 = bp[3];
    acc[0] = b0.x; acc[1] = b0.y; acc[2] = b1.x; acc[3] = b1.y;
    acc[4] = b2.x; acc[5] = b2.y; acc[6] = b3.x; acc[7] = b3.y;
}

// ---------------------------------------------------------------------------
// Fused prep + histogram. prep: zero texp, pack x into fp16 32B rows.
// hist: dst-degree histogram, 4 edges/thread via int4.
__global__ void prep_hist_kernel(const float* __restrict__ x,
                                 const int* __restrict__ ei) {
    int t = blockIdx.x * blockDim.x + threadIdx.x;
    if (t < G_GROUPS) g_texp[t] = 0.f;
    if (t < N_NODES) {
        const float* xr = &x[t * 9];
        uint4 u0;
        u0.x = h22u(__floats2half2_rn(xr[0], xr[1]));
        u0.y = h22u(__floats2half2_rn(xr[2], xr[3]));
        u0.z = h22u(__floats2half2_rn(xr[4], xr[5]));
        u0.w = h22u(__floats2half2_rn(xr[6], xr[7]));
        uint4 u1;
        u1.x = h22u(__floats2half2_rn(xr[8], 0.f));
        u1.y = 0; u1.z = 0; u1.w = 0;
        uint4* p = reinterpret_cast<uint4*>(&g_xh[t * 8]);
        p[0] = u0; p[1] = u1;
    }
    int e = t * 4;
    if (e < N_EDGES) {
        int4 d = __ldg(reinterpret_cast<const int4*>(&ei[N_EDGES + e]));
        atomicAdd(&g_deg[d.x], 1);
        atomicAdd(&g_deg[d.y], 1);
        atomicAdd(&g_deg[d.z], 1);
        atomicAdd(&g_deg[d.w], 1);
    }
}

// ---------------------------------------------------------------------------
// Parallel scan, phase A: per-block local exclusive scan (coalesced) of g_deg.
__global__ void scanA_kernel() {
    __shared__ int sh[SCAN_B];
    int tid = threadIdx.x;
    int i = blockIdx.x * SCAN_B + tid;
    int v = (i < N_NODES) ? g_deg[i] : 0;
    sh[tid] = v;
    __syncthreads();
#pragma unroll
    for (int off = 1; off < SCAN_B; off <<= 1) {
        int t = (tid >= off) ? sh[tid - off] : 0;
        __syncthreads();
        sh[tid] += t;
        __syncthreads();
    }
    if (i < N_NODES) g_off[i] = sh[tid] - v;   // local exclusive
    if (tid == SCAN_B - 1) g_bsum[blockIdx.x] = sh[tid];
}

// Phase B: one block scans the block sums (exclusive); writes g_off[N].
__global__ void scanB_kernel() {
    __shared__ int sh[512];
    int tid = threadIdx.x;
    int v = (tid < N_SCAN_BLOCKS) ? g_bsum[tid] : 0;
    sh[tid] = v;
    __syncthreads();
#pragma unroll
    for (int off = 1; off < 512; off <<= 1) {
        int t = (tid >= off) ? sh[tid - off] : 0;
        __syncthreads();
        sh[tid] += t;
        __syncthreads();
    }
    if (tid < N_SCAN_BLOCKS) g_bsum[tid] = sh[tid] - v;  // exclusive
    if (tid == N_SCAN_BLOCKS - 1) g_off[N_NODES] = sh[tid];
}

// Phase C: add block offsets; materialize g_cur; re-zero g_deg; zero the
// stride-12 agg region that scatter_red accumulates into.
__global__ void scanC_kernel() {
    int i = blockIdx.x * blockDim.x + threadIdx.x;
    if (i >= N_NODES) return;
    int o = g_off[i] + g_bsum[i >> 8];
    g_off[i] = o;
    g_cur[i] = o;
    g_deg[i] = 0;
    float4 z = make_float4(0.f, 0.f, 0.f, 0.f);
    float4* p = reinterpret_cast<float4*>(&g_agg[i * 12]);
    p[0] = z; p[1] = z; p[2] = z;
}

// ---------------------------------------------------------------------------
// Fused scatter + pass-1 aggregation. Per edge: bucket (s,a) into csr AND
// reduce the relu'd pass-1 message (half2 math, fp32 sums) into g_agg.
__global__ void scatter_red_kernel(const int* __restrict__ ei,
                                   const float* __restrict__ eattr,
                                   const float* __restrict__ We1,
                                   const float* __restrict__ be1) {
    int t = blockIdx.x * blockDim.x + threadIdx.x;
    int e = t * 4;
    if (e >= N_EDGES) return;

    __half2 w01 = __floats2half2_rn(__ldg(&We1[0]), __ldg(&We1[1]));
    __half2 w23 = __floats2half2_rn(__ldg(&We1[2]), __ldg(&We1[3]));
    __half2 w45 = __floats2half2_rn(__ldg(&We1[4]), __ldg(&We1[5]));
    __half2 w67 = __floats2half2_rn(__ldg(&We1[6]), __ldg(&We1[7]));
    __half2 w8p = __floats2half2_rn(__ldg(&We1[8]), 0.f);
    __half2 b01 = __floats2half2_rn(__ldg(&be1[0]), __ldg(&be1[1]));
    __half2 b23 = __floats2half2_rn(__ldg(&be1[2]), __ldg(&be1[3]));
    __half2 b45 = __floats2half2_rn(__ldg(&be1[4]), __ldg(&be1[5]));
    __half2 b67 = __floats2half2_rn(__ldg(&be1[6]), __ldg(&be1[7]));
    __half2 b8p = __floats2half2_rn(__ldg(&be1[8]), 0.f);
    const __half2 z2 = __float2half2_rn(0.f);

    int4   s = __ldg(reinterpret_cast<const int4*>(&ei[e]));
    int4   d = __ldg(reinterpret_cast<const int4*>(&ei[N_EDGES + e]));
    float4 a = __ldg(reinterpret_cast<const float4*>(&eattr[e]));

    int ss[4] = {s.x, s.y, s.z, s.w};
    int dd[4] = {d.x, d.y, d.z, d.w};
    float aa[4] = {a.x, a.y, a.z, a.w};

#pragma unroll
    for (int k = 0; k < 4; k++) {
        g_csr[atomicAdd(&g_cur[dd[k]], 1)] = make_int2(ss[k], __float_as_int(aa[k]));
        const uint4* xr = reinterpret_cast<const uint4*>(&g_xh[ss[k] * 8]);
        uint4 r0 = __ldg(xr);
        unsigned int r1 = __ldg(reinterpret_cast<const unsigned int*>(xr + 1));
        __half2 a2 = __float2half2_rn(aa[k]);
        __half2 m01 = __hmax2(__hadd2(u2h2(r0.x), __hfma2(a2, w01, b01)), z2);
        __half2 m23 = __hmax2(__hadd2(u2h2(r0.y), __hfma2(a2, w23, b23)), z2);
        __half2 m45 = __hmax2(__hadd2(u2h2(r0.z), __hfma2(a2, w45, b45)), z2);
        __half2 m67 = __hmax2(__hadd2(u2h2(r0.w), __hfma2(a2, w67, b67)), z2);
        __half2 m8p = __hmax2(__hadd2(u2h2(r1),   __hfma2(a2, w8p, b8p)), z2);
        float2 f01 = __half22float2(m01);
        float2 f23 = __half22float2(m23);
        float2 f45 = __half22float2(m45);
        float2 f67 = __half22float2(m67);
        float2 f8p = __half22float2(m8p);
        float* base = &g_agg[dd[k] * 12];
        red_add_v4(base + 0, f01.x, f01.y, f23.x, f23.y);
        red_add_v4(base + 4, f45.x, f45.y, f67.x, f67.y);
        red_add_f32(base + 8, f8p.x);
    }
}

// ---------------------------------------------------------------------------
// Node MLP 1: z = x + agg; h1 = relu(relu(z@W1a+b1a)@W1b+b1b), stored fp16.
__global__ void mlp1_kernel(const float* __restrict__ x,
                            const float* __restrict__ W1a, const float* __restrict__ b1a,
                            const float* __restrict__ W1b, const float* __restrict__ b1b) {
    __shared__ __align__(16) float sWa[F_IN * H_DIM];
    __shared__ __align__(16) float sWb[H_DIM * H_DIM];
    __shared__ __align__(16) float sba[H_DIM];
    __shared__ __align__(16) float sbb[H_DIM];
    int tid = threadIdx.x;
    for (int i = tid; i < F_IN * H_DIM; i += blockDim.x) sWa[i] = W1a[i];
    for (int i = tid; i < H_DIM * H_DIM; i += blockDim.x) sWb[i] = W1b[i];
    if (tid < H_DIM) { sba[tid] = b1a[tid]; sbb[tid] = b1b[tid]; }
    __syncthreads();

    int n = blockIdx.x * blockDim.x + tid;
    if (n >= N_NODES) return;

    float z[F_IN];
#pragma unroll
    for (int f = 0; f < F_IN; f++) z[f] = x[n * 9 + f] + g_agg[n * 12 + f];

    // layer A (9->64): f32x2 blocks of 16 outputs
    float t[H_DIM];
    for (int jb = 0; jb < H_DIM; jb += 16) {
        ull acc[8];
        load_bias16(acc, sba, jb);
        gemv16_f32x2(acc, sWa, z, jb, F_IN);
#pragma unroll
        for (int q = 0; q < 8; q++) {
            float2 f = unpack2(acc[q]);
            t[jb + q * 2 + 0] = fmaxf(f.x, 0.f);
            t[jb + q * 2 + 1] = fmaxf(f.y, 0.f);
        }
    }

    // layer B (64->64): f32x2, output packed fp16
    __half2 hrow[32];
    for (int jb = 0; jb < H_DIM; jb += 16) {
        ull acc[8];
        load_bias16(acc, sbb, jb);
        gemv16_f32x2(acc, sWb, t, jb, H_DIM);
#pragma unroll
        for (int q = 0; q < 8; q++) {
            float2 f = unpack2(acc[q]);
            hrow[(jb >> 1) + q] = __floats2half2_rn(fmaxf(f.x, 0.f), fmaxf(f.y, 0.f));
        }
    }
    uint4* dst = reinterpret_cast<uint4*>(&g_h1h[n * 32]);
    const uint4* src = reinterpret_cast<const uint4*>(hrow);
#pragma unroll
    for (int q = 0; q < 8; q++) dst[q] = src[q];
}

// ---------------------------------------------------------------------------
// Edge pass 2 (gather): warp per dst node, lane owns 2 features (one half2).
// half2 message math, fp32 accumulation; 8 edges in flight.
__global__ void edge2_gather(const float* __restrict__ We2,
                             const float* __restrict__ be2) {
    int gt = blockIdx.x * blockDim.x + threadIdx.x;
    int n = gt >> 5;
    int lane = gt & 31;
    if (n >= N_NODES) return;
    int c = lane * 2;

    __half2 w2 = __floats2half2_rn(__ldg(&We2[c]), __ldg(&We2[c + 1]));
    __half2 b2 = __floats2half2_rn(__ldg(&be2[c]), __ldg(&be2[c + 1]));
    const __half2 z2 = __float2half2_rn(0.f);
    int beg = __ldg(&g_off[n]);
    int end = __ldg(&g_off[n + 1]);

    float2 acc = make_float2(0.f, 0.f);
    int j = beg;
    if ((j & 1) && j < end) {  // peel to make j even (int4 csr alignment)
        int2 sa = __ldg(&g_csr[j]);
        __half2 a2 = __float2half2_rn(__int_as_float(sa.y));
        __half2 h2 = __ldg(&g_h1h[sa.x * 32 + lane]);
        float2 f = __half22float2(__hmax2(__hadd2(h2, __hfma2(a2, w2, b2)), z2));
        acc.x += f.x; acc.y += f.y;
        j++;
    }
    for (; j + 8 <= end; j += 8) {
        int4 p0 = __ldg(reinterpret_cast<const int4*>(&g_csr[j + 0]));
        int4 p1 = __ldg(reinterpret_cast<const int4*>(&g_csr[j + 2]));
        int4 p2 = __ldg(reinterpret_cast<const int4*>(&g_csr[j + 4]));
        int4 p3 = __ldg(reinterpret_cast<const int4*>(&g_csr[j + 6]));
        __half2 h0 = __ldg(&g_h1h[p0.x * 32 + lane]);
        __half2 h1 = __ldg(&g_h1h[p0.z * 32 + lane]);
        __half2 h2 = __ldg(&g_h1h[p1.x * 32 + lane]);
        __half2 h3 = __ldg(&g_h1h[p1.z * 32 + lane]);
        __half2 h4 = __ldg(&g_h1h[p2.x * 32 + lane]);
        __half2 h5 = __ldg(&g_h1h[p2.z * 32 + lane]);
        __half2 h6 = __ldg(&g_h1h[p3.x * 32 + lane]);
        __half2 h7 = __ldg(&g_h1h[p3.z * 32 + lane]);
        float2 f0 = __half22float2(__hmax2(__hadd2(h0, __hfma2(__float2half2_rn(__int_as_float(p0.y)), w2, b2)), z2));
        float2 f1 = __half22float2(__hmax2(__hadd2(h1, __hfma2(__float2half2_rn(__int_as_float(p0.w)), w2, b2)), z2));
        float2 f2 = __half22float2(__hmax2(__hadd2(h2, __hfma2(__float2half2_rn(__int_as_float(p1.y)), w2, b2)), z2));
        float2 f3 = __half22float2(__hmax2(__hadd2(h3, __hfma2(__float2half2_rn(__int_as_float(p1.w)), w2, b2)), z2));
        float2 f4 = __half22float2(__hmax2(__hadd2(h4, __hfma2(__float2half2_rn(__int_as_float(p2.y)), w2, b2)), z2));
        float2 f5 = __half22float2(__hmax2(__hadd2(h5, __hfma2(__float2half2_rn(__int_as_float(p2.w)), w2, b2)), z2));
        float2 f6 = __half22float2(__hmax2(__hadd2(h6, __hfma2(__float2half2_rn(__int_as_float(p3.y)), w2, b2)), z2));
        float2 f7 = __half22float2(__hmax2(__hadd2(h7, __hfma2(__float2half2_rn(__int_as_float(p3.w)), w2, b2)), z2));
        acc.x += f0.x + f1.x + f2.x + f3.x;
        acc.y += f0.y + f1.y + f2.y + f3.y;
        acc.x += f4.x + f5.x + f6.x + f7.x;
        acc.y += f4.y + f5.y + f6.y + f7.y;
    }
    for (; j < end; j++) {
        int2 sa = __ldg(&g_csr[j]);
        __half2 a2 = __float2half2_rn(__int_as_float(sa.y));
        __half2 h2 = __ldg(&g_h1h[sa.x * 32 + lane]);
        float2 f = __half22float2(__hmax2(__hadd2(h2, __hfma2(a2, w2, b2)), z2));
        acc.x += f.x; acc.y += f.y;
    }
    *reinterpret_cast<float2*>(&g_agg[n * H_DIM + c]) = acc;
}

// ---------------------------------------------------------------------------
// Node MLP 2 + readout head + group segment-sum of expenses.
__global__ void mlp2_kernel(const float* __restrict__ W2a, const float* __restrict__ b2a,
                            const float* __restrict__ W2b, const float* __restrict__ b2b,
                            const float* __restrict__ Wr1, const float* __restrict__ br1,
                            const float* __restrict__ Wr2, const float* __restrict__ br2,
                            const int* __restrict__ batch,
                            const int* __restrict__ term,
                            const float* __restrict__ c_cost) {
    __shared__ __align__(16) float sWa[H_DIM * H_DIM];
    __shared__ __align__(16) float sWb[H_DIM * H_DIM];
    __shared__ __align__(16) float sWr1[H_DIM * 32];
    __shared__ __align__(16) float sba[H_DIM];
    __shared__ __align__(16) float sbb[H_DIM];
    __shared__ __align__(16) float sbr1[32];
    __shared__ __align__(16) float sWr2[32];
    __shared__ float sbr2;
    int tid = threadIdx.x;
    for (int i = tid; i < H_DIM * H_DIM; i += blockDim.x) { sWa[i] = W2a[i]; sWb[i] = W2b[i]; }
    for (int i = tid; i < H_DIM * 32; i += blockDim.x) sWr1[i] = Wr1[i];
    if (tid < H_DIM) { sba[tid] = b2a[tid]; sbb[tid] = b2b[tid]; }
    if (tid < 32) { sbr1[tid] = br1[tid]; sWr2[tid] = Wr2[tid]; }
    if (tid == 0) sbr2 = br2[0];
    __syncthreads();

    int n = blockIdx.x * blockDim.x + tid;
    if (n >= N_NODES) return;

    uint4 hraw[8];
    const uint4* hsrc = reinterpret_cast<const uint4*>(&g_h1h[n * 32]);
#pragma unroll
    for (int q = 0; q < 8; q++) hraw[q] = hsrc[q];
    const __half2* hp = reinterpret_cast<const __half2*>(hraw);

    float z[H_DIM];
#pragma unroll
    for (int k = 0; k < H_DIM; k += 4) {
        float2 a01 = __half22float2(hp[k / 2 + 0]);
        float2 a23 = __half22float2(hp[k / 2 + 1]);
        float4 av = *reinterpret_cast<const float4*>(&g_agg[n * H_DIM + k]);
        z[k + 0] = a01.x + av.x;
        z[k + 1] = a01.y + av.y;
        z[k + 2] = a23.x + av.z;
        z[k + 3] = a23.y + av.w;
    }

    // layer A (64->64), f32x2
    float t[H_DIM];
    for (int jb = 0; jb < H_DIM; jb += 16) {
        ull acc[8];
        load_bias16(acc, sba, jb);
        gemv16_f32x2(acc, sWa, z, jb, H_DIM);
#pragma unroll
        for (int q = 0; q < 8; q++) {
            float2 f = unpack2(acc[q]);
            t[jb + q * 2 + 0] = fmaxf(f.x, 0.f);
            t[jb + q * 2 + 1] = fmaxf(f.y, 0.f);
        }
    }

    // layer B (64->64), f32x2, reuse z[] as h2
    for (int jb = 0; jb < H_DIM; jb += 16) {
        ull acc[8];
        load_bias16(acc, sbb, jb);
        gemv16_f32x2(acc, sWb, t, jb, H_DIM);
#pragma unroll
        for (int q = 0; q < 8; q++) {
            float2 f = unpack2(acc[q]);
            z[jb + q * 2 + 0] = fmaxf(f.x, 0.f);
            z[jb + q * 2 + 1] = fmaxf(f.y, 0.f);
        }
    }

    // readout (64->32), f32x2 over Wr1 [64 x 32]
    float r[32];
    for (int jb = 0; jb < 32; jb += 16) {
        ull acc[8];
        {
            const ulonglong2* bp = reinterpret_cast<const ulonglong2*>(&sbr1[jb]);
            ulonglong2 b0 = bp[0], b1 = bp[1], b2c = bp[2], b3 = bp[3];
            acc[0] = b0.x; acc[1] = b0.y; acc[2] = b1.x; acc[3] = b1.y;
            acc[4] = b2c.x; acc[5] = b2c.y; acc[6] = b3.x; acc[7] = b3.y;
        }
#pragma unroll 8
        for (int k = 0; k < H_DIM; k++) {
            ull zz = pack2(z[k], z[k]);
            const ulonglong2* wp = reinterpret_cast<const ulonglong2*>(&sWr1[k * 32 + jb]);
            ulonglong2 w0 = wp[0], w1 = wp[1];
            acc[0] = ffma2(zz, w0.x, acc[0]);
            acc[1] = ffma2(zz, w0.y, acc[1]);
            acc[2] = ffma2(zz, w1.x, acc[2]);
            acc[3] = ffma2(zz, w1.y, acc[3]);
            const ulonglong2* wq = wp + 2;
            ulonglong2 w2 = wq[0], w3 = wq[1];
            acc[4] = ffma2(zz, w2.x, acc[4]);
            acc[5] = ffma2(zz, w2.y, acc[5]);
            acc[6] = ffma2(zz, w3.x, acc[6]);
            acc[7] = ffma2(zz, w3.y, acc[7]);
        }
#pragma unroll
        for (int q = 0; q < 8; q++) {
            float2 f = unpack2(acc[q]);
            r[jb + q * 2 + 0] = fmaxf(f.x, 0.f);
            r[jb + q * 2 + 1] = fmaxf(f.y, 0.f);
        }
    }
    float p = sbr2;
#pragma unroll
    for (int k = 0; k < 32; k++) p = fmaf(r[k], sWr2[k], p);

    float pi = 1.f / (1.f + expf(-p));
    if (term[n] != 0) pi = 0.f;
    g_pi[n] = pi;
    atomicAdd(&g_texp[batch[n]], pi * c_cost[n]);
}

// ---------------------------------------------------------------------------
__global__ void final_kernel(const int* __restrict__ batch,
                             const float* __restrict__ B_total,
                             float* __restrict__ out) {
    int n = blockIdx.x * blockDim.x + threadIdx.x;
    if (n >= N_NODES) return;
    int b = batch[n];
    float ratio = fminf(B_total[b] / (g_texp[b] + 1e-12f), 1.f);
    out[n] = g_pi[n] * ratio;
}

// ---------------------------------------------------------------------------
extern "C" void kernel_launch(void* const* d_in, const int* in_sizes, int n_in,
                              void* d_out, int out_size) {
    const float* x       = (const float*)d_in[0];
    const int*   ei      = (const int*)d_in[1];
    const float* eattr   = (const float*)d_in[2];
    const int*   batch   = (const int*)d_in[3];
    const float* B_total = (const float*)d_in[4];
    const int*   term    = (const int*)d_in[5];
    const float* c_cost  = (const float*)d_in[6];
    const float* We1 = (const float*)d_in[7];
    const float* be1 = (const float*)d_in[8];
    const float* W1a = (const float*)d_in[9];
    const float* b1a = (const float*)d_in[10];
    const float* W1b = (const float*)d_in[11];
    const float* b1b = (const float*)d_in[12];
    const float* We2 = (const float*)d_in[13];
    const float* be2 = (const float*)d_in[14];
    const float* W2a = (const float*)d_in[15];
    const float* b2a = (const float*)d_in[16];
    const float* W2b = (const float*)d_in[17];
    const float* b2b = (const float*)d_in[18];
    const float* Wr1 = (const float*)d_in[19];
    const float* br1 = (const float*)d_in[20];
    const float* Wr2 = (const float*)d_in[21];
    const float* br2 = (const float*)d_in[22];
    float* out = (float*)d_out;

    const int NB_NODE = (N_NODES + 255) / 256;
    const int NB_EDGE4 = (N_EDGES / 4 + 255) / 256;

    prep_hist_kernel<<<NB_EDGE4, 256>>>(x, ei);
    scanA_kernel<<<N_SCAN_BLOCKS, SCAN_B>>>();
    scanB_kernel<<<1, 512>>>();
    scanC_kernel<<<NB_NODE, 256>>>();
    scatter_red_kernel<<<NB_EDGE4, 256>>>(ei, eattr, We1, be1);
    mlp1_kernel<<<NB_NODE, 256>>>(x, W1a, b1a, W1b, b1b);
    edge2_gather<<<(N_NODES * 32 + 255) / 256, 256>>>(We2, be2);
    mlp2_kernel<<<NB_NODE, 256>>>(W2a, b2a, W2b, b2b, Wr1, br1, Wr2, br2,
                                  batch, term, c_cost);
    final_kernel<<<NB_NODE, 256>>>(batch, B_total, out);
}

// round 12
// speedup vs baseline: 1.6283x; 1.0377x over previous
#include <cuda_runtime.h>
#include <cuda_fp16.h>

#define N_NODES 100000
#define N_EDGES 3200000
#define G_GROUPS 128
#define F_IN 9
#define H_DIM 64
#define SCAN_B 256
#define N_SCAN_BLOCKS ((N_NODES + SCAN_B - 1) / SCAN_B)   // 391

typedef unsigned long long ull;

// Scratch (__device__ globals; no allocation allowed).
// g_deg relies on zero-init at module load; scanC re-zeroes it after use so
// every launch (and every graph replay) starts with g_deg == 0.
__device__ __align__(16) __half2 g_h1h[N_NODES * 32];   // hidden after conv1 (fp16x2, 128B rows)
__device__ __align__(16) __half2 g_xh[N_NODES * 8];     // x padded fp16 rows (32B, 1 line each)
__device__ __align__(16) __half2 g_agg1h[N_NODES * 8];  // pass-1 agg, fp16 accum (32B rows)
__device__ __align__(16) float g_agg[N_NODES * H_DIM];  // pass-2 aggregation (fp32)
__device__ int   g_deg[N_NODES];
__device__ int   g_off[N_NODES + 1];
__device__ int   g_cur[N_NODES];
__device__ int   g_bsum[N_SCAN_BLOCKS];
__device__ __align__(16) int2 g_csr[N_EDGES];           // (src, attr bits), bucketed by dst
__device__ __align__(16) float g_pi[N_NODES];
__device__ __align__(16) float g_texp[G_GROUPS];

__device__ __forceinline__ __half2 u2h2(unsigned int u) {
    __half2 h; *reinterpret_cast<unsigned int*>(&h) = u; return h;
}
__device__ __forceinline__ unsigned int h22u(__half2 h) {
    return *reinterpret_cast<unsigned int*>(&h);
}
// fp16x2 vector global reductions (sm_90+)
__device__ __forceinline__ void red_add_v4h2(__half2* addr, __half2 a, __half2 b,
                                             __half2 c, __half2 d) {
    asm volatile("red.global.add.noftz.v4.f16x2 [%0], {%1,%2,%3,%4};"
                 :: "l"(addr), "r"(h22u(a)), "r"(h22u(b)), "r"(h22u(c)), "r"(h22u(d))
                 : "memory");
}
__device__ __forceinline__ void red_add_h2(__half2* addr, __half2 a) {
    asm volatile("red.global.add.noftz.f16x2 [%0], %1;"
                 :: "l"(addr), "r"(h22u(a)) : "memory");
}
// packed fp32x2 FMA (sm_100+): two IEEE fp32 FMAs per instruction.
__device__ __forceinline__ ull ffma2(ull a, ull b, ull c) {
    ull d;
    asm("fma.rn.f32x2 %0, %1, %2, %3;" : "=l"(d) : "l"(a), "l"(b), "l"(c));
    return d;
}
__device__ __forceinline__ ull pack2(float x, float y) {
    ull r; asm("mov.b64 %0, {%1, %2};" : "=l"(r) : "f"(x), "f"(y)); return r;
}
__device__ __forceinline__ float2 unpack2(ull r) {
    float2 f; asm("mov.b64 {%0, %1}, %2;" : "=f"(f.x), "=f"(f.y) : "l"(r)); return f;
}

// 16-output FFMA2 block: acc[8] (f32x2) += z[k] * W[k][jb..jb+15], k = 0..kdim-1
__device__ __forceinline__ void gemv16_f32x2(ull acc[8], const float* __restrict__ sW,
                                             const float* __restrict__ z, int jb, int kdim) {
#pragma unroll 8
    for (int k = 0; k < kdim; k++) {
        ull zz = pack2(z[k], z[k]);
        const ulonglong2* wp = reinterpret_cast<const ulonglong2*>(&sW[k * H_DIM + jb]);
        ulonglong2 w0 = wp[0], w1 = wp[1];
        acc[0] = ffma2(zz, w0.x, acc[0]);
        acc[1] = ffma2(zz, w0.y, acc[1]);
        acc[2] = ffma2(zz, w1.x, acc[2]);
        acc[3] = ffma2(zz, w1.y, acc[3]);
        const ulonglong2* wq = wp + 2;
        ulonglong2 w2 = wq[0], w3 = wq[1];
        acc[4] = ffma2(zz, w2.x, acc[4]);
        acc[5] = ffma2(zz, w2.y, acc[5]);
        acc[6] = ffma2(zz, w3.x, acc[6]);
        acc[7] = ffma2(zz, w3.y, acc[7]);
    }
}
__device__ __forceinline__ void load_bias16(ull acc[8], const float* __restrict__ sb, int jb) {
    const ulonglong2* bp = reinterpret_cast<const ulonglong2*>(&sb[jb]);
    ulonglong2 b0 = bp[0], b1 = bp[1], b2 = bp[2], b3 = bp[3];
    acc[0] = b0.x; acc[1] = b0.y; acc[2] = b1.x; acc[3] = b1.y;
    acc[4] = b2.x; acc[5] = b2.y; acc[6] = b3.x; acc[7] = b3.y;
}

// ---------------------------------------------------------------------------
// Fused prep + histogram. prep: zero texp, pack x into fp16 32B rows.
// hist: dst-degree histogram, 4 edges/thread via int4.
__global__ void prep_hist_kernel(const float* __restrict__ x,
                                 const int* __restrict__ ei) {
    int t = blockIdx.x * blockDim.x + threadIdx.x;
    if (t < G_GROUPS) g_texp[t] = 0.f;
    if (t < N_NODES) {
        const float* xr = &x[t * 9];
        uint4 u0;
        u0.x = h22u(__floats2half2_rn(xr[0], xr[1]));
        u0.y = h22u(__floats2half2_rn(xr[2], xr[3]));
        u0.z = h22u(__floats2half2_rn(xr[4], xr[5]));
        u0.w = h22u(__floats2half2_rn(xr[6], xr[7]));
        uint4 u1;
        u1.x = h22u(__floats2half2_rn(xr[8], 0.f));
        u1.y = 0; u1.z = 0; u1.w = 0;
        uint4* p = reinterpret_cast<uint4*>(&g_xh[t * 8]);
        p[0] = u0; p[1] = u1;
    }
    int e = t * 4;
    if (e < N_EDGES) {
        int4 d = __ldg(reinterpret_cast<const int4*>(&ei[N_EDGES + e]));
        atomicAdd(&g_deg[d.x], 1);
        atomicAdd(&g_deg[d.y], 1);
        atomicAdd(&g_deg[d.z], 1);
        atomicAdd(&g_deg[d.w], 1);
    }
}

// ---------------------------------------------------------------------------
// Parallel scan, phase A: per-block local exclusive scan (coalesced) of g_deg.
__global__ void scanA_kernel() {
    __shared__ int sh[SCAN_B];
    int tid = threadIdx.x;
    int i = blockIdx.x * SCAN_B + tid;
    int v = (i < N_NODES) ? g_deg[i] : 0;
    sh[tid] = v;
    __syncthreads();
#pragma unroll
    for (int off = 1; off < SCAN_B; off <<= 1) {
        int t = (tid >= off) ? sh[tid - off] : 0;
        __syncthreads();
        sh[tid] += t;
        __syncthreads();
    }
    if (i < N_NODES) g_off[i] = sh[tid] - v;   // local exclusive
    if (tid == SCAN_B - 1) g_bsum[blockIdx.x] = sh[tid];
}

// Phase B: one block scans the block sums (exclusive); writes g_off[N].
__global__ void scanB_kernel() {
    __shared__ int sh[512];
    int tid = threadIdx.x;
    int v = (tid < N_SCAN_BLOCKS) ? g_bsum[tid] : 0;
    sh[tid] = v;
    __syncthreads();
#pragma unroll
    for (int off = 1; off < 512; off <<= 1) {
        int t = (tid >= off) ? sh[tid - off] : 0;
        __syncthreads();
        sh[tid] += t;
        __syncthreads();
    }
    if (tid < N_SCAN_BLOCKS) g_bsum[tid] = sh[tid] - v;  // exclusive
    if (tid == N_SCAN_BLOCKS - 1) g_off[N_NODES] = sh[tid];
}

// Phase C: add block offsets; materialize g_cur; re-zero g_deg; zero the
// fp16 agg rows that scatter_red accumulates into.
__global__ void scanC_kernel() {
    int i = blockIdx.x * blockDim.x + threadIdx.x;
    if (i >= N_NODES) return;
    int o = g_off[i] + g_bsum[i >> 8];
    g_off[i] = o;
    g_cur[i] = o;
    g_deg[i] = 0;
    uint4 z = make_uint4(0, 0, 0, 0);
    uint4* p = reinterpret_cast<uint4*>(&g_agg1h[i * 8]);
    p[0] = z; p[1] = z;
}

// ---------------------------------------------------------------------------
// Fused scatter + pass-1 aggregation. Per edge: bucket (s,a) into csr AND
// reduce the relu'd pass-1 message via fp16x2 REDs (no converts, 2 REDs).
__global__ void scatter_red_kernel(const int* __restrict__ ei,
                                   const float* __restrict__ eattr,
                                   const float* __restrict__ We1,
                                   const float* __restrict__ be1) {
    int t = blockIdx.x * blockDim.x + threadIdx.x;
    int e = t * 4;
    if (e >= N_EDGES) return;

    __half2 w01 = __floats2half2_rn(__ldg(&We1[0]), __ldg(&We1[1]));
    __half2 w23 = __floats2half2_rn(__ldg(&We1[2]), __ldg(&We1[3]));
    __half2 w45 = __floats2half2_rn(__ldg(&We1[4]), __ldg(&We1[5]));
    __half2 w67 = __floats2half2_rn(__ldg(&We1[6]), __ldg(&We1[7]));
    __half2 w8p = __floats2half2_rn(__ldg(&We1[8]), 0.f);
    __half2 b01 = __floats2half2_rn(__ldg(&be1[0]), __ldg(&be1[1]));
    __half2 b23 = __floats2half2_rn(__ldg(&be1[2]), __ldg(&be1[3]));
    __half2 b45 = __floats2half2_rn(__ldg(&be1[4]), __ldg(&be1[5]));
    __half2 b67 = __floats2half2_rn(__ldg(&be1[6]), __ldg(&be1[7]));
    __half2 b8p = __floats2half2_rn(__ldg(&be1[8]), 0.f);
    const __half2 z2 = __float2half2_rn(0.f);

    int4   s = __ldg(reinterpret_cast<const int4*>(&ei[e]));
    int4   d = __ldg(reinterpret_cast<const int4*>(&ei[N_EDGES + e]));
    float4 a = __ldg(reinterpret_cast<const float4*>(&eattr[e]));

    int ss[4] = {s.x, s.y, s.z, s.w};
    int dd[4] = {d.x, d.y, d.z, d.w};
    float aa[4] = {a.x, a.y, a.z, a.w};

#pragma unroll
    for (int k = 0; k < 4; k++) {
        g_csr[atomicAdd(&g_cur[dd[k]], 1)] = make_int2(ss[k], __float_as_int(aa[k]));
        const uint4* xr = reinterpret_cast<const uint4*>(&g_xh[ss[k] * 8]);
        uint4 r0 = __ldg(xr);
        unsigned int r1 = __ldg(reinterpret_cast<const unsigned int*>(xr + 1));
        __half2 a2 = __float2half2_rn(aa[k]);
        __half2 m01 = __hmax2(__hadd2(u2h2(r0.x), __hfma2(a2, w01, b01)), z2);
        __half2 m23 = __hmax2(__hadd2(u2h2(r0.y), __hfma2(a2, w23, b23)), z2);
        __half2 m45 = __hmax2(__hadd2(u2h2(r0.z), __hfma2(a2, w45, b45)), z2);
        __half2 m67 = __hmax2(__hadd2(u2h2(r0.w), __hfma2(a2, w67, b67)), z2);
        __half2 m8p = __hmax2(__hadd2(u2h2(r1),   __hfma2(a2, w8p, b8p)), z2);
        __half2* base = &g_agg1h[dd[k] * 8];
        red_add_v4h2(base, m01, m23, m45, m67);     // features 0..7 (16B)
        red_add_h2(base + 4, m8p);                  // feature 8 (+pad 0)
    }
}

// ---------------------------------------------------------------------------
// Node MLP 1: z = x + agg(fp16); h1 = relu(relu(z@W1a+b1a)@W1b+b1b), stored fp16.
__global__ void mlp1_kernel(const float* __restrict__ x,
                            const float* __restrict__ W1a, const float* __restrict__ b1a,
                            const float* __restrict__ W1b, const float* __restrict__ b1b) {
    __shared__ __align__(16) float sWa[F_IN * H_DIM];
    __shared__ __align__(16) float sWb[H_DIM * H_DIM];
    __shared__ __align__(16) float sba[H_DIM];
    __shared__ __align__(16) float sbb[H_DIM];
    int tid = threadIdx.x;
    for (int i = tid; i < F_IN * H_DIM; i += blockDim.x) sWa[i] = W1a[i];
    for (int i = tid; i < H_DIM * H_DIM; i += blockDim.x) sWb[i] = W1b[i];
    if (tid < H_DIM) { sba[tid] = b1a[tid]; sbb[tid] = b1b[tid]; }
    __syncthreads();

    int n = blockIdx.x * blockDim.x + tid;
    if (n >= N_NODES) return;

    const uint4* ar = reinterpret_cast<const uint4*>(&g_agg1h[n * 8]);
    uint4 a0 = ar[0];
    unsigned int a1 = *reinterpret_cast<const unsigned int*>(ar + 1);
    float2 f01 = __half22float2(u2h2(a0.x));
    float2 f23 = __half22float2(u2h2(a0.y));
    float2 f45 = __half22float2(u2h2(a0.z));
    float2 f67 = __half22float2(u2h2(a0.w));
    float2 f8p = __half22float2(u2h2(a1));

    float z[F_IN];
    z[0] = x[n * 9 + 0] + f01.x;
    z[1] = x[n * 9 + 1] + f01.y;
    z[2] = x[n * 9 + 2] + f23.x;
    z[3] = x[n * 9 + 3] + f23.y;
    z[4] = x[n * 9 + 4] + f45.x;
    z[5] = x[n * 9 + 5] + f45.y;
    z[6] = x[n * 9 + 6] + f67.x;
    z[7] = x[n * 9 + 7] + f67.y;
    z[8] = x[n * 9 + 8] + f8p.x;

    // layer A (9->64): f32x2 blocks of 16 outputs
    float t[H_DIM];
    for (int jb = 0; jb < H_DIM; jb += 16) {
        ull acc[8];
        load_bias16(acc, sba, jb);
        gemv16_f32x2(acc, sWa, z, jb, F_IN);
#pragma unroll
        for (int q = 0; q < 8; q++) {
            float2 f = unpack2(acc[q]);
            t[jb + q * 2 + 0] = fmaxf(f.x, 0.f);
            t[jb + q * 2 + 1] = fmaxf(f.y, 0.f);
        }
    }

    // layer B (64->64): f32x2, output packed fp16
    __half2 hrow[32];
    for (int jb = 0; jb < H_DIM; jb += 16) {
        ull acc[8];
        load_bias16(acc, sbb, jb);
        gemv16_f32x2(acc, sWb, t, jb, H_DIM);
#pragma unroll
        for (int q = 0; q < 8; q++) {
            float2 f = unpack2(acc[q]);
            hrow[(jb >> 1) + q] = __floats2half2_rn(fmaxf(f.x, 0.f), fmaxf(f.y, 0.f));
        }
    }
    uint4* dst = reinterpret_cast<uint4*>(&g_h1h[n * 32]);
    const uint4* src = reinterpret_cast<const uint4*>(hrow);
#pragma unroll
    for (int q = 0; q < 8; q++) dst[q] = src[q];
}

// ---------------------------------------------------------------------------
// Edge pass 2 (gather): warp per dst node, lane owns 2 features (one half2).
// half2 message math, fp32 accumulation; 8 edges in flight.
__global__ void edge2_gather(const float* __restrict__ We2,
                             const float* __restrict__ be2) {
    int gt = blockIdx.x * blockDim.x + threadIdx.x;
    int n = gt >> 5;
    int lane = gt & 31;
    if (n >= N_NODES) return;
    int c = lane * 2;

    __half2 w2 = __floats2half2_rn(__ldg(&We2[c]), __ldg(&We2[c + 1]));
    __half2 b2 = __floats2half2_rn(__ldg(&be2[c]), __ldg(&be2[c + 1]));
    const __half2 z2 = __float2half2_rn(0.f);
    int beg = __ldg(&g_off[n]);
    int end = __ldg(&g_off[n + 1]);

    float2 acc = make_float2(0.f, 0.f);
    int j = beg;
    if ((j & 1) && j < end) {  // peel to make j even (int4 csr alignment)
        int2 sa = __ldg(&g_csr[j]);
        __half2 a2 = __float2half2_rn(__int_as_float(sa.y));
        __half2 h2 = __ldg(&g_h1h[sa.x * 32 + lane]);
        float2 f = __half22float2(__hmax2(__hadd2(h2, __hfma2(a2, w2, b2)), z2));
        acc.x += f.x; acc.y += f.y;
        j++;
    }
    for (; j + 8 <= end; j += 8) {
        int4 p0 = __ldg(reinterpret_cast<const int4*>(&g_csr[j + 0]));
        int4 p1 = __ldg(reinterpret_cast<const int4*>(&g_csr[j + 2]));
        int4 p2 = __ldg(reinterpret_cast<const int4*>(&g_csr[j + 4]));
        int4 p3 = __ldg(reinterpret_cast<const int4*>(&g_csr[j + 6]));
        __half2 h0 = __ldg(&g_h1h[p0.x * 32 + lane]);
        __half2 h1 = __ldg(&g_h1h[p0.z * 32 + lane]);
        __half2 h2 = __ldg(&g_h1h[p1.x * 32 + lane]);
        __half2 h3 = __ldg(&g_h1h[p1.z * 32 + lane]);
        __half2 h4 = __ldg(&g_h1h[p2.x * 32 + lane]);
        __half2 h5 = __ldg(&g_h1h[p2.z * 32 + lane]);
        __half2 h6 = __ldg(&g_h1h[p3.x * 32 + lane]);
        __half2 h7 = __ldg(&g_h1h[p3.z * 32 + lane]);
        float2 f0 = __half22float2(__hmax2(__hadd2(h0, __hfma2(__float2half2_rn(__int_as_float(p0.y)), w2, b2)), z2));
        float2 f1 = __half22float2(__hmax2(__hadd2(h1, __hfma2(__float2half2_rn(__int_as_float(p0.w)), w2, b2)), z2));
        float2 f2 = __half22float2(__hmax2(__hadd2(h2, __hfma2(__float2half2_rn(__int_as_float(p1.y)), w2, b2)), z2));
        float2 f3 = __half22float2(__hmax2(__hadd2(h3, __hfma2(__float2half2_rn(__int_as_float(p1.w)), w2, b2)), z2));
        float2 f4 = __half22float2(__hmax2(__hadd2(h4, __hfma2(__float2half2_rn(__int_as_float(p2.y)), w2, b2)), z2));
        float2 f5 = __half22float2(__hmax2(__hadd2(h5, __hfma2(__float2half2_rn(__int_as_float(p2.w)), w2, b2)), z2));
        float2 f6 = __half22float2(__hmax2(__hadd2(h6, __hfma2(__float2half2_rn(__int_as_float(p3.y)), w2, b2)), z2));
        float2 f7 = __half22float2(__hmax2(__hadd2(h7, __hfma2(__float2half2_rn(__int_as_float(p3.w)), w2, b2)), z2));
        acc.x += f0.x + f1.x + f2.x + f3.x;
        acc.y += f0.y + f1.y + f2.y + f3.y;
        acc.x += f4.x + f5.x + f6.x + f7.x;
        acc.y += f4.y + f5.y + f6.y + f7.y;
    }
    for (; j < end; j++) {
        int2 sa = __ldg(&g_csr[j]);
        __half2 a2 = __float2half2_rn(__int_as_float(sa.y));
        __half2 h2 = __ldg(&g_h1h[sa.x * 32 + lane]);
        float2 f = __half22float2(__hmax2(__hadd2(h2, __hfma2(a2, w2, b2)), z2));
        acc.x += f.x; acc.y += f.y;
    }
    *reinterpret_cast<float2*>(&g_agg[n * H_DIM + c]) = acc;
}

// ---------------------------------------------------------------------------
// Node MLP 2 + readout head + group segment-sum of expenses.
__global__ void mlp2_kernel(const float* __restrict__ W2a, const float* __restrict__ b2a,
                            const float* __restrict__ W2b, const float* __restrict__ b2b,
                            const float* __restrict__ Wr1, const float* __restrict__ br1,
                            const float* __restrict__ Wr2, const float* __restrict__ br2,
                            const int* __restrict__ batch,
                            const int* __restrict__ term,
                            const float* __restrict__ c_cost) {
    __shared__ __align__(16) float sWa[H_DIM * H_DIM];
    __shared__ __align__(16) float sWb[H_DIM * H_DIM];
    __shared__ __align__(16) float sWr1[H_DIM * 32];
    __shared__ __align__(16) float sba[H_DIM];
    __shared__ __align__(16) float sbb[H_DIM];
    __shared__ __align__(16) float sbr1[32];
    __shared__ __align__(16) float sWr2[32];
    __shared__ float sbr2;
    int tid = threadIdx.x;
    for (int i = tid; i < H_DIM * H_DIM; i += blockDim.x) { sWa[i] = W2a[i]; sWb[i] = W2b[i]; }
    for (int i = tid; i < H_DIM * 32; i += blockDim.x) sWr1[i] = Wr1[i];
    if (tid < H_DIM) { sba[tid] = b2a[tid]; sbb[tid] = b2b[tid]; }
    if (tid < 32) { sbr1[tid] = br1[tid]; sWr2[tid] = Wr2[tid]; }
    if (tid == 0) sbr2 = br2[0];
    __syncthreads();

    int n = blockIdx.x * blockDim.x + tid;
    if (n >= N_NODES) return;

    uint4 hraw[8];
    const uint4* hsrc = reinterpret_cast<const uint4*>(&g_h1h[n * 32]);
#pragma unroll
    for (int q = 0; q < 8; q++) hraw[q] = hsrc[q];
    const __half2* hp = reinterpret_cast<const __half2*>(hraw);

    float z[H_DIM];
#pragma unroll
    for (int k = 0; k < H_DIM; k += 4) {
        float2 a01 = __half22float2(hp[k / 2 + 0]);
        float2 a23 = __half22float2(hp[k / 2 + 1]);
        float4 av = *reinterpret_cast<const float4*>(&g_agg[n * H_DIM + k]);
        z[k + 0] = a01.x + av.x;
        z[k + 1] = a01.y + av.y;
        z[k + 2] = a23.x + av.z;
        z[k + 3] = a23.y + av.w;
    }

    // layer A (64->64), f32x2
    float t[H_DIM];
    for (int jb = 0; jb < H_DIM; jb += 16) {
        ull acc[8];
        load_bias16(acc, sba, jb);
        gemv16_f32x2(acc, sWa, z, jb, H_DIM);
#pragma unroll
        for (int q = 0; q < 8; q++) {
            float2 f = unpack2(acc[q]);
            t[jb + q * 2 + 0] = fmaxf(f.x, 0.f);
            t[jb + q * 2 + 1] = fmaxf(f.y, 0.f);
        }
    }

    // layer B (64->64), f32x2, reuse z[] as h2
    for (int jb = 0; jb < H_DIM; jb += 16) {
        ull acc[8];
        load_bias16(acc, sbb, jb);
        gemv16_f32x2(acc, sWb, t, jb, H_DIM);
#pragma unroll
        for (int q = 0; q < 8; q++) {
            float2 f = unpack2(acc[q]);
            z[jb + q * 2 + 0] = fmaxf(f.x, 0.f);
            z[jb + q * 2 + 1] = fmaxf(f.y, 0.f);
        }
    }

    // readout (64->32), f32x2 over Wr1 [64 x 32]
    float r[32];
    for (int jb = 0; jb < 32; jb += 16) {
        ull acc[8];
        {
            const ulonglong2* bp = reinterpret_cast<const ulonglong2*>(&sbr1[jb]);
            ulonglong2 b0 = bp[0], b1 = bp[1], b2c = bp[2], b3 = bp[3];
            acc[0] = b0.x; acc[1] = b0.y; acc[2] = b1.x; acc[3] = b1.y;
            acc[4] = b2c.x; acc[5] = b2c.y; acc[6] = b3.x; acc[7] = b3.y;
        }
#pragma unroll 8
        for (int k = 0; k < H_DIM; k++) {
            ull zz = pack2(z[k], z[k]);
            const ulonglong2* wp = reinterpret_cast<const ulonglong2*>(&sWr1[k * 32 + jb]);
            ulonglong2 w0 = wp[0], w1 = wp[1];
            acc[0] = ffma2(zz, w0.x, acc[0]);
            acc[1] = ffma2(zz, w0.y, acc[1]);
            acc[2] = ffma2(zz, w1.x, acc[2]);
            acc[3] = ffma2(zz, w1.y, acc[3]);
            const ulonglong2* wq = wp + 2;
            ulonglong2 w2 = wq[0], w3 = wq[1];
            acc[4] = ffma2(zz, w2.x, acc[4]);
            acc[5] = ffma2(zz, w2.y, acc[5]);
            acc[6] = ffma2(zz, w3.x, acc[6]);
            acc[7] = ffma2(zz, w3.y, acc[7]);
        }
#pragma unroll
        for (int q = 0; q < 8; q++) {
            float2 f = unpack2(acc[q]);
            r[jb + q * 2 + 0] = fmaxf(f.x, 0.f);
            r[jb + q * 2 + 1] = fmaxf(f.y, 0.f);
        }
    }
    float p = sbr2;
#pragma unroll
    for (int k = 0; k < 32; k++) p = fmaf(r[k], sWr2[k], p);

    float pi = 1.f / (1.f + expf(-p));
    if (term[n] != 0) pi = 0.f;
    g_pi[n] = pi;
    atomicAdd(&g_texp[batch[n]], pi * c_cost[n]);
}

// ---------------------------------------------------------------------------
__global__ void final_kernel(const int* __restrict__ batch,
                             const float* __restrict__ B_total,
                             float* __restrict__ out) {
    int n = blockIdx.x * blockDim.x + threadIdx.x;
    if (n >= N_NODES) return;
    int b = batch[n];
    float ratio = fminf(B_total[b] / (g_texp[b] + 1e-12f), 1.f);
    out[n] = g_pi[n] * ratio;
}

// ---------------------------------------------------------------------------
extern "C" void kernel_launch(void* const* d_in, const int* in_sizes, int n_in,
                              void* d_out, int out_size) {
    const float* x       = (const float*)d_in[0];
    const int*   ei      = (const int*)d_in[1];
    const float* eattr   = (const float*)d_in[2];
    const int*   batch   = (const int*)d_in[3];
    const float* B_total = (const float*)d_in[4];
    const int*   term    = (const int*)d_in[5];
    const float* c_cost  = (const float*)d_in[6];
    const float* We1 = (const float*)d_in[7];
    const float* be1 = (const float*)d_in[8];
    const float* W1a = (const float*)d_in[9];
    const float* b1a = (const float*)d_in[10];
    const float* W1b = (const float*)d_in[11];
    const float* b1b = (const float*)d_in[12];
    const float* We2 = (const float*)d_in[13];
    const float* be2 = (const float*)d_in[14];
    const float* W2a = (const float*)d_in[15];
    const float* b2a = (const float*)d_in[16];
    const float* W2b = (const float*)d_in[17];
    const float* b2b = (const float*)d_in[18];
    const float* Wr1 = (const float*)d_in[19];
    const float* br1 = (const float*)d_in[20];
    const float* Wr2 = (const float*)d_in[21];
    const float* br2 = (const float*)d_in[22];
    float* out = (float*)d_out;

    const int NB_NODE = (N_NODES + 255) / 256;
    const int NB_EDGE4 = (N_EDGES / 4 + 255) / 256;

    prep_hist_kernel<<<NB_EDGE4, 256>>>(x, ei);
    scanA_kernel<<<N_SCAN_BLOCKS, SCAN_B>>>();
    scanB_kernel<<<1, 512>>>();
    scanC_kernel<<<NB_NODE, 256>>>();
    scatter_red_kernel<<<NB_EDGE4, 256>>>(ei, eattr, We1, be1);
    mlp1_kernel<<<NB_NODE, 256>>>(x, W1a, b1a, W1b, b1b);
    edge2_gather<<<(N_NODES * 32 + 255) / 256, 256>>>(We2, be2);
    mlp2_kernel<<<NB_NODE, 256>>>(W2a, b2a, W2b, b2b, Wr1, br1, Wr2, br2,
                                  batch, term, c_cost);
    final_kernel<<<NB_NODE, 256>>>(batch, B_total, out);
}

// round 13
// speedup vs baseline: 1.6977x; 1.0426x over previous
#include <cuda_runtime.h>
#include <cuda_fp16.h>

#define N_NODES 100000
#define N_EDGES 3200000
#define G_GROUPS 128
#define F_IN 9
#define H_DIM 64
#define SCAN_B 256
#define N_SCAN_BLOCKS ((N_NODES + SCAN_B - 1) / SCAN_B)   // 391

typedef unsigned long long ull;

// Scratch (__device__ globals; no allocation allowed).
// g_deg and g_total rely on zero-init at module load; they are re-zeroed
// within each launch (scan zeroes deg, scatter_red zeroes g_total) so every
// launch / graph replay starts clean.
__device__ __align__(16) __half2 g_h1h[N_NODES * 32];   // hidden after conv1 (fp16x2, 128B rows)
__device__ __align__(16) __half2 g_xh[N_NODES * 8];     // x padded fp16 rows (32B)
__device__ __align__(16) __half2 g_agg1h[N_NODES * 8];  // pass-1 agg, fp16 accum (32B rows)
__device__ __align__(16) __half2 g_agg2h[N_NODES * 32]; // pass-2 agg, fp16 rows (128B)
__device__ int   g_deg[N_NODES];
__device__ int   g_cur[N_NODES];
__device__ int   g_total;
__device__ __align__(8) int2 g_off2[N_NODES];           // (beg, end) per node
__device__ __align__(16) int2 g_csr[N_EDGES];           // (src, attr bits), bucketed by dst
__device__ __align__(16) float g_pi[N_NODES];
__device__ __align__(16) float g_texp[G_GROUPS];

__device__ __forceinline__ __half2 u2h2(unsigned int u) {
    __half2 h; *reinterpret_cast<unsigned int*>(&h) = u; return h;
}
__device__ __forceinline__ unsigned int h22u(__half2 h) {
    return *reinterpret_cast<unsigned int*>(&h);
}
// fp16x2 vector global reductions (sm_90+)
__device__ __forceinline__ void red_add_v4h2(__half2* addr, __half2 a, __half2 b,
                                             __half2 c, __half2 d) {
    asm volatile("red.global.add.noftz.v4.f16x2 [%0], {%1,%2,%3,%4};"
                 :: "l"(addr), "r"(h22u(a)), "r"(h22u(b)), "r"(h22u(c)), "r"(h22u(d))
                 : "memory");
}
__device__ __forceinline__ void red_add_h2(__half2* addr, __half2 a) {
    asm volatile("red.global.add.noftz.f16x2 [%0], %1;"
                 :: "l"(addr), "r"(h22u(a)) : "memory");
}
// packed fp32x2 FMA (sm_100+): two IEEE fp32 FMAs per instruction.
__device__ __forceinline__ ull ffma2(ull a, ull b, ull c) {
    ull d;
    asm("fma.rn.f32x2 %0, %1, %2, %3;" : "=l"(d) : "l"(a), "l"(b), "l"(c));
    return d;
}
__device__ __forceinline__ ull pack2(float x, float y) {
    ull r; asm("mov.b64 %0, {%1, %2};" : "=l"(r) : "f"(x), "f"(y)); return r;
}
__device__ __forceinline__ float2 unpack2(ull r) {
    float2 f; asm("mov.b64 {%0, %1}, %2;" : "=f"(f.x), "=f"(f.y) : "l"(r)); return f;
}

// 16-output FFMA2 block: acc[8] (f32x2) += z[k] * W[k][jb..jb+15]
__device__ __forceinline__ void gemv16_f32x2(ull acc[8], const float* __restrict__ sW,
                                             const float* __restrict__ z, int jb, int kdim) {
#pragma unroll 8
    for (int k = 0; k < kdim; k++) {
        ull zz = pack2(z[k], z[k]);
        const ulonglong2* wp = reinterpret_cast<const ulonglong2*>(&sW[k * H_DIM + jb]);
        ulonglong2 w0 = wp[0], w1 = wp[1];
        acc[0] = ffma2(zz, w0.x, acc[0]);
        acc[1] = ffma2(zz, w0.y, acc[1]);
        acc[2] = ffma2(zz, w1.x, acc[2]);
        acc[3] = ffma2(zz, w1.y, acc[3]);
        const ulonglong2* wq = wp + 2;
        ulonglong2 w2 = wq[0], w3 = wq[1];
        acc[4] = ffma2(zz, w2.x, acc[4]);
        acc[5] = ffma2(zz, w2.y, acc[5]);
        acc[6] = ffma2(zz, w3.x, acc[6]);
        acc[7] = ffma2(zz, w3.y, acc[7]);
    }
}
__device__ __forceinline__ void load_bias16(ull acc[8], const float* __restrict__ sb, int jb) {
    const ulonglong2* bp = reinterpret_cast<const ulonglong2*>(&sb[jb]);
    ulonglong2 b0 = bp[0], b1 = bp[1], b2 = bp[2], b3 = bp[3];
    acc[0] = b0.x; acc[1] = b0.y; acc[2] = b1.x; acc[3] = b1.y;
    acc[4] = b2.x; acc[5] = b2.y; acc[6] = b3.x; acc[7] = b3.y;
}

// ---------------------------------------------------------------------------
// Fused prep + histogram. prep: zero texp, pack x into fp16 32B rows.
// hist: dst-degree histogram, 4 edges/thread via int4.
__global__ void prep_hist_kernel(const float* __restrict__ x,
                                 const int* __restrict__ ei) {
    int t = blockIdx.x * blockDim.x + threadIdx.x;
    if (t < G_GROUPS) g_texp[t] = 0.f;
    if (t < N_NODES) {
        const float* xr = &x[t * 9];
        uint4 u0;
        u0.x = h22u(__floats2half2_rn(xr[0], xr[1]));
        u0.y = h22u(__floats2half2_rn(xr[2], xr[3]));
        u0.z = h22u(__floats2half2_rn(xr[4], xr[5]));
        u0.w = h22u(__floats2half2_rn(xr[6], xr[7]));
        uint4 u1;
        u1.x = h22u(__floats2half2_rn(xr[8], 0.f));
        u1.y = 0; u1.z = 0; u1.w = 0;
        uint4* p = reinterpret_cast<uint4*>(&g_xh[t * 8]);
        p[0] = u0; p[1] = u1;
    }
    int e = t * 4;
    if (e < N_EDGES) {
        int4 d = __ldg(reinterpret_cast<const int4*>(&ei[N_EDGES + e]));
        atomicAdd(&g_deg[d.x], 1);
        atomicAdd(&g_deg[d.y], 1);
        atomicAdd(&g_deg[d.z], 1);
        atomicAdd(&g_deg[d.w], 1);
    }
}

// ---------------------------------------------------------------------------
// Single-pass scan: each tile claims a base range via one atomicAdd (segment
// assignment need not be monotonic in node id — (beg,end) pairs are stored
// explicitly). Also materializes g_cur, re-zeroes g_deg, zeroes agg1h rows.
__global__ void scan_fused_kernel() {
    __shared__ int sh[SCAN_B];
    __shared__ int s_base;
    int tid = threadIdx.x;
    int i = blockIdx.x * SCAN_B + tid;
    int v = (i < N_NODES) ? g_deg[i] : 0;
    sh[tid] = v;
    __syncthreads();
#pragma unroll
    for (int off = 1; off < SCAN_B; off <<= 1) {
        int t = (tid >= off) ? sh[tid - off] : 0;
        __syncthreads();
        sh[tid] += t;
        __syncthreads();
    }
    if (tid == SCAN_B - 1) s_base = atomicAdd(&g_total, sh[tid]);
    __syncthreads();
    if (i < N_NODES) {
        int beg = s_base + sh[tid] - v;
        g_off2[i] = make_int2(beg, beg + v);
        g_cur[i] = beg;
        g_deg[i] = 0;
        uint4 z = make_uint4(0, 0, 0, 0);
        uint4* p = reinterpret_cast<uint4*>(&g_agg1h[i * 8]);
        p[0] = z; p[1] = z;
    }
}

// ---------------------------------------------------------------------------
// Fused scatter + pass-1 aggregation. Per edge: bucket (s,a) into csr AND
// reduce the relu'd pass-1 message via fp16x2 REDs. Also resets g_total.
__global__ void scatter_red_kernel(const int* __restrict__ ei,
                                   const float* __restrict__ eattr,
                                   const float* __restrict__ We1,
                                   const float* __restrict__ be1) {
    int t = blockIdx.x * blockDim.x + threadIdx.x;
    if (t == 0) g_total = 0;   // reset for next launch/replay
    int e = t * 4;
    if (e >= N_EDGES) return;

    __half2 w01 = __floats2half2_rn(__ldg(&We1[0]), __ldg(&We1[1]));
    __half2 w23 = __floats2half2_rn(__ldg(&We1[2]), __ldg(&We1[3]));
    __half2 w45 = __floats2half2_rn(__ldg(&We1[4]), __ldg(&We1[5]));
    __half2 w67 = __floats2half2_rn(__ldg(&We1[6]), __ldg(&We1[7]));
    __half2 w8p = __floats2half2_rn(__ldg(&We1[8]), 0.f);
    __half2 b01 = __floats2half2_rn(__ldg(&be1[0]), __ldg(&be1[1]));
    __half2 b23 = __floats2half2_rn(__ldg(&be1[2]), __ldg(&be1[3]));
    __half2 b45 = __floats2half2_rn(__ldg(&be1[4]), __ldg(&be1[5]));
    __half2 b67 = __floats2half2_rn(__ldg(&be1[6]), __ldg(&be1[7]));
    __half2 b8p = __floats2half2_rn(__ldg(&be1[8]), 0.f);
    const __half2 z2 = __float2half2_rn(0.f);

    int4   s = __ldg(reinterpret_cast<const int4*>(&ei[e]));
    int4   d = __ldg(reinterpret_cast<const int4*>(&ei[N_EDGES + e]));
    float4 a = __ldg(reinterpret_cast<const float4*>(&eattr[e]));

    int ss[4] = {s.x, s.y, s.z, s.w};
    int dd[4] = {d.x, d.y, d.z, d.w};
    float aa[4] = {a.x, a.y, a.z, a.w};

#pragma unroll
    for (int k = 0; k < 4; k++) {
        g_csr[atomicAdd(&g_cur[dd[k]], 1)] = make_int2(ss[k], __float_as_int(aa[k]));
        const uint4* xr = reinterpret_cast<const uint4*>(&g_xh[ss[k] * 8]);
        uint4 r0 = __ldg(xr);
        unsigned int r1 = __ldg(reinterpret_cast<const unsigned int*>(xr + 1));
        __half2 a2 = __float2half2_rn(aa[k]);
        __half2 m01 = __hmax2(__hadd2(u2h2(r0.x), __hfma2(a2, w01, b01)), z2);
        __half2 m23 = __hmax2(__hadd2(u2h2(r0.y), __hfma2(a2, w23, b23)), z2);
        __half2 m45 = __hmax2(__hadd2(u2h2(r0.z), __hfma2(a2, w45, b45)), z2);
        __half2 m67 = __hmax2(__hadd2(u2h2(r0.w), __hfma2(a2, w67, b67)), z2);
        __half2 m8p = __hmax2(__hadd2(u2h2(r1),   __hfma2(a2, w8p, b8p)), z2);
        __half2* base = &g_agg1h[dd[k] * 8];
        red_add_v4h2(base, m01, m23, m45, m67);
        red_add_h2(base + 4, m8p);
    }
}

// ---------------------------------------------------------------------------
// Node MLP 1: z = x + agg(fp16); h1 = relu(relu(z@W1a+b1a)@W1b+b1b), stored fp16.
__global__ void mlp1_kernel(const float* __restrict__ x,
                            const float* __restrict__ W1a, const float* __restrict__ b1a,
                            const float* __restrict__ W1b, const float* __restrict__ b1b) {
    __shared__ __align__(16) float sWa[F_IN * H_DIM];
    __shared__ __align__(16) float sWb[H_DIM * H_DIM];
    __shared__ __align__(16) float sba[H_DIM];
    __shared__ __align__(16) float sbb[H_DIM];
    int tid = threadIdx.x;
    for (int i = tid; i < F_IN * H_DIM; i += blockDim.x) sWa[i] = W1a[i];
    for (int i = tid; i < H_DIM * H_DIM; i += blockDim.x) sWb[i] = W1b[i];
    if (tid < H_DIM) { sba[tid] = b1a[tid]; sbb[tid] = b1b[tid]; }
    __syncthreads();

    int n = blockIdx.x * blockDim.x + tid;
    if (n >= N_NODES) return;

    const uint4* ar = reinterpret_cast<const uint4*>(&g_agg1h[n * 8]);
    uint4 a0 = ar[0];
    unsigned int a1 = *reinterpret_cast<const unsigned int*>(ar + 1);
    float2 f01 = __half22float2(u2h2(a0.x));
    float2 f23 = __half22float2(u2h2(a0.y));
    float2 f45 = __half22float2(u2h2(a0.z));
    float2 f67 = __half22float2(u2h2(a0.w));
    float2 f8p = __half22float2(u2h2(a1));

    float z[F_IN];
    z[0] = x[n * 9 + 0] + f01.x;
    z[1] = x[n * 9 + 1] + f01.y;
    z[2] = x[n * 9 + 2] + f23.x;
    z[3] = x[n * 9 + 3] + f23.y;
    z[4] = x[n * 9 + 4] + f45.x;
    z[5] = x[n * 9 + 5] + f45.y;
    z[6] = x[n * 9 + 6] + f67.x;
    z[7] = x[n * 9 + 7] + f67.y;
    z[8] = x[n * 9 + 8] + f8p.x;

    float t[H_DIM];
    for (int jb = 0; jb < H_DIM; jb += 16) {
        ull acc[8];
        load_bias16(acc, sba, jb);
        gemv16_f32x2(acc, sWa, z, jb, F_IN);
#pragma unroll
        for (int q = 0; q < 8; q++) {
            float2 f = unpack2(acc[q]);
            t[jb + q * 2 + 0] = fmaxf(f.x, 0.f);
            t[jb + q * 2 + 1] = fmaxf(f.y, 0.f);
        }
    }

    __half2 hrow[32];
    for (int jb = 0; jb < H_DIM; jb += 16) {
        ull acc[8];
        load_bias16(acc, sbb, jb);
        gemv16_f32x2(acc, sWb, t, jb, H_DIM);
#pragma unroll
        for (int q = 0; q < 8; q++) {
            float2 f = unpack2(acc[q]);
            hrow[(jb >> 1) + q] = __floats2half2_rn(fmaxf(f.x, 0.f), fmaxf(f.y, 0.f));
        }
    }
    uint4* dst = reinterpret_cast<uint4*>(&g_h1h[n * 32]);
    const uint4* src = reinterpret_cast<const uint4*>(hrow);
#pragma unroll
    for (int q = 0; q < 8; q++) dst[q] = src[q];
}

// ---------------------------------------------------------------------------
// Edge pass 2 (gather): warp per dst node, lane owns 2 features (one half2).
// half2 message math; within-8-edge half2 tree -> fp32 master accumulator.
// agg2 stored fp16 (128B rows).
__global__ void edge2_gather(const float* __restrict__ We2,
                             const float* __restrict__ be2) {
    int gt = blockIdx.x * blockDim.x + threadIdx.x;
    int n = gt >> 5;
    int lane = gt & 31;
    if (n >= N_NODES) return;
    int c = lane * 2;

    __half2 w2 = __floats2half2_rn(__ldg(&We2[c]), __ldg(&We2[c + 1]));
    __half2 b2 = __floats2half2_rn(__ldg(&be2[c]), __ldg(&be2[c + 1]));
    const __half2 z2 = __float2half2_rn(0.f);
    int2 be = __ldg(&g_off2[n]);
    int beg = be.x, end = be.y;

    float2 acc = make_float2(0.f, 0.f);
    int j = beg;
    if ((j & 1) && j < end) {  // peel to make j even (int4 csr alignment)
        int2 sa = __ldg(&g_csr[j]);
        __half2 a2 = __float2half2_rn(__int_as_float(sa.y));
        __half2 h2 = __ldg(&g_h1h[sa.x * 32 + lane]);
        float2 f = __half22float2(__hmax2(__hadd2(h2, __hfma2(a2, w2, b2)), z2));
        acc.x += f.x; acc.y += f.y;
        j++;
    }
    for (; j + 8 <= end; j += 8) {
        int4 p0 = __ldg(reinterpret_cast<const int4*>(&g_csr[j + 0]));
        int4 p1 = __ldg(reinterpret_cast<const int4*>(&g_csr[j + 2]));
        int4 p2 = __ldg(reinterpret_cast<const int4*>(&g_csr[j + 4]));
        int4 p3 = __ldg(reinterpret_cast<const int4*>(&g_csr[j + 6]));
        __half2 h0 = __ldg(&g_h1h[p0.x * 32 + lane]);
        __half2 h1 = __ldg(&g_h1h[p0.z * 32 + lane]);
        __half2 h2 = __ldg(&g_h1h[p1.x * 32 + lane]);
        __half2 h3 = __ldg(&g_h1h[p1.z * 32 + lane]);
        __half2 h4 = __ldg(&g_h1h[p2.x * 32 + lane]);
        __half2 h5 = __ldg(&g_h1h[p2.z * 32 + lane]);
        __half2 h6 = __ldg(&g_h1h[p3.x * 32 + lane]);
        __half2 h7 = __ldg(&g_h1h[p3.z * 32 + lane]);
        __half2 m0 = __hmax2(__hadd2(h0, __hfma2(__float2half2_rn(__int_as_float(p0.y)), w2, b2)), z2);
        __half2 m1 = __hmax2(__hadd2(h1, __hfma2(__float2half2_rn(__int_as_float(p0.w)), w2, b2)), z2);
        __half2 m2 = __hmax2(__hadd2(h2, __hfma2(__float2half2_rn(__int_as_float(p1.y)), w2, b2)), z2);
        __half2 m3 = __hmax2(__hadd2(h3, __hfma2(__float2half2_rn(__int_as_float(p1.w)), w2, b2)), z2);
        __half2 m4 = __hmax2(__hadd2(h4, __hfma2(__float2half2_rn(__int_as_float(p2.y)), w2, b2)), z2);
        __half2 m5 = __hmax2(__hadd2(h5, __hfma2(__float2half2_rn(__int_as_float(p2.w)), w2, b2)), z2);
        __half2 m6 = __hmax2(__hadd2(h6, __hfma2(__float2half2_rn(__int_as_float(p3.y)), w2, b2)), z2);
        __half2 m7 = __hmax2(__hadd2(h7, __hfma2(__float2half2_rn(__int_as_float(p3.w)), w2, b2)), z2);
        // half2 tree (3 levels) then one fp32 add into master acc
        __half2 s01 = __hadd2(m0, m1), s23 = __hadd2(m2, m3);
        __half2 s45 = __hadd2(m4, m5), s67 = __hadd2(m6, m7);
        __half2 s = __hadd2(__hadd2(s01, s23), __hadd2(s45, s67));
        float2 f = __half22float2(s);
        acc.x += f.x; acc.y += f.y;
    }
    for (; j < end; j++) {
        int2 sa = __ldg(&g_csr[j]);
        __half2 a2 = __float2half2_rn(__int_as_float(sa.y));
        __half2 h2 = __ldg(&g_h1h[sa.x * 32 + lane]);
        float2 f = __half22float2(__hmax2(__hadd2(h2, __hfma2(a2, w2, b2)), z2));
        acc.x += f.x; acc.y += f.y;
    }
    g_agg2h[n * 32 + lane] = __floats2half2_rn(acc.x, acc.y);
}

// ---------------------------------------------------------------------------
// Node MLP 2 + readout head + group segment-sum of expenses.
__global__ void mlp2_kernel(const float* __restrict__ W2a, const float* __restrict__ b2a,
                            const float* __restrict__ W2b, const float* __restrict__ b2b,
                            const float* __restrict__ Wr1, const float* __restrict__ br1,
                            const float* __restrict__ Wr2, const float* __restrict__ br2,
                            const int* __restrict__ batch,
                            const int* __restrict__ term,
                            const float* __restrict__ c_cost) {
    __shared__ __align__(16) float sWa[H_DIM * H_DIM];
    __shared__ __align__(16) float sWb[H_DIM * H_DIM];
    __shared__ __align__(16) float sWr1[H_DIM * 32];
    __shared__ __align__(16) float sba[H_DIM];
    __shared__ __align__(16) float sbb[H_DIM];
    __shared__ __align__(16) float sbr1[32];
    __shared__ __align__(16) float sWr2[32];
    __shared__ float sbr2;
    int tid = threadIdx.x;
    for (int i = tid; i < H_DIM * H_DIM; i += blockDim.x) { sWa[i] = W2a[i]; sWb[i] = W2b[i]; }
    for (int i = tid; i < H_DIM * 32; i += blockDim.x) sWr1[i] = Wr1[i];
    if (tid < H_DIM) { sba[tid] = b2a[tid]; sbb[tid] = b2b[tid]; }
    if (tid < 32) { sbr1[tid] = br1[tid]; sWr2[tid] = Wr2[tid]; }
    if (tid == 0) sbr2 = br2[0];
    __syncthreads();

    int n = blockIdx.x * blockDim.x + tid;
    if (n >= N_NODES) return;

    uint4 hraw[8], araw[8];
    const uint4* hsrc = reinterpret_cast<const uint4*>(&g_h1h[n * 32]);
    const uint4* asrc = reinterpret_cast<const uint4*>(&g_agg2h[n * 32]);
#pragma unroll
    for (int q = 0; q < 8; q++) { hraw[q] = hsrc[q]; araw[q] = asrc[q]; }
    const __half2* hp = reinterpret_cast<const __half2*>(hraw);
    const __half2* ap = reinterpret_cast<const __half2*>(araw);

    float z[H_DIM];
#pragma unroll
    for (int k = 0; k < H_DIM; k += 2) {
        float2 hv = __half22float2(hp[k / 2]);
        float2 av = __half22float2(ap[k / 2]);
        z[k + 0] = hv.x + av.x;
        z[k + 1] = hv.y + av.y;
    }

    // layer A (64->64), f32x2
    float t[H_DIM];
    for (int jb = 0; jb < H_DIM; jb += 16) {
        ull acc[8];
        load_bias16(acc, sba, jb);
        gemv16_f32x2(acc, sWa, z, jb, H_DIM);
#pragma unroll
        for (int q = 0; q < 8; q++) {
            float2 f = unpack2(acc[q]);
            t[jb + q * 2 + 0] = fmaxf(f.x, 0.f);
            t[jb + q * 2 + 1] = fmaxf(f.y, 0.f);
        }
    }

    // layer B (64->64), f32x2, reuse z[] as h2
    for (int jb = 0; jb < H_DIM; jb += 16) {
        ull acc[8];
        load_bias16(acc, sbb, jb);
        gemv16_f32x2(acc, sWb, t, jb, H_DIM);
#pragma unroll
        for (int q = 0; q < 8; q++) {
            float2 f = unpack2(acc[q]);
            z[jb + q * 2 + 0] = fmaxf(f.x, 0.f);
            z[jb + q * 2 + 1] = fmaxf(f.y, 0.f);
        }
    }

    // readout (64->32), f32x2 over Wr1 [64 x 32]
    float r[32];
    for (int jb = 0; jb < 32; jb += 16) {
        ull acc[8];
        {
            const ulonglong2* bp = reinterpret_cast<const ulonglong2*>(&sbr1[jb]);
            ulonglong2 b0 = bp[0], b1 = bp[1], b2c = bp[2], b3 = bp[3];
            acc[0] = b0.x; acc[1] = b0.y; acc[2] = b1.x; acc[3] = b1.y;
            acc[4] = b2c.x; acc[5] = b2c.y; acc[6] = b3.x; acc[7] = b3.y;
        }
#pragma unroll 8
        for (int k = 0; k < H_DIM; k++) {
            ull zz = pack2(z[k], z[k]);
            const ulonglong2* wp = reinterpret_cast<const ulonglong2*>(&sWr1[k * 32 + jb]);
            ulonglong2 w0 = wp[0], w1 = wp[1];
            acc[0] = ffma2(zz, w0.x, acc[0]);
            acc[1] = ffma2(zz, w0.y, acc[1]);
            acc[2] = ffma2(zz, w1.x, acc[2]);
            acc[3] = ffma2(zz, w1.y, acc[3]);
            const ulonglong2* wq = wp + 2;
            ulonglong2 w2 = wq[0], w3 = wq[1];
            acc[4] = ffma2(zz, w2.x, acc[4]);
            acc[5] = ffma2(zz, w2.y, acc[5]);
            acc[6] = ffma2(zz, w3.x, acc[6]);
            acc[7] = ffma2(zz, w3.y, acc[7]);
        }
#pragma unroll
        for (int q = 0; q < 8; q++) {
            float2 f = unpack2(acc[q]);
            r[jb + q * 2 + 0] = fmaxf(f.x, 0.f);
            r[jb + q * 2 + 1] = fmaxf(f.y, 0.f);
        }
    }
    float p = sbr2;
#pragma unroll
    for (int k = 0; k < 32; k++) p = fmaf(r[k], sWr2[k], p);

    float pi = 1.f / (1.f + expf(-p));
    if (term[n] != 0) pi = 0.f;
    g_pi[n] = pi;
    atomicAdd(&g_texp[batch[n]], pi * c_cost[n]);
}

// ---------------------------------------------------------------------------
__global__ void final_kernel(const int* __restrict__ batch,
                             const float* __restrict__ B_total,
                             float* __restrict__ out) {
    int n = blockIdx.x * blockDim.x + threadIdx.x;
    if (n >= N_NODES) return;
    int b = batch[n];
    float ratio = fminf(B_total[b] / (g_texp[b] + 1e-12f), 1.f);
    out[n] = g_pi[n] * ratio;
}

// ---------------------------------------------------------------------------
extern "C" void kernel_launch(void* const* d_in, const int* in_sizes, int n_in,
                              void* d_out, int out_size) {
    const float* x       = (const float*)d_in[0];
    const int*   ei      = (const int*)d_in[1];
    const float* eattr   = (const float*)d_in[2];
    const int*   batch   = (const int*)d_in[3];
    const float* B_total = (const float*)d_in[4];
    const int*   term    = (const int*)d_in[5];
    const float* c_cost  = (const float*)d_in[6];
    const float* We1 = (const float*)d_in[7];
    const float* be1 = (const float*)d_in[8];
    const float* W1a = (const float*)d_in[9];
    const float* b1a = (const float*)d_in[10];
    const float* W1b = (const float*)d_in[11];
    const float* b1b = (const float*)d_in[12];
    const float* We2 = (const float*)d_in[13];
    const float* be2 = (const float*)d_in[14];
    const float* W2a = (const float*)d_in[15];
    const float* b2a = (const float*)d_in[16];
    const float* W2b = (const float*)d_in[17];
    const float* b2b = (const float*)d_in[18];
    const float* Wr1 = (const float*)d_in[19];
    const float* br1 = (const float*)d_in[20];
    const float* Wr2 = (const float*)d_in[21];
    const float* br2 = (const float*)d_in[22];
    float* out = (float*)d_out;

    const int NB_NODE = (N_NODES + 255) / 256;
    const int NB_EDGE4 = (N_EDGES / 4 + 255) / 256;

    prep_hist_kernel<<<NB_EDGE4, 256>>>(x, ei);
    scan_fused_kernel<<<N_SCAN_BLOCKS, SCAN_B>>>();
    scatter_red_kernel<<<NB_EDGE4, 256>>>(ei, eattr, We1, be1);
    mlp1_kernel<<<NB_NODE, 256>>>(x, W1a, b1a, W1b, b1b);
    edge2_gather<<<(N_NODES * 32 + 255) / 256, 256>>>(We2, be2);
    mlp2_kernel<<<NB_NODE, 256>>>(W2a, b2a, W2b, b2b, Wr1, br1, Wr2, br2,
                                  batch, term, c_cost);
    final_kernel<<<NB_NODE, 256>>>(batch, B_total, out);
}